// round 6
// baseline (speedup 1.0000x reference)
#include <cuda_runtime.h>
#include <cuda_bf16.h>
#include <math.h>
#include <stdint.h>

#define B_   2
#define T_   2048
#define D_   2048
#define HQ_  16
#define HK_  4
#define HD_  128
#define MROWS (B_*T_)            // 4096
#define QELEMS (MROWS*HQ_*HD_)   // 8388608
#define KVELEMS (MROWS*HK_*HD_)  // 2097152

// fp32 scratch
__device__ float g_q[QELEMS];
__device__ float g_kraw[KVELEMS];
__device__ float g_vraw[KVELEMS];
__device__ float g_attn[QELEMS];
// bf16 split scratch (GEMM)
__device__ __nv_bfloat16 g_xs0[MROWS*D_];
__device__ __nv_bfloat16 g_xs1[MROWS*D_];
__device__ __nv_bfloat16 g_wqT0[D_*D_], g_wqT1[D_*D_];
__device__ __nv_bfloat16 g_wkT0[512*D_], g_wkT1[512*D_];
__device__ __nv_bfloat16 g_wvT0[512*D_], g_wvT1[512*D_];
__device__ __nv_bfloat16 g_woT0[D_*D_], g_woT1[D_*D_];
// bf16 split scratch (attention), head-major [b][h][t][128]
__device__ __nv_bfloat16 g_aqh[QELEMS], g_aql[QELEMS];
__device__ __nv_bfloat16 g_akh[KVELEMS], g_akl[KVELEMS];
__device__ __nv_bfloat16 g_avh[KVELEMS], g_avl[KVELEMS];

// ============================ helpers =========================================
__device__ __forceinline__ uint32_t smem_u32(const void* p) {
    uint32_t a;
    asm("{ .reg .u64 t; cvta.to.shared.u64 t, %1; cvt.u32.u64 %0, t; }" : "=r"(a) : "l"(p));
    return a;
}
__device__ __forceinline__ void cpasync16(uint32_t s, const void* g) {
    asm volatile("cp.async.cg.shared.global [%0], [%1], 16;" :: "r"(s), "l"(g));
}
__device__ __forceinline__ void ldsm4(uint32_t& r0, uint32_t& r1, uint32_t& r2, uint32_t& r3,
                                      uint32_t addr) {
    asm volatile("ldmatrix.sync.aligned.m8n8.x4.shared.b16 {%0,%1,%2,%3}, [%4];"
                 : "=r"(r0), "=r"(r1), "=r"(r2), "=r"(r3) : "r"(addr));
}
__device__ __forceinline__ void ldsm4t(uint32_t& r0, uint32_t& r1, uint32_t& r2, uint32_t& r3,
                                       uint32_t addr) {
    asm volatile("ldmatrix.sync.aligned.m8n8.x4.trans.shared.b16 {%0,%1,%2,%3}, [%4];"
                 : "=r"(r0), "=r"(r1), "=r"(r2), "=r"(r3) : "r"(addr));
}
__device__ __forceinline__ void mma16816(float* c, const uint32_t* a, const uint32_t* b) {
    asm volatile("mma.sync.aligned.m16n8k16.row.col.f32.bf16.bf16.f32 "
                 "{%0,%1,%2,%3}, {%4,%5,%6,%7}, {%8,%9}, {%0,%1,%2,%3};"
                 : "+f"(c[0]), "+f"(c[1]), "+f"(c[2]), "+f"(c[3])
                 : "r"(a[0]), "r"(a[1]), "r"(a[2]), "r"(a[3]), "r"(b[0]), "r"(b[1]));
}
// GEMM tile swizzle: [rows][32 bf16] (64B rows, 16B chunks)
__device__ __forceinline__ uint32_t swadr(int row, int ch) {
    return (uint32_t)(row * 64 + ((ch ^ ((row >> 1) & 3)) << 4));
}
// attention tile swizzle: [rows][128 bf16] (256B rows, 16 chunks of 16B)
__device__ __forceinline__ uint32_t asw(int row, int ch) {
    return (uint32_t)(row * 256 + ((ch ^ (row & 7)) << 4));
}

// ============================ split / transpose preps ==========================
__global__ void split_f32(const float* __restrict__ in, __nv_bfloat16* __restrict__ o0,
                          __nv_bfloat16* __restrict__ o1) {
    int i = blockIdx.x * 256 + threadIdx.x;
    float4 v = ((const float4*)in)[i];
    __nv_bfloat16 h[4], l[4];
    float vv[4] = {v.x, v.y, v.z, v.w};
    #pragma unroll
    for (int j = 0; j < 4; j++) {
        h[j] = __float2bfloat16(vv[j]);
        l[j] = __float2bfloat16(vv[j] - __bfloat162float(h[j]));
    }
    ((ushort4*)o0)[i] = make_ushort4(*(unsigned short*)&h[0], *(unsigned short*)&h[1],
                                     *(unsigned short*)&h[2], *(unsigned short*)&h[3]);
    ((ushort4*)o1)[i] = make_ushort4(*(unsigned short*)&l[0], *(unsigned short*)&l[1],
                                     *(unsigned short*)&l[2], *(unsigned short*)&l[3]);
}

__global__ void wsplitT(const float* __restrict__ W, __nv_bfloat16* __restrict__ t0,
                        __nv_bfloat16* __restrict__ t1, int N) {
    __shared__ float tile[32][33];
    int n0 = blockIdx.x * 32, k0 = blockIdx.y * 32;
    int tx = threadIdx.x, ty = threadIdx.y;
    #pragma unroll
    for (int i = 0; i < 4; i++)
        tile[ty + i * 8][tx] = W[(long)(k0 + ty + i * 8) * N + n0 + tx];
    __syncthreads();
    #pragma unroll
    for (int i = 0; i < 4; i++) {
        float v = tile[tx][ty + i * 8];
        __nv_bfloat16 h = __float2bfloat16(v);
        __nv_bfloat16 l = __float2bfloat16(v - __bfloat162float(h));
        long o = (long)(n0 + ty + i * 8) * 2048 + k0 + tx;
        t0[o] = h; t1[o] = l;
    }
}

// ============================ mma.sync bf16x3 GEMM, 128x128 tile ===============
// Fused q/k/v: block n index selects weight/output. Warp tile 64x32.
#define G2_STG 32768
#define G2_A0 0
#define G2_A1 8192
#define G2_B0 16384
#define G2_B1 24576
#define G2_TOT (2*G2_STG)    // 65536

__global__ void __launch_bounds__(256, 2) gemm_mma2(
    const __nv_bfloat16* __restrict__ A0, const __nv_bfloat16* __restrict__ A1,
    const __nv_bfloat16* __restrict__ Bq0, const __nv_bfloat16* __restrict__ Bq1,
    const __nv_bfloat16* __restrict__ Bk0, const __nv_bfloat16* __restrict__ Bk1,
    const __nv_bfloat16* __restrict__ Bv0, const __nv_bfloat16* __restrict__ Bv1,
    float* __restrict__ Cq, float* __restrict__ Ck, float* __restrict__ Cv) {
    extern __shared__ char smem[];
    uint32_t sb = smem_u32(smem);
    int tid = threadIdx.x, lane = tid & 31, wid = tid >> 5;
    int wm = wid & 1, wn = wid >> 1;             // warp tile: rows wm*64, cols wn*32
    long m0 = (long)blockIdx.y * 128;

    const __nv_bfloat16 *B0, *B1;
    float* C;
    int N, n0;
    int nb = blockIdx.x;
    if (nb < 16)      { B0 = Bq0; B1 = Bq1; C = Cq; N = 2048; n0 = nb * 128; }
    else if (nb < 20) { B0 = Bk0; B1 = Bk1; C = Ck; N = 512;  n0 = (nb - 16) * 128; }
    else              { B0 = Bv0; B1 = Bv1; C = Cv; N = 512;  n0 = (nb - 20) * 128; }

    int lrow = lane & 7, ltile = lane >> 3;
    int a_row = wm * 64 + ((ltile & 1) << 3) + lrow;   // + mf*16
    int a_ch  = ltile >> 1;                            // + ks*2
    int b_row = wn * 32 + ((ltile >> 1) << 3) + lrow;  // + nf2*16
    int b_ch  = ltile & 1;                             // + ks*2

    float acc[4][4][4];
    #pragma unroll
    for (int mf = 0; mf < 4; mf++)
        #pragma unroll
        for (int nf = 0; nf < 4; nf++)
            #pragma unroll
            for (int j = 0; j < 4; j++) acc[mf][nf][j] = 0.f;

    int ldr = tid >> 1, ldh = (tid & 1) * 2;     // each thread: 2 chunks per array

    auto issue = [&](int st, int kc) {
        uint32_t base = sb + st * G2_STG;
        #pragma unroll
        for (int cc = 0; cc < 2; cc++) {
            int ch = ldh + cc;
            uint32_t sw = swadr(ldr, ch);
            long ga = (m0 + ldr) * 2048 + kc + ch * 8;
            cpasync16(base + G2_A0 + sw, A0 + ga);
            cpasync16(base + G2_A1 + sw, A1 + ga);
            long gb = (long)(n0 + ldr) * 2048 + kc + ch * 8;
            cpasync16(base + G2_B0 + sw, B0 + gb);
            cpasync16(base + G2_B1 + sw, B1 + gb);
        }
        asm volatile("cp.async.commit_group;" ::: "memory");
    };

    issue(0, 0);
    const int KI = 2048 / 32;
    for (int kci = 0; kci < KI; kci++) {
        if (kci + 1 < KI) {
            issue((kci + 1) & 1, (kci + 1) * 32);
            asm volatile("cp.async.wait_group 1;" ::: "memory");
        } else {
            asm volatile("cp.async.wait_group 0;" ::: "memory");
        }
        __syncthreads();

        uint32_t base = sb + (kci & 1) * G2_STG;
        #pragma unroll
        for (int ks = 0; ks < 2; ks++) {
            uint32_t ah[4][4], al[4][4];
            #pragma unroll
            for (int mf = 0; mf < 4; mf++) {
                uint32_t adr = base + G2_A0 + swadr(a_row + mf * 16, ks * 2 + a_ch);
                ldsm4(ah[mf][0], ah[mf][1], ah[mf][2], ah[mf][3], adr);
                adr = base + G2_A1 + swadr(a_row + mf * 16, ks * 2 + a_ch);
                ldsm4(al[mf][0], al[mf][1], al[mf][2], al[mf][3], adr);
            }
            uint32_t bh[4][2], bl[4][2];
            #pragma unroll
            for (int nf2 = 0; nf2 < 2; nf2++) {
                uint32_t adr = base + G2_B0 + swadr(b_row + nf2 * 16, ks * 2 + b_ch);
                ldsm4(bh[nf2*2][0], bh[nf2*2][1], bh[nf2*2+1][0], bh[nf2*2+1][1], adr);
                adr = base + G2_B1 + swadr(b_row + nf2 * 16, ks * 2 + b_ch);
                ldsm4(bl[nf2*2][0], bl[nf2*2][1], bl[nf2*2+1][0], bl[nf2*2+1][1], adr);
            }
            #pragma unroll
            for (int mf = 0; mf < 4; mf++)
                #pragma unroll
                for (int nf = 0; nf < 4; nf++) {
                    mma16816(acc[mf][nf], ah[mf], bh[nf]);
                    mma16816(acc[mf][nf], ah[mf], bl[nf]);
                    mma16816(acc[mf][nf], al[mf], bh[nf]);
                }
        }
        __syncthreads();
    }

    int cr = lane >> 2, cc = (lane & 3) << 1;
    #pragma unroll
    for (int mf = 0; mf < 4; mf++)
        #pragma unroll
        for (int nf = 0; nf < 4; nf++) {
            long row = m0 + wm * 64 + mf * 16 + cr;
            int col = n0 + wn * 32 + nf * 8 + cc;
            *(float2*)(C + row * N + col)       = make_float2(acc[mf][nf][0], acc[mf][nf][1]);
            *(float2*)(C + (row + 8) * N + col) = make_float2(acc[mf][nf][2], acc[mf][nf][3]);
        }
}

// ============================ RoPE + pack + bf16 splits ========================
__global__ void rope_pack(const float* __restrict__ q, const float* __restrict__ kraw,
                          const float* __restrict__ vraw, float* __restrict__ kv,
                          __nv_bfloat16* __restrict__ qh, __nv_bfloat16* __restrict__ ql,
                          __nv_bfloat16* __restrict__ kh, __nv_bfloat16* __restrict__ kl,
                          __nv_bfloat16* __restrict__ vh, __nv_bfloat16* __restrict__ vl) {
    int idx = blockIdx.x * 256 + threadIdx.x;
    {
        int row = idx >> 10;          // b*T + t
        int rem = idx & 1023;
        int h = rem >> 6, m = rem & 63;
        int b = row >> 11, t = row & 2047;
        float invf = powf(10000.0f, -(float)(2 * m) * (1.0f / 128.0f));
        float ang = (float)t * invf;
        float c = cosf(ang), s = sinf(ang);
        const float scale = 0.08838834764831845f;
        long base = (long)row * (HQ_ * HD_) + h * HD_ + m;
        float x1 = q[base], x2 = q[base + 64];
        float v1 = (x1 * c - x2 * s) * scale;
        float v2 = (x2 * c + x1 * s) * scale;
        long so = ((long)(b * HQ_ + h) * T_ + t) * 128 + m;
        __nv_bfloat16 h1 = __float2bfloat16(v1), h2 = __float2bfloat16(v2);
        qh[so] = h1;      qh[so + 64] = h2;
        ql[so] = __float2bfloat16(v1 - __bfloat162float(h1));
        ql[so + 64] = __float2bfloat16(v2 - __bfloat162float(h2));
    }
    if (idx < MROWS * HK_ * 64) {
        int krow = idx >> 8;
        int krem = idx & 255;
        int khd = krem >> 6, km = krem & 63;
        int b = krow >> 11, t = krow & 2047;
        float invf = powf(10000.0f, -(float)(2 * km) * (1.0f / 128.0f));
        float ang = (float)t * invf;
        float c = cosf(ang), s = sinf(ang);
        long src = (long)krow * (HK_ * HD_) + khd * HD_ + km;
        float x1 = kraw[src], x2 = kraw[src + 64];
        float v1 = x1 * c - x2 * s;
        float v2 = x2 * c + x1 * s;
        long dst = ((long)krow * HK_ + khd) * 256 + km;
        kv[dst]      = v1;
        kv[dst + 64] = v2;
        long so = ((long)(b * HK_ + khd) * T_ + t) * 128 + km;
        __nv_bfloat16 h1 = __float2bfloat16(v1), h2 = __float2bfloat16(v2);
        kh[so] = h1;      kh[so + 64] = h2;
        kl[so] = __float2bfloat16(v1 - __bfloat162float(h1));
        kl[so + 64] = __float2bfloat16(v2 - __bfloat162float(h2));
    }
    if (idx < KVELEMS / 4) {
        int f = idx;
        int vrow = f >> 7;
        int vc4 = f & 127;
        int vhd = vc4 >> 5, vd4 = (vc4 & 31) << 2;
        int b = vrow >> 11, t = vrow & 2047;
        float4 v = *(const float4*)(vraw + (long)f * 4);
        long dst = ((long)vrow * HK_ + vhd) * 256 + 128 + vd4;
        *(float4*)(kv + dst) = v;
        long so = ((long)(b * HK_ + vhd) * T_ + t) * 128 + vd4;
        float vv[4] = {v.x, v.y, v.z, v.w};
        #pragma unroll
        for (int j = 0; j < 4; j++) {
            __nv_bfloat16 hj = __float2bfloat16(vv[j]);
            vh[so + j] = hj;
            vl[so + j] = __float2bfloat16(vv[j] - __bfloat162float(hj));
        }
    }
}

// ============================ threefry (partitionable) =========================
__device__ __forceinline__ unsigned tf_rotl(unsigned x, int r) {
    return (x << r) | (x >> (32 - r));
}
__device__ __forceinline__ float dropout_keep(unsigned e) {
    unsigned x0 = 0u, x1 = e;
    const unsigned k0 = 0u, k1 = 1u, k2 = 0x1BD11BDAu ^ k0 ^ k1;
    x0 += k0; x1 += k1;
#define TFR(r) { x0 += x1; x1 = tf_rotl(x1, r); x1 ^= x0; }
    TFR(13) TFR(15) TFR(26) TFR(6)
    x0 += k1; x1 += k2 + 1u;
    TFR(17) TFR(29) TFR(16) TFR(24)
    x0 += k2; x1 += k0 + 2u;
    TFR(13) TFR(15) TFR(26) TFR(6)
    x0 += k0; x1 += k1 + 3u;
    TFR(17) TFR(29) TFR(16) TFR(24)
    x0 += k1; x1 += k2 + 4u;
    TFR(13) TFR(15) TFR(26) TFR(6)
    x0 += k2; x1 += k0 + 5u;
#undef TFR
    unsigned bits = x0 ^ x1;
    float u = __uint_as_float((bits >> 9) | 0x3F800000u) - 1.0f;
    return (u < 0.9f) ? (1.0f / 0.9f) : 0.0f;
}

// ============================ tensor-core attention ============================
#define A_QH 0
#define A_QL (A_QH + 128*256)
#define A_KH (A_QL + 128*256)
#define A_KL (A_KH + 64*256)
#define A_VH (A_KL + 64*256)
#define A_VL (A_VH + 64*256)
#define A_TOT (A_VL + 64*256)    // 131072 bytes

__global__ void __launch_bounds__(256) attn_mma(
    const __nv_bfloat16* __restrict__ Qh, const __nv_bfloat16* __restrict__ Ql,
    const __nv_bfloat16* __restrict__ Kh, const __nv_bfloat16* __restrict__ Kl,
    const __nv_bfloat16* __restrict__ Vh, const __nv_bfloat16* __restrict__ Vl,
    float* __restrict__ O) {
    extern __shared__ char smem[];
    uint32_t sb = smem_u32(smem);
    int tid = threadIdx.x, lane = tid & 31, wid = tid >> 5;
    int qb = (gridDim.x - 1) - blockIdx.x;
    int bh = blockIdx.y;
    int b = bh >> 4, hq = bh & 15, hk = hq & 3;

    const __nv_bfloat16* qhp = Qh + ((long)(b * HQ_ + hq) * T_ + qb * 128) * 128;
    const __nv_bfloat16* qlp = Ql + ((long)(b * HQ_ + hq) * T_ + qb * 128) * 128;
    const __nv_bfloat16* khp = Kh + (long)(b * HK_ + hk) * T_ * 128;
    const __nv_bfloat16* klp = Kl + (long)(b * HK_ + hk) * T_ * 128;
    const __nv_bfloat16* vhp = Vh + (long)(b * HK_ + hk) * T_ * 128;
    const __nv_bfloat16* vlp = Vl + (long)(b * HK_ + hk) * T_ * 128;

    #pragma unroll
    for (int it = 0; it < 16; it++) {
        int lin = tid + it * 256;
        int arr = lin >> 11, cidx = lin & 2047;
        int row = cidx >> 4, ch = cidx & 15;
        const __nv_bfloat16* src = (arr ? qlp : qhp) + row * 128 + ch * 8;
        cpasync16(sb + (arr ? A_QL : A_QH) + asw(row, ch), src);
    }

    int qrw = wid * 16;
    float m1 = -INFINITY, m2 = -INFINITY, l1 = 0.f, l2 = 0.f;
    float o[16][4];
    #pragma unroll
    for (int nf = 0; nf < 16; nf++)
        #pragma unroll
        for (int c = 0; c < 4; c++) o[nf][c] = 0.f;

    unsigned ebase = (unsigned)(b * 16 + hq) * 4194304u;
    int ig1 = qb * 128 + qrw + (lane >> 2);

    int a_row = qrw + ((lane >> 3) & 1) * 8 + (lane & 7);
    int a_chb = lane >> 4;
    int k_row8 = ((lane >> 4)) * 8 + (lane & 7);
    int k_chb = (lane >> 3) & 1;
    int v_row8 = ((lane >> 3) & 1) * 8 + (lane & 7);
    int v_chb = lane >> 4;

    int njb = 2 * qb + 2;
    for (int jb = 0; jb < njb; jb++) {
        #pragma unroll
        for (int it = 0; it < 16; it++) {
            int lin = tid + it * 256;
            int arr = lin >> 10, cidx = lin & 1023;
            int row = cidx >> 4, ch = cidx & 15;
            long g = (long)(jb * 64 + row) * 128 + ch * 8;
            const __nv_bfloat16* src = (arr == 0 ? khp : arr == 1 ? klp : arr == 2 ? vhp : vlp) + g;
            cpasync16(sb + A_KH + arr * 16384 + asw(row, ch), src);
        }
        asm volatile("cp.async.commit_group;" ::: "memory");
        asm volatile("cp.async.wait_group 0;" ::: "memory");
        __syncthreads();

        float sc[8][4];
        #pragma unroll
        for (int nf = 0; nf < 8; nf++)
            #pragma unroll
            for (int c = 0; c < 4; c++) sc[nf][c] = 0.f;
        #pragma unroll
        for (int ks = 0; ks < 8; ks++) {
            uint32_t qh4[4], ql4[4];
            ldsm4(qh4[0], qh4[1], qh4[2], qh4[3], sb + A_QH + asw(a_row, 2 * ks + a_chb));
            ldsm4(ql4[0], ql4[1], ql4[2], ql4[3], sb + A_QL + asw(a_row, 2 * ks + a_chb));
            #pragma unroll
            for (int nfp = 0; nfp < 4; nfp++) {
                uint32_t kh4[4], kl4[4];
                int br = nfp * 16 + k_row8;
                int bc = 2 * ks + k_chb;
                ldsm4(kh4[0], kh4[1], kh4[2], kh4[3], sb + A_KH + asw(br, bc));
                ldsm4(kl4[0], kl4[1], kl4[2], kl4[3], sb + A_KL + asw(br, bc));
                mma16816(sc[2 * nfp],     qh4, kh4);
                mma16816(sc[2 * nfp],     qh4, kl4);
                mma16816(sc[2 * nfp],     ql4, kh4);
                mma16816(sc[2 * nfp + 1], qh4, kh4 + 2);
                mma16816(sc[2 * nfp + 1], qh4, kl4 + 2);
                mma16816(sc[2 * nfp + 1], ql4, kh4 + 2);
            }
        }

        if (jb * 64 + 63 > qb * 128 + qrw) {
            #pragma unroll
            for (int nf = 0; nf < 8; nf++) {
                int j0 = jb * 64 + nf * 8 + (lane & 3) * 2;
                if (j0 > ig1)     sc[nf][0] = -INFINITY;
                if (j0 + 1 > ig1) sc[nf][1] = -INFINITY;
                if (j0 > ig1 + 8)     sc[nf][2] = -INFINITY;
                if (j0 + 1 > ig1 + 8) sc[nf][3] = -INFINITY;
            }
        }

        float mx1 = -INFINITY, mx2 = -INFINITY;
        #pragma unroll
        for (int nf = 0; nf < 8; nf++) {
            mx1 = fmaxf(mx1, fmaxf(sc[nf][0], sc[nf][1]));
            mx2 = fmaxf(mx2, fmaxf(sc[nf][2], sc[nf][3]));
        }
        mx1 = fmaxf(mx1, __shfl_xor_sync(0xffffffffu, mx1, 1));
        mx1 = fmaxf(mx1, __shfl_xor_sync(0xffffffffu, mx1, 2));
        mx2 = fmaxf(mx2, __shfl_xor_sync(0xffffffffu, mx2, 1));
        mx2 = fmaxf(mx2, __shfl_xor_sync(0xffffffffu, mx2, 2));
        float mn1 = fmaxf(m1, mx1), mn2 = fmaxf(m2, mx2);
        float cr1 = expf(m1 - mn1), cr2 = expf(m2 - mn2);
        float rs1 = 0.f, rs2 = 0.f;
        #pragma unroll
        for (int nf = 0; nf < 8; nf++) {
            sc[nf][0] = expf(sc[nf][0] - mn1); rs1 += sc[nf][0];
            sc[nf][1] = expf(sc[nf][1] - mn1); rs1 += sc[nf][1];
            sc[nf][2] = expf(sc[nf][2] - mn2); rs2 += sc[nf][2];
            sc[nf][3] = expf(sc[nf][3] - mn2); rs2 += sc[nf][3];
        }
        rs1 += __shfl_xor_sync(0xffffffffu, rs1, 1);
        rs1 += __shfl_xor_sync(0xffffffffu, rs1, 2);
        rs2 += __shfl_xor_sync(0xffffffffu, rs2, 1);
        rs2 += __shfl_xor_sync(0xffffffffu, rs2, 2);
        l1 = l1 * cr1 + rs1;  l2 = l2 * cr2 + rs2;
        m1 = mn1;  m2 = mn2;
        #pragma unroll
        for (int nf = 0; nf < 16; nf++) {
            o[nf][0] *= cr1; o[nf][1] *= cr1;
            o[nf][2] *= cr2; o[nf][3] *= cr2;
        }

        #pragma unroll
        for (int nf = 0; nf < 8; nf++) {
            unsigned j0 = (unsigned)(jb * 64 + nf * 8 + (lane & 3) * 2);
            sc[nf][0] *= dropout_keep(ebase + (unsigned)ig1 * 2048u + j0);
            sc[nf][1] *= dropout_keep(ebase + (unsigned)ig1 * 2048u + j0 + 1u);
            sc[nf][2] *= dropout_keep(ebase + (unsigned)(ig1 + 8) * 2048u + j0);
            sc[nf][3] *= dropout_keep(ebase + (unsigned)(ig1 + 8) * 2048u + j0 + 1u);
        }

        #pragma unroll
        for (int ksj = 0; ksj < 4; ksj++) {
            uint32_t ahi[4], alo[4];
            #pragma unroll
            for (int half = 0; half < 2; half++) {
                int nf = 2 * ksj + half;
                __nv_bfloat16 h0 = __float2bfloat16(sc[nf][0]);
                __nv_bfloat16 h1 = __float2bfloat16(sc[nf][1]);
                __nv_bfloat16 h2 = __float2bfloat16(sc[nf][2]);
                __nv_bfloat16 h3 = __float2bfloat16(sc[nf][3]);
                __nv_bfloat162 hh01 = __halves2bfloat162(h0, h1);
                __nv_bfloat162 hh23 = __halves2bfloat162(h2, h3);
                ahi[2 * half]     = *reinterpret_cast<uint32_t*>(&hh01);
                ahi[2 * half + 1] = *reinterpret_cast<uint32_t*>(&hh23);
                __nv_bfloat162 ll01 = __halves2bfloat162(
                    __float2bfloat16(sc[nf][0] - __bfloat162float(h0)),
                    __float2bfloat16(sc[nf][1] - __bfloat162float(h1)));
                __nv_bfloat162 ll23 = __halves2bfloat162(
                    __float2bfloat16(sc[nf][2] - __bfloat162float(h2)),
                    __float2bfloat16(sc[nf][3] - __bfloat162float(h3)));
                alo[2 * half]     = *reinterpret_cast<uint32_t*>(&ll01);
                alo[2 * half + 1] = *reinterpret_cast<uint32_t*>(&ll23);
            }
            #pragma unroll
            for (int nfp = 0; nfp < 8; nfp++) {
                uint32_t vh4[4], vl4[4];
                int vr = ksj * 16 + v_row8;
                int vc = 2 * nfp + v_chb;
                ldsm4t(vh4[0], vh4[1], vh4[2], vh4[3], sb + A_VH + asw(vr, vc));
                ldsm4t(vl4[0], vl4[1], vl4[2], vl4[3], sb + A_VL + asw(vr, vc));
                mma16816(o[2 * nfp],     ahi, vh4);
                mma16816(o[2 * nfp],     ahi, vl4);
                mma16816(o[2 * nfp],     alo, vh4);
                mma16816(o[2 * nfp + 1], ahi, vh4 + 2);
                mma16816(o[2 * nfp + 1], ahi, vl4 + 2);
                mma16816(o[2 * nfp + 1], alo, vh4 + 2);
            }
        }
        __syncthreads();
    }

    float inv1 = 1.f / l1, inv2 = 1.f / l2;
    long r1g = (long)(b * T_ + qb * 128 + qrw + (lane >> 2));
    #pragma unroll
    for (int nf = 0; nf < 16; nf++) {
        int col = hq * 128 + nf * 8 + (lane & 3) * 2;
        *(float2*)(O + r1g * 2048 + col)       = make_float2(o[nf][0] * inv1, o[nf][1] * inv1);
        *(float2*)(O + (r1g + 8) * 2048 + col) = make_float2(o[nf][2] * inv2, o[nf][3] * inv2);
    }
}

// ============================ launch ===========================================
extern "C" void kernel_launch(void* const* d_in, const int* in_sizes, int n_in,
                              void* d_out, int out_size) {
    const float* x  = (const float*)d_in[0];
    const float* wq = (const float*)d_in[1];
    const float* wk = (const float*)d_in[2];
    const float* wv = (const float*)d_in[3];
    const float* wo = (const float*)d_in[4];
    float* out = (float*)d_out;
    float* kv  = out + QELEMS;

    float *qp, *kp, *vp, *ap;
    cudaGetSymbolAddress((void**)&qp, g_q);
    cudaGetSymbolAddress((void**)&kp, g_kraw);
    cudaGetSymbolAddress((void**)&vp, g_vraw);
    cudaGetSymbolAddress((void**)&ap, g_attn);
    __nv_bfloat16 *xs0, *xs1, *wqT0, *wqT1, *wkT0, *wkT1, *wvT0, *wvT1, *woT0, *woT1;
    __nv_bfloat16 *aqh, *aql, *akh, *akl, *avh, *avl;
    cudaGetSymbolAddress((void**)&xs0, g_xs0);
    cudaGetSymbolAddress((void**)&xs1, g_xs1);
    cudaGetSymbolAddress((void**)&wqT0, g_wqT0);
    cudaGetSymbolAddress((void**)&wqT1, g_wqT1);
    cudaGetSymbolAddress((void**)&wkT0, g_wkT0);
    cudaGetSymbolAddress((void**)&wkT1, g_wkT1);
    cudaGetSymbolAddress((void**)&wvT0, g_wvT0);
    cudaGetSymbolAddress((void**)&wvT1, g_wvT1);
    cudaGetSymbolAddress((void**)&woT0, g_woT0);
    cudaGetSymbolAddress((void**)&woT1, g_woT1);
    cudaGetSymbolAddress((void**)&aqh, g_aqh);
    cudaGetSymbolAddress((void**)&aql, g_aql);
    cudaGetSymbolAddress((void**)&akh, g_akh);
    cudaGetSymbolAddress((void**)&akl, g_akl);
    cudaGetSymbolAddress((void**)&avh, g_avh);
    cudaGetSymbolAddress((void**)&avl, g_avl);

    cudaFuncSetAttribute(gemm_mma2, cudaFuncAttributeMaxDynamicSharedMemorySize, G2_TOT);
    cudaFuncSetAttribute(attn_mma, cudaFuncAttributeMaxDynamicSharedMemorySize, A_TOT);

    // prep
    split_f32<<<(MROWS * D_ / 4) / 256, 256>>>(x, xs0, xs1);
    wsplitT<<<dim3(D_ / 32, D_ / 32), dim3(32, 8)>>>(wq, wqT0, wqT1, D_);
    wsplitT<<<dim3(512 / 32, D_ / 32), dim3(32, 8)>>>(wk, wkT0, wkT1, 512);
    wsplitT<<<dim3(512 / 32, D_ / 32), dim3(32, 8)>>>(wv, wvT0, wvT1, 512);
    wsplitT<<<dim3(D_ / 32, D_ / 32), dim3(32, 8)>>>(wo, woT0, woT1, D_);

    // fused q/k/v projections (tensor pipe)
    gemm_mma2<<<dim3(24, MROWS / 128), 256, G2_TOT>>>(
        xs0, xs1, wqT0, wqT1, wkT0, wkT1, wvT0, wvT1, qp, kp, vp);

    rope_pack<<<(MROWS * HQ_ * 64) / 256, 256>>>(qp, kp, vp, kv, aqh, aql, akh, akl, avh, avl);

    // tensor-core attention
    attn_mma<<<dim3(T_ / 128, B_ * HQ_), 256, A_TOT>>>(aqh, aql, akh, akl, avh, avl, ap);

    // out projection
    split_f32<<<(MROWS * D_ / 4) / 256, 256>>>(ap, xs0, xs1);
    gemm_mma2<<<dim3(16, MROWS / 128), 256, G2_TOT>>>(
        xs0, xs1, woT0, woT1, woT0, woT1, woT0, woT1, out, out, out);
}

// round 7
// speedup vs baseline: 1.1161x; 1.1161x over previous
#include <cuda_runtime.h>
#include <cuda_bf16.h>
#include <math.h>
#include <stdint.h>

#define B_   2
#define T_   2048
#define D_   2048
#define HQ_  16
#define HK_  4
#define HD_  128
#define MROWS (B_*T_)            // 4096
#define QELEMS (MROWS*HQ_*HD_)   // 8388608
#define KVELEMS (MROWS*HK_*HD_)  // 2097152

// fp32 scratch
__device__ float g_q[QELEMS];
__device__ float g_kraw[KVELEMS];
__device__ float g_vraw[KVELEMS];
__device__ float g_attn[QELEMS];
// bf16 split scratch (GEMM)
__device__ __nv_bfloat16 g_xs0[MROWS*D_];
__device__ __nv_bfloat16 g_xs1[MROWS*D_];
__device__ __nv_bfloat16 g_wqT0[D_*D_], g_wqT1[D_*D_];
__device__ __nv_bfloat16 g_wkT0[512*D_], g_wkT1[512*D_];
__device__ __nv_bfloat16 g_wvT0[512*D_], g_wvT1[512*D_];
__device__ __nv_bfloat16 g_woT0[D_*D_], g_woT1[D_*D_];
// bf16 split scratch (attention), head-major [b][h][t][128]
__device__ __nv_bfloat16 g_aqh[QELEMS], g_aql[QELEMS];
__device__ __nv_bfloat16 g_akh[KVELEMS], g_akl[KVELEMS];
__device__ __nv_bfloat16 g_avh[KVELEMS], g_avl[KVELEMS];

// ============================ helpers =========================================
__device__ __forceinline__ uint32_t smem_u32(const void* p) {
    uint32_t a;
    asm("{ .reg .u64 t; cvta.to.shared.u64 t, %1; cvt.u32.u64 %0, t; }" : "=r"(a) : "l"(p));
    return a;
}
__device__ __forceinline__ void cpasync16(uint32_t s, const void* g) {
    asm volatile("cp.async.cg.shared.global [%0], [%1], 16;" :: "r"(s), "l"(g));
}
__device__ __forceinline__ void ldsm4(uint32_t& r0, uint32_t& r1, uint32_t& r2, uint32_t& r3,
                                      uint32_t addr) {
    asm volatile("ldmatrix.sync.aligned.m8n8.x4.shared.b16 {%0,%1,%2,%3}, [%4];"
                 : "=r"(r0), "=r"(r1), "=r"(r2), "=r"(r3) : "r"(addr));
}
__device__ __forceinline__ void ldsm4t(uint32_t& r0, uint32_t& r1, uint32_t& r2, uint32_t& r3,
                                       uint32_t addr) {
    asm volatile("ldmatrix.sync.aligned.m8n8.x4.trans.shared.b16 {%0,%1,%2,%3}, [%4];"
                 : "=r"(r0), "=r"(r1), "=r"(r2), "=r"(r3) : "r"(addr));
}
__device__ __forceinline__ void mma16816(float* c, const uint32_t* a, const uint32_t* b) {
    asm volatile("mma.sync.aligned.m16n8k16.row.col.f32.bf16.bf16.f32 "
                 "{%0,%1,%2,%3}, {%4,%5,%6,%7}, {%8,%9}, {%0,%1,%2,%3};"
                 : "+f"(c[0]), "+f"(c[1]), "+f"(c[2]), "+f"(c[3])
                 : "r"(a[0]), "r"(a[1]), "r"(a[2]), "r"(a[3]), "r"(b[0]), "r"(b[1]));
}
// GEMM tile swizzle: [rows][32 bf16] (64B rows, 16B chunks)
__device__ __forceinline__ uint32_t swadr(int row, int ch) {
    return (uint32_t)(row * 64 + ((ch ^ ((row >> 1) & 3)) << 4));
}
// attention tile swizzle: [rows][128 bf16] (256B rows, 16 chunks of 16B)
__device__ __forceinline__ uint32_t asw(int row, int ch) {
    return (uint32_t)(row * 256 + ((ch ^ (row & 7)) << 4));
}

// ============================ split / transpose preps ==========================
__global__ void split_f32(const float* __restrict__ in, __nv_bfloat16* __restrict__ o0,
                          __nv_bfloat16* __restrict__ o1) {
    int i = blockIdx.x * 256 + threadIdx.x;
    float4 v = ((const float4*)in)[i];
    __nv_bfloat16 h[4], l[4];
    float vv[4] = {v.x, v.y, v.z, v.w};
    #pragma unroll
    for (int j = 0; j < 4; j++) {
        h[j] = __float2bfloat16(vv[j]);
        l[j] = __float2bfloat16(vv[j] - __bfloat162float(h[j]));
    }
    ((ushort4*)o0)[i] = make_ushort4(*(unsigned short*)&h[0], *(unsigned short*)&h[1],
                                     *(unsigned short*)&h[2], *(unsigned short*)&h[3]);
    ((ushort4*)o1)[i] = make_ushort4(*(unsigned short*)&l[0], *(unsigned short*)&l[1],
                                     *(unsigned short*)&l[2], *(unsigned short*)&l[3]);
}

__global__ void wsplitT(const float* __restrict__ W, __nv_bfloat16* __restrict__ t0,
                        __nv_bfloat16* __restrict__ t1, int N) {
    __shared__ float tile[32][33];
    int n0 = blockIdx.x * 32, k0 = blockIdx.y * 32;
    int tx = threadIdx.x, ty = threadIdx.y;
    #pragma unroll
    for (int i = 0; i < 4; i++)
        tile[ty + i * 8][tx] = W[(long)(k0 + ty + i * 8) * N + n0 + tx];
    __syncthreads();
    #pragma unroll
    for (int i = 0; i < 4; i++) {
        float v = tile[tx][ty + i * 8];
        __nv_bfloat16 h = __float2bfloat16(v);
        __nv_bfloat16 l = __float2bfloat16(v - __bfloat162float(h));
        long o = (long)(n0 + ty + i * 8) * 2048 + k0 + tx;
        t0[o] = h; t1[o] = l;
    }
}

// ============================ mma.sync bf16x3 GEMM (R5 tile, fused, 3-stage) ===
#define STG_BYTES 24576
#define OFF_AH 0
#define OFF_AL 8192
#define OFF_BH 16384
#define OFF_BL 20480
#define GSM_TOT (3*STG_BYTES)   // 73728

__global__ void __launch_bounds__(256) gemm_mma(
    const __nv_bfloat16* __restrict__ A0, const __nv_bfloat16* __restrict__ A1,
    const __nv_bfloat16* __restrict__ Bq0, const __nv_bfloat16* __restrict__ Bq1,
    const __nv_bfloat16* __restrict__ Bk0, const __nv_bfloat16* __restrict__ Bk1,
    const __nv_bfloat16* __restrict__ Bv0, const __nv_bfloat16* __restrict__ Bv1,
    float* __restrict__ Cq, float* __restrict__ Ck, float* __restrict__ Cv) {
    extern __shared__ char smem[];
    uint32_t sb = smem_u32(smem);
    int tid = threadIdx.x, lane = tid & 31, wid = tid >> 5;
    int wm = wid & 3, wn = wid >> 2;
    long m0 = (long)blockIdx.y * 128;

    const __nv_bfloat16 *B0, *B1;
    float* C;
    int N, n0;
    int nb = blockIdx.x;
    if (nb < 32)      { B0 = Bq0; B1 = Bq1; C = Cq; N = 2048; n0 = nb * 64; }
    else if (nb < 40) { B0 = Bk0; B1 = Bk1; C = Ck; N = 512;  n0 = (nb - 32) * 64; }
    else              { B0 = Bv0; B1 = Bv1; C = Cv; N = 512;  n0 = (nb - 40) * 64; }

    int lrow = lane & 7, ltile = lane >> 3;
    int a_row = wm * 32 + ((ltile & 1) << 3) + lrow;
    int a_ch  = ltile >> 1;
    int b_row = wn * 32 + ((ltile >> 1) << 3) + lrow;
    int b_ch  = ltile & 1;

    float acc[2][4][4];
    #pragma unroll
    for (int mf = 0; mf < 2; mf++)
        #pragma unroll
        for (int nf = 0; nf < 4; nf++)
            #pragma unroll
            for (int j = 0; j < 4; j++) acc[mf][nf][j] = 0.f;

    int ar0 = tid >> 2, ach = tid & 3;
    int br  = tid >> 2, bch = tid & 3;

    auto issue = [&](int st, int kc) {
        uint32_t base = sb + st * STG_BYTES;
        #pragma unroll
        for (int p = 0; p < 2; p++) {
            int r = ar0 + p * 64;
            uint32_t sw = swadr(r, ach);
            long g = (m0 + r) * 2048 + kc + ach * 8;
            cpasync16(base + OFF_AH + sw, A0 + g);
            cpasync16(base + OFF_AL + sw, A1 + g);
        }
        {
            uint32_t sw = swadr(br, bch);
            long g = (long)(n0 + br) * 2048 + kc + bch * 8;
            cpasync16(base + OFF_BH + sw, B0 + g);
            cpasync16(base + OFF_BL + sw, B1 + g);
        }
        asm volatile("cp.async.commit_group;" ::: "memory");
    };

    const int KI = 2048 / 32;
    issue(0, 0);
    issue(1, 32);
    int stage = 0;
    for (int kci = 0; kci < KI; kci++) {
        if (kci + 2 < KI) {
            issue((stage + 2) % 3, (kci + 2) * 32);
            asm volatile("cp.async.wait_group 2;" ::: "memory");
        } else if (kci + 1 < KI) {
            asm volatile("cp.async.wait_group 1;" ::: "memory");
        } else {
            asm volatile("cp.async.wait_group 0;" ::: "memory");
        }
        __syncthreads();

        uint32_t base = sb + stage * STG_BYTES;
        #pragma unroll
        for (int ks = 0; ks < 2; ks++) {
            uint32_t ah[2][4], al[2][4];
            #pragma unroll
            for (int mf = 0; mf < 2; mf++) {
                uint32_t adr = base + OFF_AH + swadr(a_row + mf * 16, ks * 2 + a_ch);
                ldsm4(ah[mf][0], ah[mf][1], ah[mf][2], ah[mf][3], adr);
                adr = base + OFF_AL + swadr(a_row + mf * 16, ks * 2 + a_ch);
                ldsm4(al[mf][0], al[mf][1], al[mf][2], al[mf][3], adr);
            }
            uint32_t bh[4][2], bl[4][2];
            #pragma unroll
            for (int nf2 = 0; nf2 < 2; nf2++) {
                uint32_t adr = base + OFF_BH + swadr(b_row + nf2 * 16, ks * 2 + b_ch);
                ldsm4(bh[nf2*2][0], bh[nf2*2][1], bh[nf2*2+1][0], bh[nf2*2+1][1], adr);
                adr = base + OFF_BL + swadr(b_row + nf2 * 16, ks * 2 + b_ch);
                ldsm4(bl[nf2*2][0], bl[nf2*2][1], bl[nf2*2+1][0], bl[nf2*2+1][1], adr);
            }
            #pragma unroll
            for (int mf = 0; mf < 2; mf++)
                #pragma unroll
                for (int nf = 0; nf < 4; nf++) {
                    mma16816(acc[mf][nf], ah[mf], bh[nf]);
                    mma16816(acc[mf][nf], ah[mf], bl[nf]);
                    mma16816(acc[mf][nf], al[mf], bh[nf]);
                }
        }
        __syncthreads();
        stage = (stage + 1) % 3;
    }

    int cr = lane >> 2, cc = (lane & 3) << 1;
    #pragma unroll
    for (int mf = 0; mf < 2; mf++)
        #pragma unroll
        for (int nf = 0; nf < 4; nf++) {
            long row = m0 + wm * 32 + mf * 16 + cr;
            int col = n0 + wn * 32 + nf * 8 + cc;
            *(float2*)(C + row * N + col)       = make_float2(acc[mf][nf][0], acc[mf][nf][1]);
            *(float2*)(C + (row + 8) * N + col) = make_float2(acc[mf][nf][2], acc[mf][nf][3]);
        }
}

// ============================ RoPE + pack + bf16 splits ========================
__global__ void rope_pack(const float* __restrict__ q, const float* __restrict__ kraw,
                          const float* __restrict__ vraw, float* __restrict__ kv,
                          __nv_bfloat16* __restrict__ qh, __nv_bfloat16* __restrict__ ql,
                          __nv_bfloat16* __restrict__ kh, __nv_bfloat16* __restrict__ kl,
                          __nv_bfloat16* __restrict__ vh, __nv_bfloat16* __restrict__ vl) {
    int idx = blockIdx.x * 256 + threadIdx.x;
    {
        int row = idx >> 10;          // b*T + t
        int rem = idx & 1023;
        int h = rem >> 6, m = rem & 63;
        int b = row >> 11, t = row & 2047;
        float invf = powf(10000.0f, -(float)(2 * m) * (1.0f / 128.0f));
        float ang = (float)t * invf;
        float c = cosf(ang), s = sinf(ang);
        const float scale = 0.08838834764831845f;
        long base = (long)row * (HQ_ * HD_) + h * HD_ + m;
        float x1 = q[base], x2 = q[base + 64];
        float v1 = (x1 * c - x2 * s) * scale;
        float v2 = (x2 * c + x1 * s) * scale;
        long so = ((long)(b * HQ_ + h) * T_ + t) * 128 + m;
        __nv_bfloat16 h1 = __float2bfloat16(v1), h2 = __float2bfloat16(v2);
        qh[so] = h1;      qh[so + 64] = h2;
        ql[so] = __float2bfloat16(v1 - __bfloat162float(h1));
        ql[so + 64] = __float2bfloat16(v2 - __bfloat162float(h2));
    }
    if (idx < MROWS * HK_ * 64) {
        int krow = idx >> 8;
        int krem = idx & 255;
        int khd = krem >> 6, km = krem & 63;
        int b = krow >> 11, t = krow & 2047;
        float invf = powf(10000.0f, -(float)(2 * km) * (1.0f / 128.0f));
        float ang = (float)t * invf;
        float c = cosf(ang), s = sinf(ang);
        long src = (long)krow * (HK_ * HD_) + khd * HD_ + km;
        float x1 = kraw[src], x2 = kraw[src + 64];
        float v1 = x1 * c - x2 * s;
        float v2 = x2 * c + x1 * s;
        long dst = ((long)krow * HK_ + khd) * 256 + km;
        kv[dst]      = v1;
        kv[dst + 64] = v2;
        long so = ((long)(b * HK_ + khd) * T_ + t) * 128 + km;
        __nv_bfloat16 h1 = __float2bfloat16(v1), h2 = __float2bfloat16(v2);
        kh[so] = h1;      kh[so + 64] = h2;
        kl[so] = __float2bfloat16(v1 - __bfloat162float(h1));
        kl[so + 64] = __float2bfloat16(v2 - __bfloat162float(h2));
    }
    if (idx < KVELEMS / 4) {
        int f = idx;
        int vrow = f >> 7;
        int vc4 = f & 127;
        int vhd = vc4 >> 5, vd4 = (vc4 & 31) << 2;
        int b = vrow >> 11, t = vrow & 2047;
        float4 v = *(const float4*)(vraw + (long)f * 4);
        long dst = ((long)vrow * HK_ + vhd) * 256 + 128 + vd4;
        *(float4*)(kv + dst) = v;
        long so = ((long)(b * HK_ + vhd) * T_ + t) * 128 + vd4;
        float vv[4] = {v.x, v.y, v.z, v.w};
        #pragma unroll
        for (int j = 0; j < 4; j++) {
            __nv_bfloat16 hj = __float2bfloat16(vv[j]);
            vh[so + j] = hj;
            vl[so + j] = __float2bfloat16(vv[j] - __bfloat162float(hj));
        }
    }
}

// ============================ threefry (partitionable) =========================
__device__ __forceinline__ unsigned tf_rotl(unsigned x, int r) {
    return (x << r) | (x >> (32 - r));
}
__device__ __forceinline__ float dropout_keep(unsigned e) {
    unsigned x0 = 0u, x1 = e;
    const unsigned k0 = 0u, k1 = 1u, k2 = 0x1BD11BDAu ^ k0 ^ k1;
    x0 += k0; x1 += k1;
#define TFR(r) { x0 += x1; x1 = tf_rotl(x1, r); x1 ^= x0; }
    TFR(13) TFR(15) TFR(26) TFR(6)
    x0 += k1; x1 += k2 + 1u;
    TFR(17) TFR(29) TFR(16) TFR(24)
    x0 += k2; x1 += k0 + 2u;
    TFR(13) TFR(15) TFR(26) TFR(6)
    x0 += k0; x1 += k1 + 3u;
    TFR(17) TFR(29) TFR(16) TFR(24)
    x0 += k1; x1 += k2 + 4u;
    TFR(13) TFR(15) TFR(26) TFR(6)
    x0 += k2; x1 += k0 + 5u;
#undef TFR
    unsigned bits = x0 ^ x1;
    float u = __uint_as_float((bits >> 9) | 0x3F800000u) - 1.0f;
    return (u < 0.9f) ? (1.0f / 0.9f) : 0.0f;
}

// ============================ tensor-core attention ============================
#define A_QH 0
#define A_QL (A_QH + 128*256)
#define A_KH (A_QL + 128*256)
#define A_KL (A_KH + 64*256)
#define A_VH (A_KL + 64*256)
#define A_VL (A_VH + 64*256)
#define A_TOT (A_VL + 64*256)    // 131072 bytes

__global__ void __launch_bounds__(256) attn_mma(
    const __nv_bfloat16* __restrict__ Qh, const __nv_bfloat16* __restrict__ Ql,
    const __nv_bfloat16* __restrict__ Kh, const __nv_bfloat16* __restrict__ Kl,
    const __nv_bfloat16* __restrict__ Vh, const __nv_bfloat16* __restrict__ Vl,
    float* __restrict__ O) {
    extern __shared__ char smem[];
    uint32_t sb = smem_u32(smem);
    int tid = threadIdx.x, lane = tid & 31, wid = tid >> 5;
    int qb = (gridDim.x - 1) - blockIdx.x;
    int bh = blockIdx.y;
    int b = bh >> 4, hq = bh & 15, hk = hq & 3;

    const __nv_bfloat16* qhp = Qh + ((long)(b * HQ_ + hq) * T_ + qb * 128) * 128;
    const __nv_bfloat16* qlp = Ql + ((long)(b * HQ_ + hq) * T_ + qb * 128) * 128;
    const __nv_bfloat16* khp = Kh + (long)(b * HK_ + hk) * T_ * 128;
    const __nv_bfloat16* klp = Kl + (long)(b * HK_ + hk) * T_ * 128;
    const __nv_bfloat16* vhp = Vh + (long)(b * HK_ + hk) * T_ * 128;
    const __nv_bfloat16* vlp = Vl + (long)(b * HK_ + hk) * T_ * 128;

    #pragma unroll
    for (int it = 0; it < 16; it++) {
        int lin = tid + it * 256;
        int arr = lin >> 11, cidx = lin & 2047;
        int row = cidx >> 4, ch = cidx & 15;
        const __nv_bfloat16* src = (arr ? qlp : qhp) + row * 128 + ch * 8;
        cpasync16(sb + (arr ? A_QL : A_QH) + asw(row, ch), src);
    }

    int qrw = wid * 16;
    float m1 = -INFINITY, m2 = -INFINITY, l1 = 0.f, l2 = 0.f;
    float o[16][4];
    #pragma unroll
    for (int nf = 0; nf < 16; nf++)
        #pragma unroll
        for (int c = 0; c < 4; c++) o[nf][c] = 0.f;

    unsigned ebase = (unsigned)(b * 16 + hq) * 4194304u;
    int ig1 = qb * 128 + qrw + (lane >> 2);

    int a_row = qrw + ((lane >> 3) & 1) * 8 + (lane & 7);
    int a_chb = lane >> 4;
    int k_row8 = ((lane >> 4)) * 8 + (lane & 7);
    int k_chb = (lane >> 3) & 1;
    int v_row8 = ((lane >> 3) & 1) * 8 + (lane & 7);
    int v_chb = lane >> 4;

    int njb = 2 * qb + 2;
    for (int jb = 0; jb < njb; jb++) {
        #pragma unroll
        for (int it = 0; it < 16; it++) {
            int lin = tid + it * 256;
            int arr = lin >> 10, cidx = lin & 1023;
            int row = cidx >> 4, ch = cidx & 15;
            long g = (long)(jb * 64 + row) * 128 + ch * 8;
            const __nv_bfloat16* src = (arr == 0 ? khp : arr == 1 ? klp : arr == 2 ? vhp : vlp) + g;
            cpasync16(sb + A_KH + arr * 16384 + asw(row, ch), src);
        }
        asm volatile("cp.async.commit_group;" ::: "memory");
        asm volatile("cp.async.wait_group 0;" ::: "memory");
        __syncthreads();

        float sc[8][4];
        #pragma unroll
        for (int nf = 0; nf < 8; nf++)
            #pragma unroll
            for (int c = 0; c < 4; c++) sc[nf][c] = 0.f;
        #pragma unroll
        for (int ks = 0; ks < 8; ks++) {
            uint32_t qh4[4], ql4[4];
            ldsm4(qh4[0], qh4[1], qh4[2], qh4[3], sb + A_QH + asw(a_row, 2 * ks + a_chb));
            ldsm4(ql4[0], ql4[1], ql4[2], ql4[3], sb + A_QL + asw(a_row, 2 * ks + a_chb));
            #pragma unroll
            for (int nfp = 0; nfp < 4; nfp++) {
                uint32_t kh4[4], kl4[4];
                int br = nfp * 16 + k_row8;
                int bc = 2 * ks + k_chb;
                ldsm4(kh4[0], kh4[1], kh4[2], kh4[3], sb + A_KH + asw(br, bc));
                ldsm4(kl4[0], kl4[1], kl4[2], kl4[3], sb + A_KL + asw(br, bc));
                mma16816(sc[2 * nfp],     qh4, kh4);
                mma16816(sc[2 * nfp],     qh4, kl4);
                mma16816(sc[2 * nfp],     ql4, kh4);
                mma16816(sc[2 * nfp + 1], qh4, kh4 + 2);
                mma16816(sc[2 * nfp + 1], qh4, kl4 + 2);
                mma16816(sc[2 * nfp + 1], ql4, kh4 + 2);
            }
        }

        if (jb * 64 + 63 > qb * 128 + qrw) {
            #pragma unroll
            for (int nf = 0; nf < 8; nf++) {
                int j0 = jb * 64 + nf * 8 + (lane & 3) * 2;
                if (j0 > ig1)     sc[nf][0] = -INFINITY;
                if (j0 + 1 > ig1) sc[nf][1] = -INFINITY;
                if (j0 > ig1 + 8)     sc[nf][2] = -INFINITY;
                if (j0 + 1 > ig1 + 8) sc[nf][3] = -INFINITY;
            }
        }

        float mx1 = -INFINITY, mx2 = -INFINITY;
        #pragma unroll
        for (int nf = 0; nf < 8; nf++) {
            mx1 = fmaxf(mx1, fmaxf(sc[nf][0], sc[nf][1]));
            mx2 = fmaxf(mx2, fmaxf(sc[nf][2], sc[nf][3]));
        }
        mx1 = fmaxf(mx1, __shfl_xor_sync(0xffffffffu, mx1, 1));
        mx1 = fmaxf(mx1, __shfl_xor_sync(0xffffffffu, mx1, 2));
        mx2 = fmaxf(mx2, __shfl_xor_sync(0xffffffffu, mx2, 1));
        mx2 = fmaxf(mx2, __shfl_xor_sync(0xffffffffu, mx2, 2));
        float mn1 = fmaxf(m1, mx1), mn2 = fmaxf(m2, mx2);
        float cr1 = expf(m1 - mn1), cr2 = expf(m2 - mn2);
        float rs1 = 0.f, rs2 = 0.f;
        #pragma unroll
        for (int nf = 0; nf < 8; nf++) {
            sc[nf][0] = expf(sc[nf][0] - mn1); rs1 += sc[nf][0];
            sc[nf][1] = expf(sc[nf][1] - mn1); rs1 += sc[nf][1];
            sc[nf][2] = expf(sc[nf][2] - mn2); rs2 += sc[nf][2];
            sc[nf][3] = expf(sc[nf][3] - mn2); rs2 += sc[nf][3];
        }
        rs1 += __shfl_xor_sync(0xffffffffu, rs1, 1);
        rs1 += __shfl_xor_sync(0xffffffffu, rs1, 2);
        rs2 += __shfl_xor_sync(0xffffffffu, rs2, 1);
        rs2 += __shfl_xor_sync(0xffffffffu, rs2, 2);
        l1 = l1 * cr1 + rs1;  l2 = l2 * cr2 + rs2;
        m1 = mn1;  m2 = mn2;
        #pragma unroll
        for (int nf = 0; nf < 16; nf++) {
            o[nf][0] *= cr1; o[nf][1] *= cr1;
            o[nf][2] *= cr2; o[nf][3] *= cr2;
        }

        #pragma unroll
        for (int nf = 0; nf < 8; nf++) {
            unsigned j0 = (unsigned)(jb * 64 + nf * 8 + (lane & 3) * 2);
            sc[nf][0] *= dropout_keep(ebase + (unsigned)ig1 * 2048u + j0);
            sc[nf][1] *= dropout_keep(ebase + (unsigned)ig1 * 2048u + j0 + 1u);
            sc[nf][2] *= dropout_keep(ebase + (unsigned)(ig1 + 8) * 2048u + j0);
            sc[nf][3] *= dropout_keep(ebase + (unsigned)(ig1 + 8) * 2048u + j0 + 1u);
        }

        #pragma unroll
        for (int ksj = 0; ksj < 4; ksj++) {
            uint32_t ahi[4], alo[4];
            #pragma unroll
            for (int half = 0; half < 2; half++) {
                int nf = 2 * ksj + half;
                __nv_bfloat16 h0 = __float2bfloat16(sc[nf][0]);
                __nv_bfloat16 h1 = __float2bfloat16(sc[nf][1]);
                __nv_bfloat16 h2 = __float2bfloat16(sc[nf][2]);
                __nv_bfloat16 h3 = __float2bfloat16(sc[nf][3]);
                __nv_bfloat162 hh01 = __halves2bfloat162(h0, h1);
                __nv_bfloat162 hh23 = __halves2bfloat162(h2, h3);
                ahi[2 * half]     = *reinterpret_cast<uint32_t*>(&hh01);
                ahi[2 * half + 1] = *reinterpret_cast<uint32_t*>(&hh23);
                __nv_bfloat162 ll01 = __halves2bfloat162(
                    __float2bfloat16(sc[nf][0] - __bfloat162float(h0)),
                    __float2bfloat16(sc[nf][1] - __bfloat162float(h1)));
                __nv_bfloat162 ll23 = __halves2bfloat162(
                    __float2bfloat16(sc[nf][2] - __bfloat162float(h2)),
                    __float2bfloat16(sc[nf][3] - __bfloat162float(h3)));
                alo[2 * half]     = *reinterpret_cast<uint32_t*>(&ll01);
                alo[2 * half + 1] = *reinterpret_cast<uint32_t*>(&ll23);
            }
            #pragma unroll
            for (int nfp = 0; nfp < 8; nfp++) {
                uint32_t vh4[4], vl4[4];
                int vr = ksj * 16 + v_row8;
                int vc = 2 * nfp + v_chb;
                ldsm4t(vh4[0], vh4[1], vh4[2], vh4[3], sb + A_VH + asw(vr, vc));
                ldsm4t(vl4[0], vl4[1], vl4[2], vl4[3], sb + A_VL + asw(vr, vc));
                mma16816(o[2 * nfp],     ahi, vh4);
                mma16816(o[2 * nfp],     ahi, vl4);
                mma16816(o[2 * nfp],     alo, vh4);
                mma16816(o[2 * nfp + 1], ahi, vh4 + 2);
                mma16816(o[2 * nfp + 1], ahi, vl4 + 2);
                mma16816(o[2 * nfp + 1], alo, vh4 + 2);
            }
        }
        __syncthreads();
    }

    float inv1 = 1.f / l1, inv2 = 1.f / l2;
    long r1g = (long)(b * T_ + qb * 128 + qrw + (lane >> 2));
    #pragma unroll
    for (int nf = 0; nf < 16; nf++) {
        int col = hq * 128 + nf * 8 + (lane & 3) * 2;
        *(float2*)(O + r1g * 2048 + col)       = make_float2(o[nf][0] * inv1, o[nf][1] * inv1);
        *(float2*)(O + (r1g + 8) * 2048 + col) = make_float2(o[nf][2] * inv2, o[nf][3] * inv2);
    }
}

// ============================ launch ===========================================
extern "C" void kernel_launch(void* const* d_in, const int* in_sizes, int n_in,
                              void* d_out, int out_size) {
    const float* x  = (const float*)d_in[0];
    const float* wq = (const float*)d_in[1];
    const float* wk = (const float*)d_in[2];
    const float* wv = (const float*)d_in[3];
    const float* wo = (const float*)d_in[4];
    float* out = (float*)d_out;
    float* kv  = out + QELEMS;

    float *qp, *kp, *vp, *ap;
    cudaGetSymbolAddress((void**)&qp, g_q);
    cudaGetSymbolAddress((void**)&kp, g_kraw);
    cudaGetSymbolAddress((void**)&vp, g_vraw);
    cudaGetSymbolAddress((void**)&ap, g_attn);
    __nv_bfloat16 *xs0, *xs1, *wqT0, *wqT1, *wkT0, *wkT1, *wvT0, *wvT1, *woT0, *woT1;
    __nv_bfloat16 *aqh, *aql, *akh, *akl, *avh, *avl;
    cudaGetSymbolAddress((void**)&xs0, g_xs0);
    cudaGetSymbolAddress((void**)&xs1, g_xs1);
    cudaGetSymbolAddress((void**)&wqT0, g_wqT0);
    cudaGetSymbolAddress((void**)&wqT1, g_wqT1);
    cudaGetSymbolAddress((void**)&wkT0, g_wkT0);
    cudaGetSymbolAddress((void**)&wkT1, g_wkT1);
    cudaGetSymbolAddress((void**)&wvT0, g_wvT0);
    cudaGetSymbolAddress((void**)&wvT1, g_wvT1);
    cudaGetSymbolAddress((void**)&woT0, g_woT0);
    cudaGetSymbolAddress((void**)&woT1, g_woT1);
    cudaGetSymbolAddress((void**)&aqh, g_aqh);
    cudaGetSymbolAddress((void**)&aql, g_aql);
    cudaGetSymbolAddress((void**)&akh, g_akh);
    cudaGetSymbolAddress((void**)&akl, g_akl);
    cudaGetSymbolAddress((void**)&avh, g_avh);
    cudaGetSymbolAddress((void**)&avl, g_avl);

    cudaFuncSetAttribute(gemm_mma, cudaFuncAttributeMaxDynamicSharedMemorySize, GSM_TOT);
    cudaFuncSetAttribute(attn_mma, cudaFuncAttributeMaxDynamicSharedMemorySize, A_TOT);

    // prep
    split_f32<<<(MROWS * D_ / 4) / 256, 256>>>(x, xs0, xs1);
    wsplitT<<<dim3(D_ / 32, D_ / 32), dim3(32, 8)>>>(wq, wqT0, wqT1, D_);
    wsplitT<<<dim3(512 / 32, D_ / 32), dim3(32, 8)>>>(wk, wkT0, wkT1, 512);
    wsplitT<<<dim3(512 / 32, D_ / 32), dim3(32, 8)>>>(wv, wvT0, wvT1, 512);
    wsplitT<<<dim3(D_ / 32, D_ / 32), dim3(32, 8)>>>(wo, woT0, woT1, D_);

    // fused q/k/v projections (tensor pipe)
    gemm_mma<<<dim3(48, MROWS / 128), 256, GSM_TOT>>>(
        xs0, xs1, wqT0, wqT1, wkT0, wkT1, wvT0, wvT1, qp, kp, vp);

    rope_pack<<<(MROWS * HQ_ * 64) / 256, 256>>>(qp, kp, vp, kv, aqh, aql, akh, akl, avh, avl);

    // tensor-core attention
    attn_mma<<<dim3(T_ / 128, B_ * HQ_), 256, A_TOT>>>(aqh, aql, akh, akl, avh, avl, ap);

    // out projection
    split_f32<<<(MROWS * D_ / 4) / 256, 256>>>(ap, xs0, xs1);
    gemm_mma<<<dim3(32, MROWS / 128), 256, GSM_TOT>>>(
        xs0, xs1, woT0, woT1, woT0, woT1, woT0, woT1, out, out, out);
}

// round 8
// speedup vs baseline: 1.1972x; 1.0727x over previous
#include <cuda_runtime.h>
#include <cuda_bf16.h>
#include <math.h>
#include <stdint.h>

#define B_   2
#define T_   2048
#define D_   2048
#define HQ_  16
#define HK_  4
#define HD_  128
#define MROWS (B_*T_)            // 4096
#define QELEMS (MROWS*HQ_*HD_)   // 8388608
#define KVELEMS (MROWS*HK_*HD_)  // 2097152
#define NTRIPLES 8704            // 32 bh * sum_{qb<16}(2qb+2)

// fp32 scratch
__device__ float g_q[QELEMS];
__device__ float g_kraw[KVELEMS];
__device__ float g_vraw[KVELEMS];
__device__ float g_attn[QELEMS];
// dropout mask bits: [bh(32)][qb(16)][jb(32)][wid(8)][lane(32)] one uint32 each
__device__ uint32_t g_mask[32*16*32*8*32];   // 16 MB
// bf16 split scratch (GEMM)
__device__ __nv_bfloat16 g_xs0[MROWS*D_];
__device__ __nv_bfloat16 g_xs1[MROWS*D_];
__device__ __nv_bfloat16 g_wqT0[D_*D_], g_wqT1[D_*D_];
__device__ __nv_bfloat16 g_wkT0[512*D_], g_wkT1[512*D_];
__device__ __nv_bfloat16 g_wvT0[512*D_], g_wvT1[512*D_];
__device__ __nv_bfloat16 g_woT0[D_*D_], g_woT1[D_*D_];
// bf16 split scratch (attention), head-major [b][h][t][128]
__device__ __nv_bfloat16 g_aqh[QELEMS], g_aql[QELEMS];
__device__ __nv_bfloat16 g_akh[KVELEMS], g_akl[KVELEMS];
__device__ __nv_bfloat16 g_avh[KVELEMS], g_avl[KVELEMS];

// ============================ helpers =========================================
__device__ __forceinline__ uint32_t smem_u32(const void* p) {
    uint32_t a;
    asm("{ .reg .u64 t; cvta.to.shared.u64 t, %1; cvt.u32.u64 %0, t; }" : "=r"(a) : "l"(p));
    return a;
}
__device__ __forceinline__ void cpasync16(uint32_t s, const void* g) {
    asm volatile("cp.async.cg.shared.global [%0], [%1], 16;" :: "r"(s), "l"(g));
}
__device__ __forceinline__ void ldsm4(uint32_t& r0, uint32_t& r1, uint32_t& r2, uint32_t& r3,
                                      uint32_t addr) {
    asm volatile("ldmatrix.sync.aligned.m8n8.x4.shared.b16 {%0,%1,%2,%3}, [%4];"
                 : "=r"(r0), "=r"(r1), "=r"(r2), "=r"(r3) : "r"(addr));
}
__device__ __forceinline__ void ldsm4t(uint32_t& r0, uint32_t& r1, uint32_t& r2, uint32_t& r3,
                                       uint32_t addr) {
    asm volatile("ldmatrix.sync.aligned.m8n8.x4.trans.shared.b16 {%0,%1,%2,%3}, [%4];"
                 : "=r"(r0), "=r"(r1), "=r"(r2), "=r"(r3) : "r"(addr));
}
__device__ __forceinline__ void mma16816(float* c, const uint32_t* a, const uint32_t* b) {
    asm volatile("mma.sync.aligned.m16n8k16.row.col.f32.bf16.bf16.f32 "
                 "{%0,%1,%2,%3}, {%4,%5,%6,%7}, {%8,%9}, {%0,%1,%2,%3};"
                 : "+f"(c[0]), "+f"(c[1]), "+f"(c[2]), "+f"(c[3])
                 : "r"(a[0]), "r"(a[1]), "r"(a[2]), "r"(a[3]), "r"(b[0]), "r"(b[1]));
}
// GEMM tile swizzle: [rows][32 bf16] (64B rows, 16B chunks)
__device__ __forceinline__ uint32_t swadr(int row, int ch) {
    return (uint32_t)(row * 64 + ((ch ^ ((row >> 1) & 3)) << 4));
}
// attention tile swizzle: [rows][128 bf16] (256B rows, 16 chunks of 16B)
__device__ __forceinline__ uint32_t asw(int row, int ch) {
    return (uint32_t)(row * 256 + ((ch ^ (row & 7)) << 4));
}

// ============================ threefry (partitionable) =========================
__device__ __forceinline__ unsigned tf_rotl(unsigned x, int r) {
    return (x << r) | (x >> (32 - r));
}
__device__ __forceinline__ unsigned dropout_bit(unsigned e) {
    unsigned x0 = 0u, x1 = e;
    const unsigned k0 = 0u, k1 = 1u, k2 = 0x1BD11BDAu ^ k0 ^ k1;
    x0 += k0; x1 += k1;
#define TFR(r) { x0 += x1; x1 = tf_rotl(x1, r); x1 ^= x0; }
    TFR(13) TFR(15) TFR(26) TFR(6)
    x0 += k1; x1 += k2 + 1u;
    TFR(17) TFR(29) TFR(16) TFR(24)
    x0 += k2; x1 += k0 + 2u;
    TFR(13) TFR(15) TFR(26) TFR(6)
    x0 += k0; x1 += k1 + 3u;
    TFR(17) TFR(29) TFR(16) TFR(24)
    x0 += k1; x1 += k2 + 4u;
    TFR(13) TFR(15) TFR(26) TFR(6)
    x0 += k2; x1 += k0 + 5u;
#undef TFR
    unsigned bits = x0 ^ x1;
    float u = __uint_as_float((bits >> 9) | 0x3F800000u) - 1.0f;
    return (u < 0.9f) ? 1u : 0u;
}

// ============================ split / transpose preps ==========================
__global__ void split_f32(const float* __restrict__ in, __nv_bfloat16* __restrict__ o0,
                          __nv_bfloat16* __restrict__ o1) {
    int i = blockIdx.x * 256 + threadIdx.x;
    float4 v = ((const float4*)in)[i];
    __nv_bfloat16 h[4], l[4];
    float vv[4] = {v.x, v.y, v.z, v.w};
    #pragma unroll
    for (int j = 0; j < 4; j++) {
        h[j] = __float2bfloat16(vv[j]);
        l[j] = __float2bfloat16(vv[j] - __bfloat162float(h[j]));
    }
    ((ushort4*)o0)[i] = make_ushort4(*(unsigned short*)&h[0], *(unsigned short*)&h[1],
                                     *(unsigned short*)&h[2], *(unsigned short*)&h[3]);
    ((ushort4*)o1)[i] = make_ushort4(*(unsigned short*)&l[0], *(unsigned short*)&l[1],
                                     *(unsigned short*)&l[2], *(unsigned short*)&l[3]);
}

__global__ void wsplitT(const float* __restrict__ W, __nv_bfloat16* __restrict__ t0,
                        __nv_bfloat16* __restrict__ t1, int N) {
    __shared__ float tile[32][33];
    int n0 = blockIdx.x * 32, k0 = blockIdx.y * 32;
    int tx = threadIdx.x, ty = threadIdx.y;
    #pragma unroll
    for (int i = 0; i < 4; i++)
        tile[ty + i * 8][tx] = W[(long)(k0 + ty + i * 8) * N + n0 + tx];
    __syncthreads();
    #pragma unroll
    for (int i = 0; i < 4; i++) {
        float v = tile[tx][ty + i * 8];
        __nv_bfloat16 h = __float2bfloat16(v);
        __nv_bfloat16 l = __float2bfloat16(v - __bfloat162float(h));
        long o = (long)(n0 + ty + i * 8) * 2048 + k0 + tx;
        t0[o] = h; t1[o] = l;
    }
}

// ============================ mma.sync bf16x3 GEMM (fused qkv + mask gen) ======
#define STG_BYTES 24576
#define OFF_AH 0
#define OFF_AL 8192
#define OFF_BH 16384
#define OFF_BL 20480
#define GSM_TOT (3*STG_BYTES)   // 73728

__global__ void __launch_bounds__(256) gemm_mma(
    const __nv_bfloat16* __restrict__ A0, const __nv_bfloat16* __restrict__ A1,
    const __nv_bfloat16* __restrict__ Bq0, const __nv_bfloat16* __restrict__ Bq1,
    const __nv_bfloat16* __restrict__ Bk0, const __nv_bfloat16* __restrict__ Bk1,
    const __nv_bfloat16* __restrict__ Bv0, const __nv_bfloat16* __restrict__ Bv1,
    float* __restrict__ Cq, float* __restrict__ Ck, float* __restrict__ Cv,
    uint32_t* __restrict__ mask) {
    extern __shared__ char smem[];
    uint32_t sb = smem_u32(smem);
    int tid = threadIdx.x, lane = tid & 31, wid = tid >> 5;
    int wm = wid & 3, wn = wid >> 2;
    long m0 = (long)blockIdx.y * 128;

    const __nv_bfloat16 *B0, *B1;
    float* C;
    int N, n0;
    int nb = blockIdx.x;
    if (nb < 32)      { B0 = Bq0; B1 = Bq1; C = Cq; N = 2048; n0 = nb * 64; }
    else if (nb < 40) { B0 = Bk0; B1 = Bk1; C = Ck; N = 512;  n0 = (nb - 32) * 64; }
    else              { B0 = Bv0; B1 = Bv1; C = Cv; N = 512;  n0 = (nb - 40) * 64; }

    int lrow = lane & 7, ltile = lane >> 3;
    int a_row = wm * 32 + ((ltile & 1) << 3) + lrow;
    int a_ch  = ltile >> 1;
    int b_row = wn * 32 + ((ltile >> 1) << 3) + lrow;
    int b_ch  = ltile & 1;

    float acc[2][4][4];
    #pragma unroll
    for (int mf = 0; mf < 2; mf++)
        #pragma unroll
        for (int nf = 0; nf < 4; nf++)
            #pragma unroll
            for (int j = 0; j < 4; j++) acc[mf][nf][j] = 0.f;

    int ar0 = tid >> 2, ach = tid & 3;
    int br  = tid >> 2, bch = tid & 3;

    // ---- interleaved dropout-mask generation state ----
    int mstride = gridDim.x * gridDim.y;              // 1536 for qkv launch
    int mt = mask ? (blockIdx.y * gridDim.x + blockIdx.x) : NTRIPLES;
    int mh = 0;
    uint32_t mword = 0;
    unsigned mebase = 0;
    int mrowb = 0, mcolb = 0;
    long mwidx = 0;

    auto mask_step = [&]() {
        if (mt >= NTRIPLES) return;
        if (mh == 0) {
            int bh = mt / 272;
            int r = mt - bh * 272;
            int qb = 0;
            while (r >= 2 * qb + 2) { r -= 2 * qb + 2; qb++; }
            int jb = r;
            mebase = (unsigned)bh * 4194304u;
            mrowb = qb * 128 + wid * 16 + (lane >> 2);
            mcolb = jb * 64 + (lane & 3) * 2;
            mwidx = ((((long)bh * 16 + qb) * 32 + jb) * 8 + wid) * 32 + lane;
        }
        int nf = mh >> 2, rs = (mh >> 1) & 1, cs = mh & 1;
        unsigned e = mebase + (unsigned)(mrowb + rs * 8) * 2048u
                            + (unsigned)(mcolb + nf * 8 + cs);
        mword |= dropout_bit(e) << mh;
        mh++;
        if (mh == 32) { mask[mwidx] = mword; mword = 0; mh = 0; mt += mstride; }
    };

    auto issue = [&](int st, int kc) {
        uint32_t base = sb + st * STG_BYTES;
        #pragma unroll
        for (int p = 0; p < 2; p++) {
            int r = ar0 + p * 64;
            uint32_t sw = swadr(r, ach);
            long g = (m0 + r) * 2048 + kc + ach * 8;
            cpasync16(base + OFF_AH + sw, A0 + g);
            cpasync16(base + OFF_AL + sw, A1 + g);
        }
        {
            uint32_t sw = swadr(br, bch);
            long g = (long)(n0 + br) * 2048 + kc + bch * 8;
            cpasync16(base + OFF_BH + sw, B0 + g);
            cpasync16(base + OFF_BL + sw, B1 + g);
        }
        asm volatile("cp.async.commit_group;" ::: "memory");
    };

    const int KI = 2048 / 32;
    issue(0, 0);
    issue(1, 32);
    int stage = 0;
    for (int kci = 0; kci < KI; kci++) {
        if (kci + 1 < KI) {
            asm volatile("cp.async.wait_group 1;" ::: "memory");
        } else {
            asm volatile("cp.async.wait_group 0;" ::: "memory");
        }
        __syncthreads();
        if (kci + 2 < KI) issue((stage + 2) % 3, (kci + 2) * 32);

        uint32_t base = sb + stage * STG_BYTES;
        #pragma unroll
        for (int ks = 0; ks < 2; ks++) {
            uint32_t ah[2][4], al[2][4];
            #pragma unroll
            for (int mf = 0; mf < 2; mf++) {
                uint32_t adr = base + OFF_AH + swadr(a_row + mf * 16, ks * 2 + a_ch);
                ldsm4(ah[mf][0], ah[mf][1], ah[mf][2], ah[mf][3], adr);
                adr = base + OFF_AL + swadr(a_row + mf * 16, ks * 2 + a_ch);
                ldsm4(al[mf][0], al[mf][1], al[mf][2], al[mf][3], adr);
            }
            uint32_t bh[4][2], bl[4][2];
            #pragma unroll
            for (int nf2 = 0; nf2 < 2; nf2++) {
                uint32_t adr = base + OFF_BH + swadr(b_row + nf2 * 16, ks * 2 + b_ch);
                ldsm4(bh[nf2*2][0], bh[nf2*2][1], bh[nf2*2+1][0], bh[nf2*2+1][1], adr);
                adr = base + OFF_BL + swadr(b_row + nf2 * 16, ks * 2 + b_ch);
                ldsm4(bl[nf2*2][0], bl[nf2*2][1], bl[nf2*2+1][0], bl[nf2*2+1][1], adr);
            }
            #pragma unroll
            for (int mf = 0; mf < 2; mf++)
                #pragma unroll
                for (int nf = 0; nf < 4; nf++) {
                    mma16816(acc[mf][nf], ah[mf], bh[nf]);
                    mma16816(acc[mf][nf], ah[mf], bl[nf]);
                    mma16816(acc[mf][nf], al[mf], bh[nf]);
                }
        }
        // absorb threefry into idle ALU slots (3 hashes per thread per chunk)
        mask_step();
        mask_step();
        mask_step();
        stage = (stage + 1) % 3;
    }
    // safety flush (normally a no-op: 3*64 = 192 >= max 6 triples * 32 hashes)
    while (mt < NTRIPLES) mask_step();

    int cr = lane >> 2, cc = (lane & 3) << 1;
    #pragma unroll
    for (int mf = 0; mf < 2; mf++)
        #pragma unroll
        for (int nf = 0; nf < 4; nf++) {
            long row = m0 + wm * 32 + mf * 16 + cr;
            int col = n0 + wn * 32 + nf * 8 + cc;
            *(float2*)(C + row * N + col)       = make_float2(acc[mf][nf][0], acc[mf][nf][1]);
            *(float2*)(C + (row + 8) * N + col) = make_float2(acc[mf][nf][2], acc[mf][nf][3]);
        }
}

// ============================ RoPE + pack + bf16 splits ========================
__global__ void rope_pack(const float* __restrict__ q, const float* __restrict__ kraw,
                          const float* __restrict__ vraw, float* __restrict__ kv,
                          __nv_bfloat16* __restrict__ qh, __nv_bfloat16* __restrict__ ql,
                          __nv_bfloat16* __restrict__ kh, __nv_bfloat16* __restrict__ kl,
                          __nv_bfloat16* __restrict__ vh, __nv_bfloat16* __restrict__ vl) {
    int idx = blockIdx.x * 256 + threadIdx.x;
    {
        int row = idx >> 10;          // b*T + t
        int rem = idx & 1023;
        int h = rem >> 6, m = rem & 63;
        int b = row >> 11, t = row & 2047;
        float invf = powf(10000.0f, -(float)(2 * m) * (1.0f / 128.0f));
        float ang = (float)t * invf;
        float c = cosf(ang), s = sinf(ang);
        const float scale = 0.08838834764831845f;
        long base = (long)row * (HQ_ * HD_) + h * HD_ + m;
        float x1 = q[base], x2 = q[base + 64];
        float v1 = (x1 * c - x2 * s) * scale;
        float v2 = (x2 * c + x1 * s) * scale;
        long so = ((long)(b * HQ_ + h) * T_ + t) * 128 + m;
        __nv_bfloat16 h1 = __float2bfloat16(v1), h2 = __float2bfloat16(v2);
        qh[so] = h1;      qh[so + 64] = h2;
        ql[so] = __float2bfloat16(v1 - __bfloat162float(h1));
        ql[so + 64] = __float2bfloat16(v2 - __bfloat162float(h2));
    }
    if (idx < MROWS * HK_ * 64) {
        int krow = idx >> 8;
        int krem = idx & 255;
        int khd = krem >> 6, km = krem & 63;
        int b = krow >> 11, t = krow & 2047;
        float invf = powf(10000.0f, -(float)(2 * km) * (1.0f / 128.0f));
        float ang = (float)t * invf;
        float c = cosf(ang), s = sinf(ang);
        long src = (long)krow * (HK_ * HD_) + khd * HD_ + km;
        float x1 = kraw[src], x2 = kraw[src + 64];
        float v1 = x1 * c - x2 * s;
        float v2 = x2 * c + x1 * s;
        long dst = ((long)krow * HK_ + khd) * 256 + km;
        kv[dst]      = v1;
        kv[dst + 64] = v2;
        long so = ((long)(b * HK_ + khd) * T_ + t) * 128 + km;
        __nv_bfloat16 h1 = __float2bfloat16(v1), h2 = __float2bfloat16(v2);
        kh[so] = h1;      kh[so + 64] = h2;
        kl[so] = __float2bfloat16(v1 - __bfloat162float(h1));
        kl[so + 64] = __float2bfloat16(v2 - __bfloat162float(h2));
    }
    if (idx < KVELEMS / 4) {
        int f = idx;
        int vrow = f >> 7;
        int vc4 = f & 127;
        int vhd = vc4 >> 5, vd4 = (vc4 & 31) << 2;
        int b = vrow >> 11, t = vrow & 2047;
        float4 v = *(const float4*)(vraw + (long)f * 4);
        long dst = ((long)vrow * HK_ + vhd) * 256 + 128 + vd4;
        *(float4*)(kv + dst) = v;
        long so = ((long)(b * HK_ + vhd) * T_ + t) * 128 + vd4;
        float vv[4] = {v.x, v.y, v.z, v.w};
        #pragma unroll
        for (int j = 0; j < 4; j++) {
            __nv_bfloat16 hj = __float2bfloat16(vv[j]);
            vh[so + j] = hj;
            vl[so + j] = __float2bfloat16(vv[j] - __bfloat162float(hj));
        }
    }
}

// ============================ tensor-core attention ============================
#define A_QH 0
#define A_QL (A_QH + 128*256)
#define A_KH (A_QL + 128*256)
#define A_KL (A_KH + 64*256)
#define A_VH (A_KL + 64*256)
#define A_VL (A_VH + 64*256)
#define A_TOT (A_VL + 64*256)    // 131072 bytes

__global__ void __launch_bounds__(256) attn_mma(
    const __nv_bfloat16* __restrict__ Qh, const __nv_bfloat16* __restrict__ Ql,
    const __nv_bfloat16* __restrict__ Kh, const __nv_bfloat16* __restrict__ Kl,
    const __nv_bfloat16* __restrict__ Vh, const __nv_bfloat16* __restrict__ Vl,
    const uint32_t* __restrict__ Mask, float* __restrict__ O) {
    extern __shared__ char smem[];
    uint32_t sb = smem_u32(smem);
    int tid = threadIdx.x, lane = tid & 31, wid = tid >> 5;
    int qb = (gridDim.x - 1) - blockIdx.x;
    int bh = blockIdx.y;
    int b = bh >> 4, hq = bh & 15, hk = hq & 3;

    const __nv_bfloat16* qhp = Qh + ((long)(b * HQ_ + hq) * T_ + qb * 128) * 128;
    const __nv_bfloat16* qlp = Ql + ((long)(b * HQ_ + hq) * T_ + qb * 128) * 128;
    const __nv_bfloat16* khp = Kh + (long)(b * HK_ + hk) * T_ * 128;
    const __nv_bfloat16* klp = Kl + (long)(b * HK_ + hk) * T_ * 128;
    const __nv_bfloat16* vhp = Vh + (long)(b * HK_ + hk) * T_ * 128;
    const __nv_bfloat16* vlp = Vl + (long)(b * HK_ + hk) * T_ * 128;

    #pragma unroll
    for (int it = 0; it < 16; it++) {
        int lin = tid + it * 256;
        int arr = lin >> 11, cidx = lin & 2047;
        int row = cidx >> 4, ch = cidx & 15;
        const __nv_bfloat16* src = (arr ? qlp : qhp) + row * 128 + ch * 8;
        cpasync16(sb + (arr ? A_QL : A_QH) + asw(row, ch), src);
    }

    int qrw = wid * 16;
    float m1 = -INFINITY, m2 = -INFINITY, l1 = 0.f, l2 = 0.f;
    float o[16][4];
    #pragma unroll
    for (int nf = 0; nf < 16; nf++)
        #pragma unroll
        for (int c = 0; c < 4; c++) o[nf][c] = 0.f;

    int ig1 = qb * 128 + qrw + (lane >> 2);
    long wbase0 = ((long)bh * 16 + qb) * 8192 + wid * 32 + lane;

    int a_row = qrw + ((lane >> 3) & 1) * 8 + (lane & 7);
    int a_chb = lane >> 4;
    int k_row8 = ((lane >> 4)) * 8 + (lane & 7);
    int k_chb = (lane >> 3) & 1;
    int v_row8 = ((lane >> 3) & 1) * 8 + (lane & 7);
    int v_chb = lane >> 4;

    int njb = 2 * qb + 2;
    for (int jb = 0; jb < njb; jb++) {
        #pragma unroll
        for (int it = 0; it < 16; it++) {
            int lin = tid + it * 256;
            int arr = lin >> 10, cidx = lin & 1023;
            int row = cidx >> 4, ch = cidx & 15;
            long g = (long)(jb * 64 + row) * 128 + ch * 8;
            const __nv_bfloat16* src = (arr == 0 ? khp : arr == 1 ? klp : arr == 2 ? vhp : vlp) + g;
            cpasync16(sb + A_KH + arr * 16384 + asw(row, ch), src);
        }
        asm volatile("cp.async.commit_group;" ::: "memory");
        uint32_t mw = Mask[wbase0 + (long)jb * 256];   // precomputed dropout bits
        asm volatile("cp.async.wait_group 0;" ::: "memory");
        __syncthreads();

        float sc[8][4];
        #pragma unroll
        for (int nf = 0; nf < 8; nf++)
            #pragma unroll
            for (int c = 0; c < 4; c++) sc[nf][c] = 0.f;
        #pragma unroll
        for (int ks = 0; ks < 8; ks++) {
            uint32_t qh4[4], ql4[4];
            ldsm4(qh4[0], qh4[1], qh4[2], qh4[3], sb + A_QH + asw(a_row, 2 * ks + a_chb));
            ldsm4(ql4[0], ql4[1], ql4[2], ql4[3], sb + A_QL + asw(a_row, 2 * ks + a_chb));
            #pragma unroll
            for (int nfp = 0; nfp < 4; nfp++) {
                uint32_t kh4[4], kl4[4];
                int br = nfp * 16 + k_row8;
                int bc = 2 * ks + k_chb;
                ldsm4(kh4[0], kh4[1], kh4[2], kh4[3], sb + A_KH + asw(br, bc));
                ldsm4(kl4[0], kl4[1], kl4[2], kl4[3], sb + A_KL + asw(br, bc));
                mma16816(sc[2 * nfp],     qh4, kh4);
                mma16816(sc[2 * nfp],     qh4, kl4);
                mma16816(sc[2 * nfp],     ql4, kh4);
                mma16816(sc[2 * nfp + 1], qh4, kh4 + 2);
                mma16816(sc[2 * nfp + 1], qh4, kl4 + 2);
                mma16816(sc[2 * nfp + 1], ql4, kh4 + 2);
            }
        }

        if (jb * 64 + 63 > qb * 128 + qrw) {
            #pragma unroll
            for (int nf = 0; nf < 8; nf++) {
                int j0 = jb * 64 + nf * 8 + (lane & 3) * 2;
                if (j0 > ig1)     sc[nf][0] = -INFINITY;
                if (j0 + 1 > ig1) sc[nf][1] = -INFINITY;
                if (j0 > ig1 + 8)     sc[nf][2] = -INFINITY;
                if (j0 + 1 > ig1 + 8) sc[nf][3] = -INFINITY;
            }
        }

        float mx1 = -INFINITY, mx2 = -INFINITY;
        #pragma unroll
        for (int nf = 0; nf < 8; nf++) {
            mx1 = fmaxf(mx1, fmaxf(sc[nf][0], sc[nf][1]));
            mx2 = fmaxf(mx2, fmaxf(sc[nf][2], sc[nf][3]));
        }
        mx1 = fmaxf(mx1, __shfl_xor_sync(0xffffffffu, mx1, 1));
        mx1 = fmaxf(mx1, __shfl_xor_sync(0xffffffffu, mx1, 2));
        mx2 = fmaxf(mx2, __shfl_xor_sync(0xffffffffu, mx2, 1));
        mx2 = fmaxf(mx2, __shfl_xor_sync(0xffffffffu, mx2, 2));
        float mn1 = fmaxf(m1, mx1), mn2 = fmaxf(m2, mx2);
        float cr1 = __expf(m1 - mn1), cr2 = __expf(m2 - mn2);
        float rs1 = 0.f, rs2 = 0.f;
        #pragma unroll
        for (int nf = 0; nf < 8; nf++) {
            sc[nf][0] = __expf(sc[nf][0] - mn1); rs1 += sc[nf][0];
            sc[nf][1] = __expf(sc[nf][1] - mn1); rs1 += sc[nf][1];
            sc[nf][2] = __expf(sc[nf][2] - mn2); rs2 += sc[nf][2];
            sc[nf][3] = __expf(sc[nf][3] - mn2); rs2 += sc[nf][3];
        }
        rs1 += __shfl_xor_sync(0xffffffffu, rs1, 1);
        rs1 += __shfl_xor_sync(0xffffffffu, rs1, 2);
        rs2 += __shfl_xor_sync(0xffffffffu, rs2, 1);
        rs2 += __shfl_xor_sync(0xffffffffu, rs2, 2);
        l1 = l1 * cr1 + rs1;  l2 = l2 * cr2 + rs2;   // denom WITHOUT dropout (matches ref)
        m1 = mn1;  m2 = mn2;
        #pragma unroll
        for (int nf = 0; nf < 16; nf++) {
            o[nf][0] *= cr1; o[nf][1] *= cr1;
            o[nf][2] *= cr2; o[nf][3] *= cr2;
        }

        // dropout from precomputed mask bits
        #pragma unroll
        for (int nf = 0; nf < 8; nf++) {
            sc[nf][0] *= ((mw >> (nf * 4 + 0)) & 1u) ? (1.0f / 0.9f) : 0.f;
            sc[nf][1] *= ((mw >> (nf * 4 + 1)) & 1u) ? (1.0f / 0.9f) : 0.f;
            sc[nf][2] *= ((mw >> (nf * 4 + 2)) & 1u) ? (1.0f / 0.9f) : 0.f;
            sc[nf][3] *= ((mw >> (nf * 4 + 3)) & 1u) ? (1.0f / 0.9f) : 0.f;
        }

        #pragma unroll
        for (int ksj = 0; ksj < 4; ksj++) {
            uint32_t ahi[4], alo[4];
            #pragma unroll
            for (int half = 0; half < 2; half++) {
                int nf = 2 * ksj + half;
                __nv_bfloat16 h0 = __float2bfloat16(sc[nf][0]);
                __nv_bfloat16 h1 = __float2bfloat16(sc[nf][1]);
                __nv_bfloat16 h2 = __float2bfloat16(sc[nf][2]);
                __nv_bfloat16 h3 = __float2bfloat16(sc[nf][3]);
                __nv_bfloat162 hh01 = __halves2bfloat162(h0, h1);
                __nv_bfloat162 hh23 = __halves2bfloat162(h2, h3);
                ahi[2 * half]     = *reinterpret_cast<uint32_t*>(&hh01);
                ahi[2 * half + 1] = *reinterpret_cast<uint32_t*>(&hh23);
                __nv_bfloat162 ll01 = __halves2bfloat162(
                    __float2bfloat16(sc[nf][0] - __bfloat162float(h0)),
                    __float2bfloat16(sc[nf][1] - __bfloat162float(h1)));
                __nv_bfloat162 ll23 = __halves2bfloat162(
                    __float2bfloat16(sc[nf][2] - __bfloat162float(h2)),
                    __float2bfloat16(sc[nf][3] - __bfloat162float(h3)));
                alo[2 * half]     = *reinterpret_cast<uint32_t*>(&ll01);
                alo[2 * half + 1] = *reinterpret_cast<uint32_t*>(&ll23);
            }
            #pragma unroll
            for (int nfp = 0; nfp < 8; nfp++) {
                uint32_t vh4[4], vl4[4];
                int vr = ksj * 16 + v_row8;
                int vc = 2 * nfp + v_chb;
                ldsm4t(vh4[0], vh4[1], vh4[2], vh4[3], sb + A_VH + asw(vr, vc));
                ldsm4t(vl4[0], vl4[1], vl4[2], vl4[3], sb + A_VL + asw(vr, vc));
                mma16816(o[2 * nfp],     ahi, vh4);
                mma16816(o[2 * nfp],     ahi, vl4);
                mma16816(o[2 * nfp],     alo, vh4);
                mma16816(o[2 * nfp + 1], ahi, vh4 + 2);
                mma16816(o[2 * nfp + 1], ahi, vl4 + 2);
                mma16816(o[2 * nfp + 1], alo, vh4 + 2);
            }
        }
        __syncthreads();
    }

    float inv1 = 1.f / l1, inv2 = 1.f / l2;
    long r1g = (long)(b * T_ + qb * 128 + qrw + (lane >> 2));
    #pragma unroll
    for (int nf = 0; nf < 16; nf++) {
        int col = hq * 128 + nf * 8 + (lane & 3) * 2;
        *(float2*)(O + r1g * 2048 + col)       = make_float2(o[nf][0] * inv1, o[nf][1] * inv1);
        *(float2*)(O + (r1g + 8) * 2048 + col) = make_float2(o[nf][2] * inv2, o[nf][3] * inv2);
    }
}

// ============================ launch ===========================================
extern "C" void kernel_launch(void* const* d_in, const int* in_sizes, int n_in,
                              void* d_out, int out_size) {
    const float* x  = (const float*)d_in[0];
    const float* wq = (const float*)d_in[1];
    const float* wk = (const float*)d_in[2];
    const float* wv = (const float*)d_in[3];
    const float* wo = (const float*)d_in[4];
    float* out = (float*)d_out;
    float* kv  = out + QELEMS;

    float *qp, *kp, *vp, *ap;
    cudaGetSymbolAddress((void**)&qp, g_q);
    cudaGetSymbolAddress((void**)&kp, g_kraw);
    cudaGetSymbolAddress((void**)&vp, g_vraw);
    cudaGetSymbolAddress((void**)&ap, g_attn);
    uint32_t* maskp;
    cudaGetSymbolAddress((void**)&maskp, g_mask);
    __nv_bfloat16 *xs0, *xs1, *wqT0, *wqT1, *wkT0, *wkT1, *wvT0, *wvT1, *woT0, *woT1;
    __nv_bfloat16 *aqh, *aql, *akh, *akl, *avh, *avl;
    cudaGetSymbolAddress((void**)&xs0, g_xs0);
    cudaGetSymbolAddress((void**)&xs1, g_xs1);
    cudaGetSymbolAddress((void**)&wqT0, g_wqT0);
    cudaGetSymbolAddress((void**)&wqT1, g_wqT1);
    cudaGetSymbolAddress((void**)&wkT0, g_wkT0);
    cudaGetSymbolAddress((void**)&wkT1, g_wkT1);
    cudaGetSymbolAddress((void**)&wvT0, g_wvT0);
    cudaGetSymbolAddress((void**)&wvT1, g_wvT1);
    cudaGetSymbolAddress((void**)&woT0, g_woT0);
    cudaGetSymbolAddress((void**)&woT1, g_woT1);
    cudaGetSymbolAddress((void**)&aqh, g_aqh);
    cudaGetSymbolAddress((void**)&aql, g_aql);
    cudaGetSymbolAddress((void**)&akh, g_akh);
    cudaGetSymbolAddress((void**)&akl, g_akl);
    cudaGetSymbolAddress((void**)&avh, g_avh);
    cudaGetSymbolAddress((void**)&avl, g_avl);

    cudaFuncSetAttribute(gemm_mma, cudaFuncAttributeMaxDynamicSharedMemorySize, GSM_TOT);
    cudaFuncSetAttribute(attn_mma, cudaFuncAttributeMaxDynamicSharedMemorySize, A_TOT);

    // prep
    split_f32<<<(MROWS * D_ / 4) / 256, 256>>>(x, xs0, xs1);
    wsplitT<<<dim3(D_ / 32, D_ / 32), dim3(32, 8)>>>(wq, wqT0, wqT1, D_);
    wsplitT<<<dim3(512 / 32, D_ / 32), dim3(32, 8)>>>(wk, wkT0, wkT1, 512);
    wsplitT<<<dim3(512 / 32, D_ / 32), dim3(32, 8)>>>(wv, wvT0, wvT1, 512);
    wsplitT<<<dim3(D_ / 32, D_ / 32), dim3(32, 8)>>>(wo, woT0, woT1, D_);

    // fused q/k/v projections + dropout-mask generation (tensor + idle-ALU)
    gemm_mma<<<dim3(48, MROWS / 128), 256, GSM_TOT>>>(
        xs0, xs1, wqT0, wqT1, wkT0, wkT1, wvT0, wvT1, qp, kp, vp, maskp);

    rope_pack<<<(MROWS * HQ_ * 64) / 256, 256>>>(qp, kp, vp, kv, aqh, aql, akh, akl, avh, avl);

    // tensor-core attention (consumes precomputed mask bits)
    attn_mma<<<dim3(T_ / 128, B_ * HQ_), 256, A_TOT>>>(aqh, aql, akh, akl, avh, avl, maskp, ap);

    // out projection (no mask generation)
    split_f32<<<(MROWS * D_ / 4) / 256, 256>>>(ap, xs0, xs1);
    gemm_mma<<<dim3(32, MROWS / 128), 256, GSM_TOT>>>(
        xs0, xs1, woT0, woT1, woT0, woT1, woT0, woT1, out, out, out, (uint32_t*)nullptr);
}

// round 9
// speedup vs baseline: 1.2395x; 1.0353x over previous
#include <cuda_runtime.h>
#include <cuda_bf16.h>
#include <math.h>
#include <stdint.h>

#define B_   2
#define T_   2048
#define D_   2048
#define HQ_  16
#define HK_  4
#define HD_  128
#define MROWS (B_*T_)            // 4096
#define QELEMS (MROWS*HQ_*HD_)   // 8388608
#define KVELEMS (MROWS*HK_*HD_)  // 2097152
#define NTRIPLES 8704            // 32 bh * sum_{qb<16}(2qb+2)

// fp32 scratch
__device__ float g_q[QELEMS];
__device__ float g_kraw[KVELEMS];
__device__ float g_vraw[KVELEMS];
// dropout mask bits: [bh(32)][qb(16)][jb(32)][wid(8)][lane(32)] one uint32 each
__device__ uint32_t g_mask[32*16*32*8*32];   // 16 MB
// bf16 split scratch (GEMM)
__device__ __nv_bfloat16 g_xs0[MROWS*D_];
__device__ __nv_bfloat16 g_xs1[MROWS*D_];
__device__ __nv_bfloat16 g_wqT0[D_*D_], g_wqT1[D_*D_];
__device__ __nv_bfloat16 g_wkT0[512*D_], g_wkT1[512*D_];
__device__ __nv_bfloat16 g_wvT0[512*D_], g_wvT1[512*D_];
__device__ __nv_bfloat16 g_woT0[D_*D_], g_woT1[D_*D_];
// bf16 split scratch (attention), head-major [b][h][t][128]
__device__ __nv_bfloat16 g_aqh[QELEMS], g_aql[QELEMS];
__device__ __nv_bfloat16 g_akh[KVELEMS], g_akl[KVELEMS];
__device__ __nv_bfloat16 g_avh[KVELEMS], g_avl[KVELEMS];

// ============================ helpers =========================================
__device__ __forceinline__ uint32_t smem_u32(const void* p) {
    uint32_t a;
    asm("{ .reg .u64 t; cvta.to.shared.u64 t, %1; cvt.u32.u64 %0, t; }" : "=r"(a) : "l"(p));
    return a;
}
__device__ __forceinline__ void cpasync16(uint32_t s, const void* g) {
    asm volatile("cp.async.cg.shared.global [%0], [%1], 16;" :: "r"(s), "l"(g));
}
__device__ __forceinline__ void ldsm4(uint32_t& r0, uint32_t& r1, uint32_t& r2, uint32_t& r3,
                                      uint32_t addr) {
    asm volatile("ldmatrix.sync.aligned.m8n8.x4.shared.b16 {%0,%1,%2,%3}, [%4];"
                 : "=r"(r0), "=r"(r1), "=r"(r2), "=r"(r3) : "r"(addr));
}
__device__ __forceinline__ void ldsm4t(uint32_t& r0, uint32_t& r1, uint32_t& r2, uint32_t& r3,
                                       uint32_t addr) {
    asm volatile("ldmatrix.sync.aligned.m8n8.x4.trans.shared.b16 {%0,%1,%2,%3}, [%4];"
                 : "=r"(r0), "=r"(r1), "=r"(r2), "=r"(r3) : "r"(addr));
}
__device__ __forceinline__ void mma16816(float* c, const uint32_t* a, const uint32_t* b) {
    asm volatile("mma.sync.aligned.m16n8k16.row.col.f32.bf16.bf16.f32 "
                 "{%0,%1,%2,%3}, {%4,%5,%6,%7}, {%8,%9}, {%0,%1,%2,%3};"
                 : "+f"(c[0]), "+f"(c[1]), "+f"(c[2]), "+f"(c[3])
                 : "r"(a[0]), "r"(a[1]), "r"(a[2]), "r"(a[3]), "r"(b[0]), "r"(b[1]));
}
// GEMM tile swizzle: [rows][32 bf16] (64B rows, 16B chunks)
__device__ __forceinline__ uint32_t swadr(int row, int ch) {
    return (uint32_t)(row * 64 + ((ch ^ ((row >> 1) & 3)) << 4));
}
// attention tile swizzle: [rows][128 bf16] (256B rows, 16 chunks of 16B)
__device__ __forceinline__ uint32_t asw(int row, int ch) {
    return (uint32_t)(row * 256 + ((ch ^ (row & 7)) << 4));
}

// ============================ threefry (partitionable) =========================
__device__ __forceinline__ unsigned tf_rotl(unsigned x, int r) {
    return (x << r) | (x >> (32 - r));
}
__device__ __forceinline__ unsigned dropout_bit(unsigned e) {
    unsigned x0 = 0u, x1 = e;
    const unsigned k0 = 0u, k1 = 1u, k2 = 0x1BD11BDAu ^ k0 ^ k1;
    x0 += k0; x1 += k1;
#define TFR(r) { x0 += x1; x1 = tf_rotl(x1, r); x1 ^= x0; }
    TFR(13) TFR(15) TFR(26) TFR(6)
    x0 += k1; x1 += k2 + 1u;
    TFR(17) TFR(29) TFR(16) TFR(24)
    x0 += k2; x1 += k0 + 2u;
    TFR(13) TFR(15) TFR(26) TFR(6)
    x0 += k0; x1 += k1 + 3u;
    TFR(17) TFR(29) TFR(16) TFR(24)
    x0 += k1; x1 += k2 + 4u;
    TFR(13) TFR(15) TFR(26) TFR(6)
    x0 += k2; x1 += k0 + 5u;
#undef TFR
    unsigned bits = x0 ^ x1;
    float u = __uint_as_float((bits >> 9) | 0x3F800000u) - 1.0f;
    return (u < 0.9f) ? 1u : 0u;
}

// ============================ split / transpose preps ==========================
__global__ void split_f32(const float* __restrict__ in, __nv_bfloat16* __restrict__ o0,
                          __nv_bfloat16* __restrict__ o1) {
    int i = blockIdx.x * 256 + threadIdx.x;
    float4 v = ((const float4*)in)[i];
    __nv_bfloat16 h[4], l[4];
    float vv[4] = {v.x, v.y, v.z, v.w};
    #pragma unroll
    for (int j = 0; j < 4; j++) {
        h[j] = __float2bfloat16(vv[j]);
        l[j] = __float2bfloat16(vv[j] - __bfloat162float(h[j]));
    }
    ((ushort4*)o0)[i] = make_ushort4(*(unsigned short*)&h[0], *(unsigned short*)&h[1],
                                     *(unsigned short*)&h[2], *(unsigned short*)&h[3]);
    ((ushort4*)o1)[i] = make_ushort4(*(unsigned short*)&l[0], *(unsigned short*)&l[1],
                                     *(unsigned short*)&l[2], *(unsigned short*)&l[3]);
}

__global__ void wsplitT(const float* __restrict__ W, __nv_bfloat16* __restrict__ t0,
                        __nv_bfloat16* __restrict__ t1, int N) {
    __shared__ float tile[32][33];
    int n0 = blockIdx.x * 32, k0 = blockIdx.y * 32;
    int tx = threadIdx.x, ty = threadIdx.y;
    #pragma unroll
    for (int i = 0; i < 4; i++)
        tile[ty + i * 8][tx] = W[(long)(k0 + ty + i * 8) * N + n0 + tx];
    __syncthreads();
    #pragma unroll
    for (int i = 0; i < 4; i++) {
        float v = tile[tx][ty + i * 8];
        __nv_bfloat16 h = __float2bfloat16(v);
        __nv_bfloat16 l = __float2bfloat16(v - __bfloat162float(h));
        long o = (long)(n0 + ty + i * 8) * 2048 + k0 + tx;
        t0[o] = h; t1[o] = l;
    }
}

// ============================ mma.sync bf16x3 GEMM (fused qkv + mask gen) ======
#define STG_BYTES 24576
#define OFF_AH 0
#define OFF_AL 8192
#define OFF_BH 16384
#define OFF_BL 20480
#define GSM_TOT (3*STG_BYTES)   // 73728

__global__ void __launch_bounds__(256) gemm_mma(
    const __nv_bfloat16* __restrict__ A0, const __nv_bfloat16* __restrict__ A1,
    const __nv_bfloat16* __restrict__ Bq0, const __nv_bfloat16* __restrict__ Bq1,
    const __nv_bfloat16* __restrict__ Bk0, const __nv_bfloat16* __restrict__ Bk1,
    const __nv_bfloat16* __restrict__ Bv0, const __nv_bfloat16* __restrict__ Bv1,
    float* __restrict__ Cq, float* __restrict__ Ck, float* __restrict__ Cv,
    uint32_t* __restrict__ mask) {
    extern __shared__ char smem[];
    uint32_t sb = smem_u32(smem);
    int tid = threadIdx.x, lane = tid & 31, wid = tid >> 5;
    int wm = wid & 3, wn = wid >> 2;
    long m0 = (long)blockIdx.y * 128;

    const __nv_bfloat16 *B0, *B1;
    float* C;
    int N, n0;
    int nb = blockIdx.x;
    if (nb < 32)      { B0 = Bq0; B1 = Bq1; C = Cq; N = 2048; n0 = nb * 64; }
    else if (nb < 40) { B0 = Bk0; B1 = Bk1; C = Ck; N = 512;  n0 = (nb - 32) * 64; }
    else              { B0 = Bv0; B1 = Bv1; C = Cv; N = 512;  n0 = (nb - 40) * 64; }

    int lrow = lane & 7, ltile = lane >> 3;
    int a_row = wm * 32 + ((ltile & 1) << 3) + lrow;
    int a_ch  = ltile >> 1;
    int b_row = wn * 32 + ((ltile >> 1) << 3) + lrow;
    int b_ch  = ltile & 1;

    float acc[2][4][4];
    #pragma unroll
    for (int mf = 0; mf < 2; mf++)
        #pragma unroll
        for (int nf = 0; nf < 4; nf++)
            #pragma unroll
            for (int j = 0; j < 4; j++) acc[mf][nf][j] = 0.f;

    int ar0 = tid >> 2, ach = tid & 3;
    int br  = tid >> 2, bch = tid & 3;

    // ---- interleaved dropout-mask generation state ----
    int mstride = gridDim.x * gridDim.y;
    int mt = mask ? (blockIdx.y * gridDim.x + blockIdx.x) : NTRIPLES;
    int mh = 0;
    uint32_t mword = 0;
    unsigned mebase = 0;
    int mrowb = 0, mcolb = 0;
    long mwidx = 0;

    auto mask_step = [&]() {
        if (mt >= NTRIPLES) return;
        if (mh == 0) {
            int bh = mt / 272;
            int r = mt - bh * 272;
            int qb = 0;
            while (r >= 2 * qb + 2) { r -= 2 * qb + 2; qb++; }
            int jb = r;
            mebase = (unsigned)bh * 4194304u;
            mrowb = qb * 128 + wid * 16 + (lane >> 2);
            mcolb = jb * 64 + (lane & 3) * 2;
            mwidx = ((((long)bh * 16 + qb) * 32 + jb) * 8 + wid) * 32 + lane;
        }
        int nf = mh >> 2, rs = (mh >> 1) & 1, cs = mh & 1;
        unsigned e = mebase + (unsigned)(mrowb + rs * 8) * 2048u
                            + (unsigned)(mcolb + nf * 8 + cs);
        mword |= dropout_bit(e) << mh;
        mh++;
        if (mh == 32) { mask[mwidx] = mword; mword = 0; mh = 0; mt += mstride; }
    };

    auto issue = [&](int st, int kc) {
        uint32_t base = sb + st * STG_BYTES;
        #pragma unroll
        for (int p = 0; p < 2; p++) {
            int r = ar0 + p * 64;
            uint32_t sw = swadr(r, ach);
            long g = (m0 + r) * 2048 + kc + ach * 8;
            cpasync16(base + OFF_AH + sw, A0 + g);
            cpasync16(base + OFF_AL + sw, A1 + g);
        }
        {
            uint32_t sw = swadr(br, bch);
            long g = (long)(n0 + br) * 2048 + kc + bch * 8;
            cpasync16(base + OFF_BH + sw, B0 + g);
            cpasync16(base + OFF_BL + sw, B1 + g);
        }
        asm volatile("cp.async.commit_group;" ::: "memory");
    };

    const int KI = 2048 / 32;
    issue(0, 0);
    issue(1, 32);
    int stage = 0;
    for (int kci = 0; kci < KI; kci++) {
        if (kci + 1 < KI) {
            asm volatile("cp.async.wait_group 1;" ::: "memory");
        } else {
            asm volatile("cp.async.wait_group 0;" ::: "memory");
        }
        __syncthreads();
        if (kci + 2 < KI) issue((stage + 2) % 3, (kci + 2) * 32);

        uint32_t base = sb + stage * STG_BYTES;
        #pragma unroll
        for (int ks = 0; ks < 2; ks++) {
            uint32_t ah[2][4], al[2][4];
            #pragma unroll
            for (int mf = 0; mf < 2; mf++) {
                uint32_t adr = base + OFF_AH + swadr(a_row + mf * 16, ks * 2 + a_ch);
                ldsm4(ah[mf][0], ah[mf][1], ah[mf][2], ah[mf][3], adr);
                adr = base + OFF_AL + swadr(a_row + mf * 16, ks * 2 + a_ch);
                ldsm4(al[mf][0], al[mf][1], al[mf][2], al[mf][3], adr);
            }
            uint32_t bh[4][2], bl[4][2];
            #pragma unroll
            for (int nf2 = 0; nf2 < 2; nf2++) {
                uint32_t adr = base + OFF_BH + swadr(b_row + nf2 * 16, ks * 2 + b_ch);
                ldsm4(bh[nf2*2][0], bh[nf2*2][1], bh[nf2*2+1][0], bh[nf2*2+1][1], adr);
                adr = base + OFF_BL + swadr(b_row + nf2 * 16, ks * 2 + b_ch);
                ldsm4(bl[nf2*2][0], bl[nf2*2][1], bl[nf2*2+1][0], bl[nf2*2+1][1], adr);
            }
            #pragma unroll
            for (int mf = 0; mf < 2; mf++)
                #pragma unroll
                for (int nf = 0; nf < 4; nf++) {
                    mma16816(acc[mf][nf], ah[mf], bh[nf]);
                    mma16816(acc[mf][nf], ah[mf], bl[nf]);
                    mma16816(acc[mf][nf], al[mf], bh[nf]);
                }
        }
        mask_step();
        mask_step();
        mask_step();
        stage = (stage + 1) % 3;
    }
    while (mt < NTRIPLES) mask_step();

    int cr = lane >> 2, cc = (lane & 3) << 1;
    #pragma unroll
    for (int mf = 0; mf < 2; mf++)
        #pragma unroll
        for (int nf = 0; nf < 4; nf++) {
            long row = m0 + wm * 32 + mf * 16 + cr;
            int col = n0 + wn * 32 + nf * 8 + cc;
            *(float2*)(C + row * N + col)       = make_float2(acc[mf][nf][0], acc[mf][nf][1]);
            *(float2*)(C + (row + 8) * N + col) = make_float2(acc[mf][nf][2], acc[mf][nf][3]);
        }
}

// ============================ RoPE + pack + bf16 splits ========================
__global__ void rope_pack(const float* __restrict__ q, const float* __restrict__ kraw,
                          const float* __restrict__ vraw, float* __restrict__ kv,
                          __nv_bfloat16* __restrict__ qh, __nv_bfloat16* __restrict__ ql,
                          __nv_bfloat16* __restrict__ kh, __nv_bfloat16* __restrict__ kl,
                          __nv_bfloat16* __restrict__ vh, __nv_bfloat16* __restrict__ vl) {
    int idx = blockIdx.x * 256 + threadIdx.x;
    {
        int row = idx >> 10;          // b*T + t
        int rem = idx & 1023;
        int h = rem >> 6, m = rem & 63;
        int b = row >> 11, t = row & 2047;
        float invf = powf(10000.0f, -(float)(2 * m) * (1.0f / 128.0f));
        float ang = (float)t * invf;
        float c = cosf(ang), s = sinf(ang);
        const float scale = 0.08838834764831845f;
        long base = (long)row * (HQ_ * HD_) + h * HD_ + m;
        float x1 = q[base], x2 = q[base + 64];
        float v1 = (x1 * c - x2 * s) * scale;
        float v2 = (x2 * c + x1 * s) * scale;
        long so = ((long)(b * HQ_ + h) * T_ + t) * 128 + m;
        __nv_bfloat16 h1 = __float2bfloat16(v1), h2 = __float2bfloat16(v2);
        qh[so] = h1;      qh[so + 64] = h2;
        ql[so] = __float2bfloat16(v1 - __bfloat162float(h1));
        ql[so + 64] = __float2bfloat16(v2 - __bfloat162float(h2));
    }
    if (idx < MROWS * HK_ * 64) {
        int krow = idx >> 8;
        int krem = idx & 255;
        int khd = krem >> 6, km = krem & 63;
        int b = krow >> 11, t = krow & 2047;
        float invf = powf(10000.0f, -(float)(2 * km) * (1.0f / 128.0f));
        float ang = (float)t * invf;
        float c = cosf(ang), s = sinf(ang);
        long src = (long)krow * (HK_ * HD_) + khd * HD_ + km;
        float x1 = kraw[src], x2 = kraw[src + 64];
        float v1 = x1 * c - x2 * s;
        float v2 = x2 * c + x1 * s;
        long dst = ((long)krow * HK_ + khd) * 256 + km;
        kv[dst]      = v1;
        kv[dst + 64] = v2;
        long so = ((long)(b * HK_ + khd) * T_ + t) * 128 + km;
        __nv_bfloat16 h1 = __float2bfloat16(v1), h2 = __float2bfloat16(v2);
        kh[so] = h1;      kh[so + 64] = h2;
        kl[so] = __float2bfloat16(v1 - __bfloat162float(h1));
        kl[so + 64] = __float2bfloat16(v2 - __bfloat162float(h2));
    }
    if (idx < KVELEMS / 4) {
        int f = idx;
        int vrow = f >> 7;
        int vc4 = f & 127;
        int vhd = vc4 >> 5, vd4 = (vc4 & 31) << 2;
        int b = vrow >> 11, t = vrow & 2047;
        float4 v = *(const float4*)(vraw + (long)f * 4);
        long dst = ((long)vrow * HK_ + vhd) * 256 + 128 + vd4;
        *(float4*)(kv + dst) = v;
        long so = ((long)(b * HK_ + vhd) * T_ + t) * 128 + vd4;
        float vv[4] = {v.x, v.y, v.z, v.w};
        #pragma unroll
        for (int j = 0; j < 4; j++) {
            __nv_bfloat16 hj = __float2bfloat16(vv[j]);
            vh[so + j] = hj;
            vl[so + j] = __float2bfloat16(vv[j] - __bfloat162float(hj));
        }
    }
}

// ============================ tensor-core attention ============================
// smem: Q hi/lo (2x32KB) + 2-stage KV (2x64KB) = 192 KB; double-buffered pipeline.
#define A_QH 0
#define A_QL (A_QH + 128*256)
#define A_KV0 (A_QL + 128*256)          // stage base; KH/KL/VH/VL at +0/16K/32K/48K
#define A_KVSTG 65536
#define A_TOT (A_KV0 + 2*A_KVSTG)       // 196608 bytes

__global__ void __launch_bounds__(256) attn_mma(
    const __nv_bfloat16* __restrict__ Qh, const __nv_bfloat16* __restrict__ Ql,
    const __nv_bfloat16* __restrict__ Kh, const __nv_bfloat16* __restrict__ Kl,
    const __nv_bfloat16* __restrict__ Vh, const __nv_bfloat16* __restrict__ Vl,
    const uint32_t* __restrict__ Mask,
    __nv_bfloat16* __restrict__ Oh, __nv_bfloat16* __restrict__ Ol) {
    extern __shared__ char smem[];
    uint32_t sb = smem_u32(smem);
    int tid = threadIdx.x, lane = tid & 31, wid = tid >> 5;
    int qb = (gridDim.x - 1) - blockIdx.x;
    int bh = blockIdx.y;
    int b = bh >> 4, hq = bh & 15, hk = hq & 3;

    const __nv_bfloat16* qhp = Qh + ((long)(b * HQ_ + hq) * T_ + qb * 128) * 128;
    const __nv_bfloat16* qlp = Ql + ((long)(b * HQ_ + hq) * T_ + qb * 128) * 128;
    const __nv_bfloat16* khp = Kh + (long)(b * HK_ + hk) * T_ * 128;
    const __nv_bfloat16* klp = Kl + (long)(b * HK_ + hk) * T_ * 128;
    const __nv_bfloat16* vhp = Vh + (long)(b * HK_ + hk) * T_ * 128;
    const __nv_bfloat16* vlp = Vl + (long)(b * HK_ + hk) * T_ * 128;

    // Q tiles (folded into first commit group)
    #pragma unroll
    for (int it = 0; it < 16; it++) {
        int lin = tid + it * 256;
        int arr = lin >> 11, cidx = lin & 2047;
        int row = cidx >> 4, ch = cidx & 15;
        const __nv_bfloat16* src = (arr ? qlp : qhp) + row * 128 + ch * 8;
        cpasync16(sb + (arr ? A_QL : A_QH) + asw(row, ch), src);
    }

    auto kv_issue = [&](int st, int jb) {
        uint32_t base = sb + A_KV0 + st * A_KVSTG;
        #pragma unroll
        for (int it = 0; it < 16; it++) {
            int lin = tid + it * 256;
            int arr = lin >> 10, cidx = lin & 1023;
            int row = cidx >> 4, ch = cidx & 15;
            long g = (long)(jb * 64 + row) * 128 + ch * 8;
            const __nv_bfloat16* src = (arr == 0 ? khp : arr == 1 ? klp : arr == 2 ? vhp : vlp) + g;
            cpasync16(base + arr * 16384 + asw(row, ch), src);
        }
        asm volatile("cp.async.commit_group;" ::: "memory");
    };

    int qrw = wid * 16;
    float m1 = -INFINITY, m2 = -INFINITY, l1 = 0.f, l2 = 0.f;
    float o[16][4];
    #pragma unroll
    for (int nf = 0; nf < 16; nf++)
        #pragma unroll
        for (int c = 0; c < 4; c++) o[nf][c] = 0.f;

    int ig1 = qb * 128 + qrw + (lane >> 2);
    long wbase0 = ((long)bh * 16 + qb) * 8192 + wid * 32 + lane;

    int a_row = qrw + ((lane >> 3) & 1) * 8 + (lane & 7);
    int a_chb = lane >> 4;
    int k_row8 = ((lane >> 4)) * 8 + (lane & 7);
    int k_chb = (lane >> 3) & 1;
    int v_row8 = ((lane >> 3) & 1) * 8 + (lane & 7);
    int v_chb = lane >> 4;

    int njb = 2 * qb + 2;
    kv_issue(0, 0);   // includes Q loads in this group
    for (int jb = 0; jb < njb; jb++) {
        // prefetch next KV into the other buffer (overlaps with compute below)
        if (jb + 1 < njb) {
            kv_issue((jb + 1) & 1, jb + 1);
            asm volatile("cp.async.wait_group 1;" ::: "memory");
        } else {
            asm volatile("cp.async.wait_group 0;" ::: "memory");
        }
        uint32_t mw = Mask[wbase0 + (long)jb * 256];
        __syncthreads();
        uint32_t kvb = sb + A_KV0 + (jb & 1) * A_KVSTG;

        float sc[8][4];
        #pragma unroll
        for (int nf = 0; nf < 8; nf++)
            #pragma unroll
            for (int c = 0; c < 4; c++) sc[nf][c] = 0.f;
        #pragma unroll
        for (int ks = 0; ks < 8; ks++) {
            uint32_t qh4[4], ql4[4];
            ldsm4(qh4[0], qh4[1], qh4[2], qh4[3], sb + A_QH + asw(a_row, 2 * ks + a_chb));
            ldsm4(ql4[0], ql4[1], ql4[2], ql4[3], sb + A_QL + asw(a_row, 2 * ks + a_chb));
            #pragma unroll
            for (int nfp = 0; nfp < 4; nfp++) {
                uint32_t kh4[4], kl4[4];
                int br = nfp * 16 + k_row8;
                int bc = 2 * ks + k_chb;
                ldsm4(kh4[0], kh4[1], kh4[2], kh4[3], kvb + asw(br, bc));
                ldsm4(kl4[0], kl4[1], kl4[2], kl4[3], kvb + 16384 + asw(br, bc));
                mma16816(sc[2 * nfp],     qh4, kh4);
                mma16816(sc[2 * nfp],     qh4, kl4);
                mma16816(sc[2 * nfp],     ql4, kh4);
                mma16816(sc[2 * nfp + 1], qh4, kh4 + 2);
                mma16816(sc[2 * nfp + 1], qh4, kl4 + 2);
                mma16816(sc[2 * nfp + 1], ql4, kh4 + 2);
            }
        }

        if (jb * 64 + 63 > qb * 128 + qrw) {
            #pragma unroll
            for (int nf = 0; nf < 8; nf++) {
                int j0 = jb * 64 + nf * 8 + (lane & 3) * 2;
                if (j0 > ig1)     sc[nf][0] = -INFINITY;
                if (j0 + 1 > ig1) sc[nf][1] = -INFINITY;
                if (j0 > ig1 + 8)     sc[nf][2] = -INFINITY;
                if (j0 + 1 > ig1 + 8) sc[nf][3] = -INFINITY;
            }
        }

        float mx1 = -INFINITY, mx2 = -INFINITY;
        #pragma unroll
        for (int nf = 0; nf < 8; nf++) {
            mx1 = fmaxf(mx1, fmaxf(sc[nf][0], sc[nf][1]));
            mx2 = fmaxf(mx2, fmaxf(sc[nf][2], sc[nf][3]));
        }
        mx1 = fmaxf(mx1, __shfl_xor_sync(0xffffffffu, mx1, 1));
        mx1 = fmaxf(mx1, __shfl_xor_sync(0xffffffffu, mx1, 2));
        mx2 = fmaxf(mx2, __shfl_xor_sync(0xffffffffu, mx2, 1));
        mx2 = fmaxf(mx2, __shfl_xor_sync(0xffffffffu, mx2, 2));
        float mn1 = fmaxf(m1, mx1), mn2 = fmaxf(m2, mx2);
        float cr1 = __expf(m1 - mn1), cr2 = __expf(m2 - mn2);
        float rs1 = 0.f, rs2 = 0.f;
        #pragma unroll
        for (int nf = 0; nf < 8; nf++) {
            sc[nf][0] = __expf(sc[nf][0] - mn1); rs1 += sc[nf][0];
            sc[nf][1] = __expf(sc[nf][1] - mn1); rs1 += sc[nf][1];
            sc[nf][2] = __expf(sc[nf][2] - mn2); rs2 += sc[nf][2];
            sc[nf][3] = __expf(sc[nf][3] - mn2); rs2 += sc[nf][3];
        }
        rs1 += __shfl_xor_sync(0xffffffffu, rs1, 1);
        rs1 += __shfl_xor_sync(0xffffffffu, rs1, 2);
        rs2 += __shfl_xor_sync(0xffffffffu, rs2, 1);
        rs2 += __shfl_xor_sync(0xffffffffu, rs2, 2);
        l1 = l1 * cr1 + rs1;  l2 = l2 * cr2 + rs2;   // denom WITHOUT dropout (matches ref)
        m1 = mn1;  m2 = mn2;
        #pragma unroll
        for (int nf = 0; nf < 16; nf++) {
            o[nf][0] *= cr1; o[nf][1] *= cr1;
            o[nf][2] *= cr2; o[nf][3] *= cr2;
        }

        #pragma unroll
        for (int nf = 0; nf < 8; nf++) {
            sc[nf][0] *= ((mw >> (nf * 4 + 0)) & 1u) ? (1.0f / 0.9f) : 0.f;
            sc[nf][1] *= ((mw >> (nf * 4 + 1)) & 1u) ? (1.0f / 0.9f) : 0.f;
            sc[nf][2] *= ((mw >> (nf * 4 + 2)) & 1u) ? (1.0f / 0.9f) : 0.f;
            sc[nf][3] *= ((mw >> (nf * 4 + 3)) & 1u) ? (1.0f / 0.9f) : 0.f;
        }

        #pragma unroll
        for (int ksj = 0; ksj < 4; ksj++) {
            uint32_t ahi[4], alo[4];
            #pragma unroll
            for (int half = 0; half < 2; half++) {
                int nf = 2 * ksj + half;
                __nv_bfloat16 h0 = __float2bfloat16(sc[nf][0]);
                __nv_bfloat16 h1 = __float2bfloat16(sc[nf][1]);
                __nv_bfloat16 h2 = __float2bfloat16(sc[nf][2]);
                __nv_bfloat16 h3 = __float2bfloat16(sc[nf][3]);
                __nv_bfloat162 hh01 = __halves2bfloat162(h0, h1);
                __nv_bfloat162 hh23 = __halves2bfloat162(h2, h3);
                ahi[2 * half]     = *reinterpret_cast<uint32_t*>(&hh01);
                ahi[2 * half + 1] = *reinterpret_cast<uint32_t*>(&hh23);
                __nv_bfloat162 ll01 = __halves2bfloat162(
                    __float2bfloat16(sc[nf][0] - __bfloat162float(h0)),
                    __float2bfloat16(sc[nf][1] - __bfloat162float(h1)));
                __nv_bfloat162 ll23 = __halves2bfloat162(
                    __float2bfloat16(sc[nf][2] - __bfloat162float(h2)),
                    __float2bfloat16(sc[nf][3] - __bfloat162float(h3)));
                alo[2 * half]     = *reinterpret_cast<uint32_t*>(&ll01);
                alo[2 * half + 1] = *reinterpret_cast<uint32_t*>(&ll23);
            }
            #pragma unroll
            for (int nfp = 0; nfp < 8; nfp++) {
                uint32_t vh4[4], vl4[4];
                int vr = ksj * 16 + v_row8;
                int vc = 2 * nfp + v_chb;
                ldsm4t(vh4[0], vh4[1], vh4[2], vh4[3], kvb + 32768 + asw(vr, vc));
                ldsm4t(vl4[0], vl4[1], vl4[2], vl4[3], kvb + 49152 + asw(vr, vc));
                mma16816(o[2 * nfp],     ahi, vh4);
                mma16816(o[2 * nfp],     ahi, vl4);
                mma16816(o[2 * nfp],     alo, vh4);
                mma16816(o[2 * nfp + 1], ahi, vh4 + 2);
                mma16816(o[2 * nfp + 1], ahi, vl4 + 2);
                mma16816(o[2 * nfp + 1], alo, vh4 + 2);
            }
        }
        __syncthreads();
    }

    // fused epilogue: normalize and write bf16 hi/lo splits (wo GEMM's A operand)
    float inv1 = 1.f / l1, inv2 = 1.f / l2;
    long r1g = (long)(b * T_ + qb * 128 + qrw + (lane >> 2));
    #pragma unroll
    for (int nf = 0; nf < 16; nf++) {
        int col = hq * 128 + nf * 8 + (lane & 3) * 2;
        float v0 = o[nf][0] * inv1, v1 = o[nf][1] * inv1;
        float v2 = o[nf][2] * inv2, v3 = o[nf][3] * inv2;
        __nv_bfloat16 h0 = __float2bfloat16(v0), h1 = __float2bfloat16(v1);
        __nv_bfloat16 h2 = __float2bfloat16(v2), h3 = __float2bfloat16(v3);
        __nv_bfloat162 hp1 = __halves2bfloat162(h0, h1);
        __nv_bfloat162 hp2 = __halves2bfloat162(h2, h3);
        __nv_bfloat162 lp1 = __halves2bfloat162(
            __float2bfloat16(v0 - __bfloat162float(h0)),
            __float2bfloat16(v1 - __bfloat162float(h1)));
        __nv_bfloat162 lp2 = __halves2bfloat162(
            __float2bfloat16(v2 - __bfloat162float(h2)),
            __float2bfloat16(v3 - __bfloat162float(h3)));
        *(uint32_t*)(Oh + r1g * 2048 + col)       = *reinterpret_cast<uint32_t*>(&hp1);
        *(uint32_t*)(Ol + r1g * 2048 + col)       = *reinterpret_cast<uint32_t*>(&lp1);
        *(uint32_t*)(Oh + (r1g + 8) * 2048 + col) = *reinterpret_cast<uint32_t*>(&hp2);
        *(uint32_t*)(Ol + (r1g + 8) * 2048 + col) = *reinterpret_cast<uint32_t*>(&lp2);
    }
}

// ============================ launch ===========================================
extern "C" void kernel_launch(void* const* d_in, const int* in_sizes, int n_in,
                              void* d_out, int out_size) {
    const float* x  = (const float*)d_in[0];
    const float* wq = (const float*)d_in[1];
    const float* wk = (const float*)d_in[2];
    const float* wv = (const float*)d_in[3];
    const float* wo = (const float*)d_in[4];
    float* out = (float*)d_out;
    float* kv  = out + QELEMS;

    float *qp, *kp, *vp;
    cudaGetSymbolAddress((void**)&qp, g_q);
    cudaGetSymbolAddress((void**)&kp, g_kraw);
    cudaGetSymbolAddress((void**)&vp, g_vraw);
    uint32_t* maskp;
    cudaGetSymbolAddress((void**)&maskp, g_mask);
    __nv_bfloat16 *xs0, *xs1, *wqT0, *wqT1, *wkT0, *wkT1, *wvT0, *wvT1, *woT0, *woT1;
    __nv_bfloat16 *aqh, *aql, *akh, *akl, *avh, *avl;
    cudaGetSymbolAddress((void**)&xs0, g_xs0);
    cudaGetSymbolAddress((void**)&xs1, g_xs1);
    cudaGetSymbolAddress((void**)&wqT0, g_wqT0);
    cudaGetSymbolAddress((void**)&wqT1, g_wqT1);
    cudaGetSymbolAddress((void**)&wkT0, g_wkT0);
    cudaGetSymbolAddress((void**)&wkT1, g_wkT1);
    cudaGetSymbolAddress((void**)&wvT0, g_wvT0);
    cudaGetSymbolAddress((void**)&wvT1, g_wvT1);
    cudaGetSymbolAddress((void**)&woT0, g_woT0);
    cudaGetSymbolAddress((void**)&woT1, g_woT1);
    cudaGetSymbolAddress((void**)&aqh, g_aqh);
    cudaGetSymbolAddress((void**)&aql, g_aql);
    cudaGetSymbolAddress((void**)&akh, g_akh);
    cudaGetSymbolAddress((void**)&akl, g_akl);
    cudaGetSymbolAddress((void**)&avh, g_avh);
    cudaGetSymbolAddress((void**)&avl, g_avl);

    cudaFuncSetAttribute(gemm_mma, cudaFuncAttributeMaxDynamicSharedMemorySize, GSM_TOT);
    cudaFuncSetAttribute(attn_mma, cudaFuncAttributeMaxDynamicSharedMemorySize, A_TOT);

    // prep
    split_f32<<<(MROWS * D_ / 4) / 256, 256>>>(x, xs0, xs1);
    wsplitT<<<dim3(D_ / 32, D_ / 32), dim3(32, 8)>>>(wq, wqT0, wqT1, D_);
    wsplitT<<<dim3(512 / 32, D_ / 32), dim3(32, 8)>>>(wk, wkT0, wkT1, 512);
    wsplitT<<<dim3(512 / 32, D_ / 32), dim3(32, 8)>>>(wv, wvT0, wvT1, 512);
    wsplitT<<<dim3(D_ / 32, D_ / 32), dim3(32, 8)>>>(wo, woT0, woT1, D_);

    // fused q/k/v projections + dropout-mask generation (tensor + idle-ALU)
    gemm_mma<<<dim3(48, MROWS / 128), 256, GSM_TOT>>>(
        xs0, xs1, wqT0, wqT1, wkT0, wkT1, wvT0, wvT1, qp, kp, vp, maskp);

    rope_pack<<<(MROWS * HQ_ * 64) / 256, 256>>>(qp, kp, vp, kv, aqh, aql, akh, akl, avh, avl);

    // tensor-core attention: double-buffered KV, writes bf16 splits directly
    attn_mma<<<dim3(T_ / 128, B_ * HQ_), 256, A_TOT>>>(
        aqh, aql, akh, akl, avh, avl, maskp, xs0, xs1);

    // out projection (no mask generation)
    gemm_mma<<<dim3(32, MROWS / 128), 256, GSM_TOT>>>(
        xs0, xs1, woT0, woT1, woT0, woT1, woT0, woT1, out, out, out, (uint32_t*)nullptr);
}

// round 11
// speedup vs baseline: 1.3851x; 1.1174x over previous
#include <cuda_runtime.h>
#include <cuda_bf16.h>
#include <cuda_fp16.h>
#include <math.h>
#include <stdint.h>

#define B_   2
#define T_   2048
#define D_   2048
#define HQ_  16
#define HK_  4
#define HD_  128
#define MROWS (B_*T_)            // 4096
#define QELEMS (MROWS*HQ_*HD_)   // 8388608
#define KVELEMS (MROWS*HK_*HD_)  // 2097152
#define NTRIPLES 8704            // 32 bh * sum_{qb<16}(2qb+2)

// fp32 scratch
__device__ float g_q[QELEMS];
__device__ float g_kraw[KVELEMS];
__device__ float g_vraw[KVELEMS];
// dropout mask bits
__device__ uint32_t g_mask[32*16*32*8*32];   // 16 MB
// bf16 split scratch (qkv GEMM)
__device__ __nv_bfloat16 g_xs0[MROWS*D_];
__device__ __nv_bfloat16 g_xs1[MROWS*D_];
__device__ __nv_bfloat16 g_wqT0[D_*D_], g_wqT1[D_*D_];
__device__ __nv_bfloat16 g_wkT0[512*D_], g_wkT1[512*D_];
__device__ __nv_bfloat16 g_wvT0[512*D_], g_wvT1[512*D_];
// fp16 for wo path
__device__ __half g_woh0[D_*D_], g_woh1[D_*D_];
__device__ __half g_ao[MROWS*D_];            // attention output (fp16)
// attention operands, head-major [b][h][t][128]
__device__ __nv_bfloat16 g_aqh[QELEMS], g_aql[QELEMS];
__device__ __nv_bfloat16 g_akh[KVELEMS], g_akl[KVELEMS];
__device__ __half g_avh[KVELEMS], g_avl[KVELEMS];

// ============================ helpers =========================================
__device__ __forceinline__ uint32_t smem_u32(const void* p) {
    uint32_t a;
    asm("{ .reg .u64 t; cvta.to.shared.u64 t, %1; cvt.u32.u64 %0, t; }" : "=r"(a) : "l"(p));
    return a;
}
__device__ __forceinline__ void cpasync16(uint32_t s, const void* g) {
    asm volatile("cp.async.cg.shared.global [%0], [%1], 16;" :: "r"(s), "l"(g));
}
__device__ __forceinline__ void ldsm4(uint32_t& r0, uint32_t& r1, uint32_t& r2, uint32_t& r3,
                                      uint32_t addr) {
    asm volatile("ldmatrix.sync.aligned.m8n8.x4.shared.b16 {%0,%1,%2,%3}, [%4];"
                 : "=r"(r0), "=r"(r1), "=r"(r2), "=r"(r3) : "r"(addr));
}
__device__ __forceinline__ void ldsm4t(uint32_t& r0, uint32_t& r1, uint32_t& r2, uint32_t& r3,
                                       uint32_t addr) {
    asm volatile("ldmatrix.sync.aligned.m8n8.x4.trans.shared.b16 {%0,%1,%2,%3}, [%4];"
                 : "=r"(r0), "=r"(r1), "=r"(r2), "=r"(r3) : "r"(addr));
}
__device__ __forceinline__ void mma16816(float* c, const uint32_t* a, const uint32_t* b) {
    asm volatile("mma.sync.aligned.m16n8k16.row.col.f32.bf16.bf16.f32 "
                 "{%0,%1,%2,%3}, {%4,%5,%6,%7}, {%8,%9}, {%0,%1,%2,%3};"
                 : "+f"(c[0]), "+f"(c[1]), "+f"(c[2]), "+f"(c[3])
                 : "r"(a[0]), "r"(a[1]), "r"(a[2]), "r"(a[3]), "r"(b[0]), "r"(b[1]));
}
__device__ __forceinline__ void mma16816h(float* c, const uint32_t* a, const uint32_t* b) {
    asm volatile("mma.sync.aligned.m16n8k16.row.col.f32.f16.f16.f32 "
                 "{%0,%1,%2,%3}, {%4,%5,%6,%7}, {%8,%9}, {%0,%1,%2,%3};"
                 : "+f"(c[0]), "+f"(c[1]), "+f"(c[2]), "+f"(c[3])
                 : "r"(a[0]), "r"(a[1]), "r"(a[2]), "r"(a[3]), "r"(b[0]), "r"(b[1]));
}
// GEMM tile swizzle: [rows][32 elems of 2B] (64B rows, 16B chunks)
__device__ __forceinline__ uint32_t swadr(int row, int ch) {
    return (uint32_t)(row * 64 + ((ch ^ ((row >> 1) & 3)) << 4));
}
// attention tile swizzle: [rows][128 elems] (256B rows, 16 chunks of 16B)
__device__ __forceinline__ uint32_t asw(int row, int ch) {
    return (uint32_t)(row * 256 + ((ch ^ (row & 7)) << 4));
}

// ============================ threefry (partitionable) =========================
__device__ __forceinline__ unsigned tf_rotl(unsigned x, int r) {
    return (x << r) | (x >> (32 - r));
}
__device__ __forceinline__ unsigned dropout_bit(unsigned e) {
    unsigned x0 = 0u, x1 = e;
    const unsigned k0 = 0u, k1 = 1u, k2 = 0x1BD11BDAu ^ k0 ^ k1;
    x0 += k0; x1 += k1;
#define TFR(r) { x0 += x1; x1 = tf_rotl(x1, r); x1 ^= x0; }
    TFR(13) TFR(15) TFR(26) TFR(6)
    x0 += k1; x1 += k2 + 1u;
    TFR(17) TFR(29) TFR(16) TFR(24)
    x0 += k2; x1 += k0 + 2u;
    TFR(13) TFR(15) TFR(26) TFR(6)
    x0 += k0; x1 += k1 + 3u;
    TFR(17) TFR(29) TFR(16) TFR(24)
    x0 += k1; x1 += k2 + 4u;
    TFR(13) TFR(15) TFR(26) TFR(6)
    x0 += k2; x1 += k0 + 5u;
#undef TFR
    unsigned bits = x0 ^ x1;
    float u = __uint_as_float((bits >> 9) | 0x3F800000u) - 1.0f;
    return (u < 0.9f) ? 1u : 0u;
}

// ============================ split / transpose preps ==========================
__global__ void split_f32(const float* __restrict__ in, __nv_bfloat16* __restrict__ o0,
                          __nv_bfloat16* __restrict__ o1) {
    int i = blockIdx.x * 256 + threadIdx.x;
    float4 v = ((const float4*)in)[i];
    __nv_bfloat16 h[4], l[4];
    float vv[4] = {v.x, v.y, v.z, v.w};
    #pragma unroll
    for (int j = 0; j < 4; j++) {
        h[j] = __float2bfloat16(vv[j]);
        l[j] = __float2bfloat16(vv[j] - __bfloat162float(h[j]));
    }
    ((ushort4*)o0)[i] = make_ushort4(*(unsigned short*)&h[0], *(unsigned short*)&h[1],
                                     *(unsigned short*)&h[2], *(unsigned short*)&h[3]);
    ((ushort4*)o1)[i] = make_ushort4(*(unsigned short*)&l[0], *(unsigned short*)&l[1],
                                     *(unsigned short*)&l[2], *(unsigned short*)&l[3]);
}

__global__ void wsplitT(const float* __restrict__ W, __nv_bfloat16* __restrict__ t0,
                        __nv_bfloat16* __restrict__ t1, int N) {
    __shared__ float tile[32][33];
    int n0 = blockIdx.x * 32, k0 = blockIdx.y * 32;
    int tx = threadIdx.x, ty = threadIdx.y;
    #pragma unroll
    for (int i = 0; i < 4; i++)
        tile[ty + i * 8][tx] = W[(long)(k0 + ty + i * 8) * N + n0 + tx];
    __syncthreads();
    #pragma unroll
    for (int i = 0; i < 4; i++) {
        float v = tile[tx][ty + i * 8];
        __nv_bfloat16 h = __float2bfloat16(v);
        __nv_bfloat16 l = __float2bfloat16(v - __bfloat162float(h));
        long o = (long)(n0 + ty + i * 8) * 2048 + k0 + tx;
        t0[o] = h; t1[o] = l;
    }
}

// fp16 variant for wo
__global__ void wsplitT_h(const float* __restrict__ W, __half* __restrict__ t0,
                          __half* __restrict__ t1, int N) {
    __shared__ float tile[32][33];
    int n0 = blockIdx.x * 32, k0 = blockIdx.y * 32;
    int tx = threadIdx.x, ty = threadIdx.y;
    #pragma unroll
    for (int i = 0; i < 4; i++)
        tile[ty + i * 8][tx] = W[(long)(k0 + ty + i * 8) * N + n0 + tx];
    __syncthreads();
    #pragma unroll
    for (int i = 0; i < 4; i++) {
        float v = tile[tx][ty + i * 8];
        __half h = __float2half_rn(v);
        __half l = __float2half_rn(v - __half2float(h));
        long o = (long)(n0 + ty + i * 8) * 2048 + k0 + tx;
        t0[o] = h; t1[o] = l;
    }
}

// ============================ mma.sync bf16x3 GEMM (fused qkv + mask gen) ======
#define STG_BYTES 24576
#define OFF_AH 0
#define OFF_AL 8192
#define OFF_BH 16384
#define OFF_BL 20480
#define GSM_TOT (3*STG_BYTES)   // 73728

__global__ void __launch_bounds__(256) gemm_mma(
    const __nv_bfloat16* __restrict__ A0, const __nv_bfloat16* __restrict__ A1,
    const __nv_bfloat16* __restrict__ Bq0, const __nv_bfloat16* __restrict__ Bq1,
    const __nv_bfloat16* __restrict__ Bk0, const __nv_bfloat16* __restrict__ Bk1,
    const __nv_bfloat16* __restrict__ Bv0, const __nv_bfloat16* __restrict__ Bv1,
    float* __restrict__ Cq, float* __restrict__ Ck, float* __restrict__ Cv,
    uint32_t* __restrict__ mask) {
    extern __shared__ char smem[];
    uint32_t sb = smem_u32(smem);
    int tid = threadIdx.x, lane = tid & 31, wid = tid >> 5;
    int wm = wid & 3, wn = wid >> 2;
    long m0 = (long)blockIdx.y * 128;

    const __nv_bfloat16 *B0, *B1;
    float* C;
    int N, n0;
    int nb = blockIdx.x;
    if (nb < 32)      { B0 = Bq0; B1 = Bq1; C = Cq; N = 2048; n0 = nb * 64; }
    else if (nb < 40) { B0 = Bk0; B1 = Bk1; C = Ck; N = 512;  n0 = (nb - 32) * 64; }
    else              { B0 = Bv0; B1 = Bv1; C = Cv; N = 512;  n0 = (nb - 40) * 64; }

    int lrow = lane & 7, ltile = lane >> 3;
    int a_row = wm * 32 + ((ltile & 1) << 3) + lrow;
    int a_ch  = ltile >> 1;
    int b_row = wn * 32 + ((ltile >> 1) << 3) + lrow;
    int b_ch  = ltile & 1;

    float acc[2][4][4];
    #pragma unroll
    for (int mf = 0; mf < 2; mf++)
        #pragma unroll
        for (int nf = 0; nf < 4; nf++)
            #pragma unroll
            for (int j = 0; j < 4; j++) acc[mf][nf][j] = 0.f;

    int ar0 = tid >> 2, ach = tid & 3;
    int br  = tid >> 2, bch = tid & 3;

    int mstride = gridDim.x * gridDim.y;
    int mt = mask ? (blockIdx.y * gridDim.x + blockIdx.x) : NTRIPLES;
    int mh = 0;
    uint32_t mword = 0;
    unsigned mebase = 0;
    int mrowb = 0, mcolb = 0;
    long mwidx = 0;

    auto mask_step = [&]() {
        if (mt >= NTRIPLES) return;
        if (mh == 0) {
            int bh = mt / 272;
            int r = mt - bh * 272;
            int qb = 0;
            while (r >= 2 * qb + 2) { r -= 2 * qb + 2; qb++; }
            int jb = r;
            mebase = (unsigned)bh * 4194304u;
            mrowb = qb * 128 + wid * 16 + (lane >> 2);
            mcolb = jb * 64 + (lane & 3) * 2;
            mwidx = ((((long)bh * 16 + qb) * 32 + jb) * 8 + wid) * 32 + lane;
        }
        int nf = mh >> 2, rs = (mh >> 1) & 1, cs = mh & 1;
        unsigned e = mebase + (unsigned)(mrowb + rs * 8) * 2048u
                            + (unsigned)(mcolb + nf * 8 + cs);
        mword |= dropout_bit(e) << mh;
        mh++;
        if (mh == 32) { mask[mwidx] = mword; mword = 0; mh = 0; mt += mstride; }
    };

    auto issue = [&](int st, int kc) {
        uint32_t base = sb + st * STG_BYTES;
        #pragma unroll
        for (int p = 0; p < 2; p++) {
            int r = ar0 + p * 64;
            uint32_t sw = swadr(r, ach);
            long g = (m0 + r) * 2048 + kc + ach * 8;
            cpasync16(base + OFF_AH + sw, A0 + g);
            cpasync16(base + OFF_AL + sw, A1 + g);
        }
        {
            uint32_t sw = swadr(br, bch);
            long g = (long)(n0 + br) * 2048 + kc + bch * 8;
            cpasync16(base + OFF_BH + sw, B0 + g);
            cpasync16(base + OFF_BL + sw, B1 + g);
        }
        asm volatile("cp.async.commit_group;" ::: "memory");
    };

    const int KI = 2048 / 32;
    issue(0, 0);
    issue(1, 32);
    int stage = 0;
    for (int kci = 0; kci < KI; kci++) {
        if (kci + 1 < KI) {
            asm volatile("cp.async.wait_group 1;" ::: "memory");
        } else {
            asm volatile("cp.async.wait_group 0;" ::: "memory");
        }
        __syncthreads();
        if (kci + 2 < KI) issue((stage + 2) % 3, (kci + 2) * 32);

        uint32_t base = sb + stage * STG_BYTES;
        #pragma unroll
        for (int ks = 0; ks < 2; ks++) {
            uint32_t ah[2][4], al[2][4];
            #pragma unroll
            for (int mf = 0; mf < 2; mf++) {
                uint32_t adr = base + OFF_AH + swadr(a_row + mf * 16, ks * 2 + a_ch);
                ldsm4(ah[mf][0], ah[mf][1], ah[mf][2], ah[mf][3], adr);
                adr = base + OFF_AL + swadr(a_row + mf * 16, ks * 2 + a_ch);
                ldsm4(al[mf][0], al[mf][1], al[mf][2], al[mf][3], adr);
            }
            uint32_t bh[4][2], bl[4][2];
            #pragma unroll
            for (int nf2 = 0; nf2 < 2; nf2++) {
                uint32_t adr = base + OFF_BH + swadr(b_row + nf2 * 16, ks * 2 + b_ch);
                ldsm4(bh[nf2*2][0], bh[nf2*2][1], bh[nf2*2+1][0], bh[nf2*2+1][1], adr);
                adr = base + OFF_BL + swadr(b_row + nf2 * 16, ks * 2 + b_ch);
                ldsm4(bl[nf2*2][0], bl[nf2*2][1], bl[nf2*2+1][0], bl[nf2*2+1][1], adr);
            }
            #pragma unroll
            for (int mf = 0; mf < 2; mf++)
                #pragma unroll
                for (int nf = 0; nf < 4; nf++) {
                    mma16816(acc[mf][nf], ah[mf], bh[nf]);
                    mma16816(acc[mf][nf], ah[mf], bl[nf]);
                    mma16816(acc[mf][nf], al[mf], bh[nf]);
                }
        }
        mask_step();
        mask_step();
        mask_step();
        stage = (stage + 1) % 3;
    }
    while (mt < NTRIPLES) mask_step();

    int cr = lane >> 2, cc = (lane & 3) << 1;
    #pragma unroll
    for (int mf = 0; mf < 2; mf++)
        #pragma unroll
        for (int nf = 0; nf < 4; nf++) {
            long row = m0 + wm * 32 + mf * 16 + cr;
            int col = n0 + wn * 32 + nf * 8 + cc;
            *(float2*)(C + row * N + col)       = make_float2(acc[mf][nf][0], acc[mf][nf][1]);
            *(float2*)(C + (row + 8) * N + col) = make_float2(acc[mf][nf][2], acc[mf][nf][3]);
        }
}

// ============================ fp16x2 GEMM for wo ===============================
// C = A0 * (B0 + B1); A fp16 (attention output), B fp16 hi/lo splits.
#define W_STG 16384
#define W_A0 0
#define W_B0 8192
#define W_B1 12288
#define WSM_TOT (3*W_STG)   // 49152

__global__ void __launch_bounds__(256) gemm_wo(
    const __half* __restrict__ A0,
    const __half* __restrict__ B0, const __half* __restrict__ B1,
    float* __restrict__ C) {
    extern __shared__ char smem[];
    uint32_t sb = smem_u32(smem);
    int tid = threadIdx.x, lane = tid & 31, wid = tid >> 5;
    int wm = wid & 3, wn = wid >> 2;
    long m0 = (long)blockIdx.y * 128;
    int n0 = blockIdx.x * 64;

    int lrow = lane & 7, ltile = lane >> 3;
    int a_row = wm * 32 + ((ltile & 1) << 3) + lrow;
    int a_ch  = ltile >> 1;
    int b_row = wn * 32 + ((ltile >> 1) << 3) + lrow;
    int b_ch  = ltile & 1;

    float acc[2][4][4];
    #pragma unroll
    for (int mf = 0; mf < 2; mf++)
        #pragma unroll
        for (int nf = 0; nf < 4; nf++)
            #pragma unroll
            for (int j = 0; j < 4; j++) acc[mf][nf][j] = 0.f;

    int ar0 = tid >> 1, ach2 = (tid & 1) * 2;     // A: 2 chunks/thread
    int br  = tid >> 2, bch = tid & 3;            // B: 1 chunk/thread/array

    auto issue = [&](int st, int kc) {
        uint32_t base = sb + st * W_STG;
        #pragma unroll
        for (int cc2 = 0; cc2 < 2; cc2++) {
            int ch = ach2 + cc2;
            cpasync16(base + W_A0 + swadr(ar0, ch), A0 + (m0 + ar0) * 2048 + kc + ch * 8);
        }
        {
            long g = (long)(n0 + br) * 2048 + kc + bch * 8;
            cpasync16(base + W_B0 + swadr(br, bch), B0 + g);
            cpasync16(base + W_B1 + swadr(br, bch), B1 + g);
        }
        asm volatile("cp.async.commit_group;" ::: "memory");
    };

    const int KI = 2048 / 32;
    issue(0, 0);
    issue(1, 32);
    int stage = 0;
    for (int kci = 0; kci < KI; kci++) {
        if (kci + 1 < KI) {
            asm volatile("cp.async.wait_group 1;" ::: "memory");
        } else {
            asm volatile("cp.async.wait_group 0;" ::: "memory");
        }
        __syncthreads();
        if (kci + 2 < KI) issue((stage + 2) % 3, (kci + 2) * 32);

        uint32_t base = sb + stage * W_STG;
        #pragma unroll
        for (int ks = 0; ks < 2; ks++) {
            uint32_t ah[2][4];
            #pragma unroll
            for (int mf = 0; mf < 2; mf++) {
                uint32_t adr = base + W_A0 + swadr(a_row + mf * 16, ks * 2 + a_ch);
                ldsm4(ah[mf][0], ah[mf][1], ah[mf][2], ah[mf][3], adr);
            }
            uint32_t bh[4][2], bl[4][2];
            #pragma unroll
            for (int nf2 = 0; nf2 < 2; nf2++) {
                uint32_t adr = base + W_B0 + swadr(b_row + nf2 * 16, ks * 2 + b_ch);
                ldsm4(bh[nf2*2][0], bh[nf2*2][1], bh[nf2*2+1][0], bh[nf2*2+1][1], adr);
                adr = base + W_B1 + swadr(b_row + nf2 * 16, ks * 2 + b_ch);
                ldsm4(bl[nf2*2][0], bl[nf2*2][1], bl[nf2*2+1][0], bl[nf2*2+1][1], adr);
            }
            #pragma unroll
            for (int mf = 0; mf < 2; mf++)
                #pragma unroll
                for (int nf = 0; nf < 4; nf++) {
                    mma16816h(acc[mf][nf], ah[mf], bh[nf]);
                    mma16816h(acc[mf][nf], ah[mf], bl[nf]);
                }
        }
        stage = (stage + 1) % 3;
    }

    int cr = lane >> 2, cc = (lane & 3) << 1;
    #pragma unroll
    for (int mf = 0; mf < 2; mf++)
        #pragma unroll
        for (int nf = 0; nf < 4; nf++) {
            long row = m0 + wm * 32 + mf * 16 + cr;
            int col = n0 + wn * 32 + nf * 8 + cc;
            *(float2*)(C + row * 2048 + col)       = make_float2(acc[mf][nf][0], acc[mf][nf][1]);
            *(float2*)(C + (row + 8) * 2048 + col) = make_float2(acc[mf][nf][2], acc[mf][nf][3]);
        }
}

// ============================ RoPE + pack + splits =============================
#define ROPE_RK (-0.20762050593478158f)   // -2*log2(10000)/128
__global__ void rope_pack(const float* __restrict__ q, const float* __restrict__ kraw,
                          const float* __restrict__ vraw, float* __restrict__ kv,
                          __nv_bfloat16* __restrict__ qh, __nv_bfloat16* __restrict__ ql,
                          __nv_bfloat16* __restrict__ kh, __nv_bfloat16* __restrict__ kl,
                          __half* __restrict__ vh, __half* __restrict__ vl) {
    int idx = blockIdx.x * 256 + threadIdx.x;
    {
        int row = idx >> 10;          // b*T + t
        int rem = idx & 1023;
        int h = rem >> 6, m = rem & 63;
        int b = row >> 11, t = row & 2047;
        float invf = exp2f(ROPE_RK * (float)m);
        float ang = (float)t * invf;
        float c, s;
        sincosf(ang, &s, &c);
        const float scale = 0.08838834764831845f;
        long base = (long)row * (HQ_ * HD_) + h * HD_ + m;
        float x1 = q[base], x2 = q[base + 64];
        float v1 = (x1 * c - x2 * s) * scale;
        float v2 = (x2 * c + x1 * s) * scale;
        long so = ((long)(b * HQ_ + h) * T_ + t) * 128 + m;
        __nv_bfloat16 h1 = __float2bfloat16(v1), h2 = __float2bfloat16(v2);
        qh[so] = h1;      qh[so + 64] = h2;
        ql[so] = __float2bfloat16(v1 - __bfloat162float(h1));
        ql[so + 64] = __float2bfloat16(v2 - __bfloat162float(h2));
    }
    if (idx < MROWS * HK_ * 64) {
        int krow = idx >> 8;
        int krem = idx & 255;
        int khd = krem >> 6, km = krem & 63;
        int b = krow >> 11, t = krow & 2047;
        float invf = exp2f(ROPE_RK * (float)km);
        float ang = (float)t * invf;
        float c, s;
        sincosf(ang, &s, &c);
        long src = (long)krow * (HK_ * HD_) + khd * HD_ + km;
        float x1 = kraw[src], x2 = kraw[src + 64];
        float v1 = x1 * c - x2 * s;
        float v2 = x2 * c + x1 * s;
        long dst = ((long)krow * HK_ + khd) * 256 + km;
        kv[dst]      = v1;
        kv[dst + 64] = v2;
        long so = ((long)(b * HK_ + khd) * T_ + t) * 128 + km;
        __nv_bfloat16 h1 = __float2bfloat16(v1), h2 = __float2bfloat16(v2);
        kh[so] = h1;      kh[so + 64] = h2;
        kl[so] = __float2bfloat16(v1 - __bfloat162float(h1));
        kl[so + 64] = __float2bfloat16(v2 - __bfloat162float(h2));
    }
    if (idx < KVELEMS / 4) {
        int f = idx;
        int vrow = f >> 7;
        int vc4 = f & 127;
        int vhd = vc4 >> 5, vd4 = (vc4 & 31) << 2;
        int b = vrow >> 11, t = vrow & 2047;
        float4 v = *(const float4*)(vraw + (long)f * 4);
        long dst = ((long)vrow * HK_ + vhd) * 256 + 128 + vd4;
        *(float4*)(kv + dst) = v;
        long so = ((long)(b * HK_ + vhd) * T_ + t) * 128 + vd4;
        float vv[4] = {v.x, v.y, v.z, v.w};
        #pragma unroll
        for (int j = 0; j < 4; j++) {
            __half hj = __float2half_rn(vv[j]);
            vh[so + j] = hj;
            vl[so + j] = __float2half_rn(vv[j] - __half2float(hj));
        }
    }
}

// ============================ tensor-core attention ============================
// smem: Q hi/lo (2x32KB) + 2-stage KV (2x64KB) = 192 KB; double-buffered pipeline.
#define A_QH 0
#define A_QL (A_QH + 128*256)
#define A_KV0 (A_QL + 128*256)          // stage base; KH/KL/VH/VL at +0/16K/32K/48K
#define A_KVSTG 65536
#define A_TOT (A_KV0 + 2*A_KVSTG)       // 196608 bytes

__global__ void __launch_bounds__(256) attn_mma(
    const __nv_bfloat16* __restrict__ Qh, const __nv_bfloat16* __restrict__ Ql,
    const __nv_bfloat16* __restrict__ Kh, const __nv_bfloat16* __restrict__ Kl,
    const __half* __restrict__ Vh, const __half* __restrict__ Vl,
    const uint32_t* __restrict__ Mask, __half* __restrict__ Oh) {
    extern __shared__ char smem[];
    uint32_t sb = smem_u32(smem);
    int tid = threadIdx.x, lane = tid & 31, wid = tid >> 5;
    int qb = (gridDim.x - 1) - blockIdx.x;
    int bh = blockIdx.y;
    int b = bh >> 4, hq = bh & 15, hk = hq & 3;

    const __nv_bfloat16* qhp = Qh + ((long)(b * HQ_ + hq) * T_ + qb * 128) * 128;
    const __nv_bfloat16* qlp = Ql + ((long)(b * HQ_ + hq) * T_ + qb * 128) * 128;
    const __nv_bfloat16* khp = Kh + (long)(b * HK_ + hk) * T_ * 128;
    const __nv_bfloat16* klp = Kl + (long)(b * HK_ + hk) * T_ * 128;
    const __half* vhp = Vh + (long)(b * HK_ + hk) * T_ * 128;
    const __half* vlp = Vl + (long)(b * HK_ + hk) * T_ * 128;

    #pragma unroll
    for (int it = 0; it < 16; it++) {
        int lin = tid + it * 256;
        int arr = lin >> 11, cidx = lin & 2047;
        int row = cidx >> 4, ch = cidx & 15;
        const __nv_bfloat16* src = (arr ? qlp : qhp) + row * 128 + ch * 8;
        cpasync16(sb + (arr ? A_QL : A_QH) + asw(row, ch), src);
    }

    auto kv_issue = [&](int st, int jb) {
        uint32_t base = sb + A_KV0 + st * A_KVSTG;
        #pragma unroll
        for (int it = 0; it < 16; it++) {
            int lin = tid + it * 256;
            int arr = lin >> 10, cidx = lin & 1023;
            int row = cidx >> 4, ch = cidx & 15;
            long g = (long)(jb * 64 + row) * 128 + ch * 8;
            const void* src;
            if (arr == 0)      src = khp + g;
            else if (arr == 1) src = klp + g;
            else if (arr == 2) src = vhp + g;
            else               src = vlp + g;
            cpasync16(base + arr * 16384 + asw(row, ch), src);
        }
        asm volatile("cp.async.commit_group;" ::: "memory");
    };

    int qrw = wid * 16;
    float m1 = -INFINITY, m2 = -INFINITY, l1 = 0.f, l2 = 0.f;
    float o[16][4];
    #pragma unroll
    for (int nf = 0; nf < 16; nf++)
        #pragma unroll
        for (int c = 0; c < 4; c++) o[nf][c] = 0.f;

    int ig1 = qb * 128 + qrw + (lane >> 2);
    long wbase0 = ((long)bh * 16 + qb) * 8192 + wid * 32 + lane;

    int a_row = qrw + ((lane >> 3) & 1) * 8 + (lane & 7);
    int a_chb = lane >> 4;
    int k_row8 = ((lane >> 4)) * 8 + (lane & 7);
    int k_chb = (lane >> 3) & 1;
    int v_row8 = ((lane >> 3) & 1) * 8 + (lane & 7);
    int v_chb = lane >> 4;

    int njb = 2 * qb + 2;
    kv_issue(0, 0);
    for (int jb = 0; jb < njb; jb++) {
        if (jb + 1 < njb) {
            kv_issue((jb + 1) & 1, jb + 1);
            asm volatile("cp.async.wait_group 1;" ::: "memory");
        } else {
            asm volatile("cp.async.wait_group 0;" ::: "memory");
        }
        uint32_t mw = Mask[wbase0 + (long)jb * 256];
        __syncthreads();
        uint32_t kvb = sb + A_KV0 + (jb & 1) * A_KVSTG;

        float sc[8][4];
        #pragma unroll
        for (int nf = 0; nf < 8; nf++)
            #pragma unroll
            for (int c = 0; c < 4; c++) sc[nf][c] = 0.f;
        #pragma unroll
        for (int ks = 0; ks < 8; ks++) {
            uint32_t qh4[4], ql4[4];
            ldsm4(qh4[0], qh4[1], qh4[2], qh4[3], sb + A_QH + asw(a_row, 2 * ks + a_chb));
            ldsm4(ql4[0], ql4[1], ql4[2], ql4[3], sb + A_QL + asw(a_row, 2 * ks + a_chb));
            #pragma unroll
            for (int nfp = 0; nfp < 4; nfp++) {
                uint32_t kh4[4], kl4[4];
                int br = nfp * 16 + k_row8;
                int bc = 2 * ks + k_chb;
                ldsm4(kh4[0], kh4[1], kh4[2], kh4[3], kvb + asw(br, bc));
                ldsm4(kl4[0], kl4[1], kl4[2], kl4[3], kvb + 16384 + asw(br, bc));
                mma16816(sc[2 * nfp],     qh4, kh4);
                mma16816(sc[2 * nfp],     qh4, kl4);
                mma16816(sc[2 * nfp],     ql4, kh4);
                mma16816(sc[2 * nfp + 1], qh4, kh4 + 2);
                mma16816(sc[2 * nfp + 1], qh4, kl4 + 2);
                mma16816(sc[2 * nfp + 1], ql4, kh4 + 2);
            }
        }

        if (jb * 64 + 63 > qb * 128 + qrw) {
            #pragma unroll
            for (int nf = 0; nf < 8; nf++) {
                int j0 = jb * 64 + nf * 8 + (lane & 3) * 2;
                if (j0 > ig1)     sc[nf][0] = -INFINITY;
                if (j0 + 1 > ig1) sc[nf][1] = -INFINITY;
                if (j0 > ig1 + 8)     sc[nf][2] = -INFINITY;
                if (j0 + 1 > ig1 + 8) sc[nf][3] = -INFINITY;
            }
        }

        float mx1 = -INFINITY, mx2 = -INFINITY;
        #pragma unroll
        for (int nf = 0; nf < 8; nf++) {
            mx1 = fmaxf(mx1, fmaxf(sc[nf][0], sc[nf][1]));
            mx2 = fmaxf(mx2, fmaxf(sc[nf][2], sc[nf][3]));
        }
        mx1 = fmaxf(mx1, __shfl_xor_sync(0xffffffffu, mx1, 1));
        mx1 = fmaxf(mx1, __shfl_xor_sync(0xffffffffu, mx1, 2));
        mx2 = fmaxf(mx2, __shfl_xor_sync(0xffffffffu, mx2, 1));
        mx2 = fmaxf(mx2, __shfl_xor_sync(0xffffffffu, mx2, 2));
        float mn1 = fmaxf(m1, mx1), mn2 = fmaxf(m2, mx2);
        float cr1 = __expf(m1 - mn1), cr2 = __expf(m2 - mn2);
        float rs1 = 0.f, rs2 = 0.f;
        #pragma unroll
        for (int nf = 0; nf < 8; nf++) {
            sc[nf][0] = __expf(sc[nf][0] - mn1); rs1 += sc[nf][0];
            sc[nf][1] = __expf(sc[nf][1] - mn1); rs1 += sc[nf][1];
            sc[nf][2] = __expf(sc[nf][2] - mn2); rs2 += sc[nf][2];
            sc[nf][3] = __expf(sc[nf][3] - mn2); rs2 += sc[nf][3];
        }
        rs1 += __shfl_xor_sync(0xffffffffu, rs1, 1);
        rs1 += __shfl_xor_sync(0xffffffffu, rs1, 2);
        rs2 += __shfl_xor_sync(0xffffffffu, rs2, 1);
        rs2 += __shfl_xor_sync(0xffffffffu, rs2, 2);
        l1 = l1 * cr1 + rs1;  l2 = l2 * cr2 + rs2;   // denom WITHOUT dropout (matches ref)
        m1 = mn1;  m2 = mn2;
        #pragma unroll
        for (int nf = 0; nf < 16; nf++) {
            o[nf][0] *= cr1; o[nf][1] *= cr1;
            o[nf][2] *= cr2; o[nf][3] *= cr2;
        }

        #pragma unroll
        for (int nf = 0; nf < 8; nf++) {
            sc[nf][0] *= ((mw >> (nf * 4 + 0)) & 1u) ? (1.0f / 0.9f) : 0.f;
            sc[nf][1] *= ((mw >> (nf * 4 + 1)) & 1u) ? (1.0f / 0.9f) : 0.f;
            sc[nf][2] *= ((mw >> (nf * 4 + 2)) & 1u) ? (1.0f / 0.9f) : 0.f;
            sc[nf][3] *= ((mw >> (nf * 4 + 3)) & 1u) ? (1.0f / 0.9f) : 0.f;
        }

        // O += P V  (P fp16, V fp16 hi/lo: 2 MMAs per fragment pair)
        #pragma unroll
        for (int ksj = 0; ksj < 4; ksj++) {
            uint32_t ahi[4];
            #pragma unroll
            for (int half = 0; half < 2; half++) {
                int nf = 2 * ksj + half;
                __half2 p01 = __floats2half2_rn(sc[nf][0], sc[nf][1]);
                __half2 p23 = __floats2half2_rn(sc[nf][2], sc[nf][3]);
                ahi[2 * half]     = *reinterpret_cast<uint32_t*>(&p01);
                ahi[2 * half + 1] = *reinterpret_cast<uint32_t*>(&p23);
            }
            #pragma unroll
            for (int nfp = 0; nfp < 8; nfp++) {
                uint32_t vh4[4], vl4[4];
                int vr = ksj * 16 + v_row8;
                int vc = 2 * nfp + v_chb;
                ldsm4t(vh4[0], vh4[1], vh4[2], vh4[3], kvb + 32768 + asw(vr, vc));
                ldsm4t(vl4[0], vl4[1], vl4[2], vl4[3], kvb + 49152 + asw(vr, vc));
                mma16816h(o[2 * nfp],     ahi, vh4);
                mma16816h(o[2 * nfp],     ahi, vl4);
                mma16816h(o[2 * nfp + 1], ahi, vh4 + 2);
                mma16816h(o[2 * nfp + 1], ahi, vl4 + 2);
            }
        }
        __syncthreads();
    }

    // fused epilogue: normalize, write fp16 output (wo GEMM's A operand)
    float inv1 = 1.f / l1, inv2 = 1.f / l2;
    long r1g = (long)(b * T_ + qb * 128 + qrw + (lane >> 2));
    #pragma unroll
    for (int nf = 0; nf < 16; nf++) {
        int col = hq * 128 + nf * 8 + (lane & 3) * 2;
        __half2 h1 = __floats2half2_rn(o[nf][0] * inv1, o[nf][1] * inv1);
        __half2 h2 = __floats2half2_rn(o[nf][2] * inv2, o[nf][3] * inv2);
        *(uint32_t*)(Oh + r1g * 2048 + col)       = *reinterpret_cast<uint32_t*>(&h1);
        *(uint32_t*)(Oh + (r1g + 8) * 2048 + col) = *reinterpret_cast<uint32_t*>(&h2);
    }
}

// ============================ launch ===========================================
extern "C" void kernel_launch(void* const* d_in, const int* in_sizes, int n_in,
                              void* d_out, int out_size) {
    const float* x  = (const float*)d_in[0];
    const float* wq = (const float*)d_in[1];
    const float* wk = (const float*)d_in[2];
    const float* wv = (const float*)d_in[3];
    const float* wo = (const float*)d_in[4];
    float* out = (float*)d_out;
    float* kv  = out + QELEMS;

    float *qp, *kp, *vp;
    cudaGetSymbolAddress((void**)&qp, g_q);
    cudaGetSymbolAddress((void**)&kp, g_kraw);
    cudaGetSymbolAddress((void**)&vp, g_vraw);
    uint32_t* maskp;
    cudaGetSymbolAddress((void**)&maskp, g_mask);
    __nv_bfloat16 *xs0, *xs1, *wqT0, *wqT1, *wkT0, *wkT1, *wvT0, *wvT1;
    __nv_bfloat16 *aqh, *aql, *akh, *akl;
    __half *avh, *avl, *woh0, *woh1, *ao;
    cudaGetSymbolAddress((void**)&xs0, g_xs0);
    cudaGetSymbolAddress((void**)&xs1, g_xs1);
    cudaGetSymbolAddress((void**)&wqT0, g_wqT0);
    cudaGetSymbolAddress((void**)&wqT1, g_wqT1);
    cudaGetSymbolAddress((void**)&wkT0, g_wkT0);
    cudaGetSymbolAddress((void**)&wkT1, g_wkT1);
    cudaGetSymbolAddress((void**)&wvT0, g_wvT0);
    cudaGetSymbolAddress((void**)&wvT1, g_wvT1);
    cudaGetSymbolAddress((void**)&woh0, g_woh0);
    cudaGetSymbolAddress((void**)&woh1, g_woh1);
    cudaGetSymbolAddress((void**)&ao, g_ao);
    cudaGetSymbolAddress((void**)&aqh, g_aqh);
    cudaGetSymbolAddress((void**)&aql, g_aql);
    cudaGetSymbolAddress((void**)&akh, g_akh);
    cudaGetSymbolAddress((void**)&akl, g_akl);
    cudaGetSymbolAddress((void**)&avh, g_avh);
    cudaGetSymbolAddress((void**)&avl, g_avl);

    cudaFuncSetAttribute(gemm_mma, cudaFuncAttributeMaxDynamicSharedMemorySize, GSM_TOT);
    cudaFuncSetAttribute(gemm_wo, cudaFuncAttributeMaxDynamicSharedMemorySize, WSM_TOT);
    cudaFuncSetAttribute(attn_mma, cudaFuncAttributeMaxDynamicSharedMemorySize, A_TOT);

    // prep
    split_f32<<<(MROWS * D_ / 4) / 256, 256>>>(x, xs0, xs1);
    wsplitT<<<dim3(D_ / 32, D_ / 32), dim3(32, 8)>>>(wq, wqT0, wqT1, D_);
    wsplitT<<<dim3(512 / 32, D_ / 32), dim3(32, 8)>>>(wk, wkT0, wkT1, 512);
    wsplitT<<<dim3(512 / 32, D_ / 32), dim3(32, 8)>>>(wv, wvT0, wvT1, 512);
    wsplitT_h<<<dim3(D_ / 32, D_ / 32), dim3(32, 8)>>>(wo, woh0, woh1, D_);

    // fused q/k/v projections + dropout-mask generation
    gemm_mma<<<dim3(48, MROWS / 128), 256, GSM_TOT>>>(
        xs0, xs1, wqT0, wqT1, wkT0, wkT1, wvT0, wvT1, qp, kp, vp, maskp);

    rope_pack<<<(MROWS * HQ_ * 64) / 256, 256>>>(qp, kp, vp, kv, aqh, aql, akh, akl, avh, avl);

    // tensor-core attention: writes fp16 output directly
    attn_mma<<<dim3(T_ / 128, B_ * HQ_), 256, A_TOT>>>(
        aqh, aql, akh, akl, avh, avl, maskp, ao);

    // out projection: fp16x2
    gemm_wo<<<dim3(32, MROWS / 128), 256, WSM_TOT>>>(ao, woh0, woh1, out);
}

// round 12
// speedup vs baseline: 1.5414x; 1.1129x over previous
#include <cuda_runtime.h>
#include <cuda_bf16.h>
#include <cuda_fp16.h>
#include <math.h>
#include <stdint.h>

#define B_   2
#define T_   2048
#define D_   2048
#define HQ_  16
#define HK_  4
#define HD_  128
#define MROWS (B_*T_)            // 4096
#define QELEMS (MROWS*HQ_*HD_)   // 8388608
#define KVELEMS (MROWS*HK_*HD_)  // 2097152
#define NTRIPLES 8704            // 32 bh * sum_{qb<16}(2qb+2)

// fp32 scratch (GEMM outputs)
__device__ float g_q[QELEMS];
__device__ float g_kraw[KVELEMS];
__device__ float g_vraw[KVELEMS];
// dropout mask bits
__device__ uint32_t g_mask[32*16*32*8*32];   // 16 MB
// fp16 operands
__device__ __half g_xh[MROWS*D_];            // x (single fp16)
__device__ __half g_wqh0[D_*D_], g_wqh1[D_*D_];
__device__ __half g_wkh0[512*D_], g_wkh1[512*D_];
__device__ __half g_wvh0[512*D_], g_wvh1[512*D_];
__device__ __half g_woh0[D_*D_], g_woh1[D_*D_];
__device__ __half g_ao[MROWS*D_];            // attention output (fp16)
// attention operands, head-major [b][h][t][128]
__device__ __half g_aqh[QELEMS];             // Q (single fp16, pre-scaled)
__device__ __half g_akh[KVELEMS], g_akl[KVELEMS];
__device__ __half g_avh[KVELEMS], g_avl[KVELEMS];

// ============================ helpers =========================================
__device__ __forceinline__ uint32_t smem_u32(const void* p) {
    uint32_t a;
    asm("{ .reg .u64 t; cvta.to.shared.u64 t, %1; cvt.u32.u64 %0, t; }" : "=r"(a) : "l"(p));
    return a;
}
__device__ __forceinline__ void cpasync16(uint32_t s, const void* g) {
    asm volatile("cp.async.cg.shared.global [%0], [%1], 16;" :: "r"(s), "l"(g));
}
__device__ __forceinline__ void ldsm4(uint32_t& r0, uint32_t& r1, uint32_t& r2, uint32_t& r3,
                                      uint32_t addr) {
    asm volatile("ldmatrix.sync.aligned.m8n8.x4.shared.b16 {%0,%1,%2,%3}, [%4];"
                 : "=r"(r0), "=r"(r1), "=r"(r2), "=r"(r3) : "r"(addr));
}
__device__ __forceinline__ void ldsm4t(uint32_t& r0, uint32_t& r1, uint32_t& r2, uint32_t& r3,
                                       uint32_t addr) {
    asm volatile("ldmatrix.sync.aligned.m8n8.x4.trans.shared.b16 {%0,%1,%2,%3}, [%4];"
                 : "=r"(r0), "=r"(r1), "=r"(r2), "=r"(r3) : "r"(addr));
}
__device__ __forceinline__ void mma16816h(float* c, const uint32_t* a, const uint32_t* b) {
    asm volatile("mma.sync.aligned.m16n8k16.row.col.f32.f16.f16.f32 "
                 "{%0,%1,%2,%3}, {%4,%5,%6,%7}, {%8,%9}, {%0,%1,%2,%3};"
                 : "+f"(c[0]), "+f"(c[1]), "+f"(c[2]), "+f"(c[3])
                 : "r"(a[0]), "r"(a[1]), "r"(a[2]), "r"(a[3]), "r"(b[0]), "r"(b[1]));
}
// GEMM tile swizzle: [rows][32 elems of 2B] (64B rows, 16B chunks)
__device__ __forceinline__ uint32_t swadr(int row, int ch) {
    return (uint32_t)(row * 64 + ((ch ^ ((row >> 1) & 3)) << 4));
}
// attention tile swizzle: [rows][128 elems] (256B rows, 16 chunks of 16B)
__device__ __forceinline__ uint32_t asw(int row, int ch) {
    return (uint32_t)(row * 256 + ((ch ^ (row & 7)) << 4));
}

// ============================ threefry (partitionable) =========================
__device__ __forceinline__ unsigned tf_rotl(unsigned x, int r) {
    return (x << r) | (x >> (32 - r));
}
__device__ __forceinline__ unsigned dropout_bit(unsigned e) {
    unsigned x0 = 0u, x1 = e;
    const unsigned k0 = 0u, k1 = 1u, k2 = 0x1BD11BDAu ^ k0 ^ k1;
    x0 += k0; x1 += k1;
#define TFR(r) { x0 += x1; x1 = tf_rotl(x1, r); x1 ^= x0; }
    TFR(13) TFR(15) TFR(26) TFR(6)
    x0 += k1; x1 += k2 + 1u;
    TFR(17) TFR(29) TFR(16) TFR(24)
    x0 += k2; x1 += k0 + 2u;
    TFR(13) TFR(15) TFR(26) TFR(6)
    x0 += k0; x1 += k1 + 3u;
    TFR(17) TFR(29) TFR(16) TFR(24)
    x0 += k1; x1 += k2 + 4u;
    TFR(13) TFR(15) TFR(26) TFR(6)
    x0 += k2; x1 += k0 + 5u;
#undef TFR
    unsigned bits = x0 ^ x1;
    float u = __uint_as_float((bits >> 9) | 0x3F800000u) - 1.0f;
    return (u < 0.9f) ? 1u : 0u;
}

// ============================ prep kernels =====================================
__global__ void conv_h(const float* __restrict__ in, __half* __restrict__ o0) {
    int i = blockIdx.x * 256 + threadIdx.x;
    float4 v = ((const float4*)in)[i];
    __half2 a = __floats2half2_rn(v.x, v.y);
    __half2 b = __floats2half2_rn(v.z, v.w);
    ((uint2*)o0)[i] = make_uint2(*reinterpret_cast<uint32_t*>(&a),
                                 *reinterpret_cast<uint32_t*>(&b));
}

__global__ void wsplitT_h(const float* __restrict__ W, __half* __restrict__ t0,
                          __half* __restrict__ t1, int N) {
    __shared__ float tile[32][33];
    int n0 = blockIdx.x * 32, k0 = blockIdx.y * 32;
    int tx = threadIdx.x, ty = threadIdx.y;
    #pragma unroll
    for (int i = 0; i < 4; i++)
        tile[ty + i * 8][tx] = W[(long)(k0 + ty + i * 8) * N + n0 + tx];
    __syncthreads();
    #pragma unroll
    for (int i = 0; i < 4; i++) {
        float v = tile[tx][ty + i * 8];
        __half h = __float2half_rn(v);
        __half l = __float2half_rn(v - __half2float(h));
        long o = (long)(n0 + ty + i * 8) * 2048 + k0 + tx;
        t0[o] = h; t1[o] = l;
    }
}

// ============================ unified fp16x2 GEMM (+ optional mask gen) ========
// C = A * (B0 + B1); A single fp16 row-major [M][2048], B hi/lo fp16 [N][2048].
#define G_STG 16384
#define G_A  0
#define G_B0 8192
#define G_B1 12288
#define G_TOT (3*G_STG)   // 49152

__global__ void __launch_bounds__(256) gemm_h(
    const __half* __restrict__ A,
    const __half* __restrict__ Bq0, const __half* __restrict__ Bq1,
    const __half* __restrict__ Bk0, const __half* __restrict__ Bk1,
    const __half* __restrict__ Bv0, const __half* __restrict__ Bv1,
    float* __restrict__ Cq, float* __restrict__ Ck, float* __restrict__ Cv,
    uint32_t* __restrict__ mask) {
    extern __shared__ char smem[];
    uint32_t sb = smem_u32(smem);
    int tid = threadIdx.x, lane = tid & 31, wid = tid >> 5;
    int wm = wid & 3, wn = wid >> 2;
    long m0 = (long)blockIdx.y * 128;

    const __half *B0, *B1;
    float* C;
    int N, n0;
    int nb = blockIdx.x;
    if (nb < 32)      { B0 = Bq0; B1 = Bq1; C = Cq; N = 2048; n0 = nb * 64; }
    else if (nb < 40) { B0 = Bk0; B1 = Bk1; C = Ck; N = 512;  n0 = (nb - 32) * 64; }
    else              { B0 = Bv0; B1 = Bv1; C = Cv; N = 512;  n0 = (nb - 40) * 64; }

    int lrow = lane & 7, ltile = lane >> 3;
    int a_row = wm * 32 + ((ltile & 1) << 3) + lrow;
    int a_ch  = ltile >> 1;
    int b_row = wn * 32 + ((ltile >> 1) << 3) + lrow;
    int b_ch  = ltile & 1;

    float acc[2][4][4];
    #pragma unroll
    for (int mf = 0; mf < 2; mf++)
        #pragma unroll
        for (int nf = 0; nf < 4; nf++)
            #pragma unroll
            for (int j = 0; j < 4; j++) acc[mf][nf][j] = 0.f;

    int ar = tid >> 1, ach2 = (tid & 1) * 2;   // A: 2 chunks/thread
    int br = tid >> 2, bch = tid & 3;          // B: 1 chunk/thread/array

    // ---- interleaved dropout-mask generation state ----
    int mstride = gridDim.x * gridDim.y;
    int mt = mask ? (blockIdx.y * gridDim.x + blockIdx.x) : NTRIPLES;
    int mh = 0;
    uint32_t mword = 0;
    unsigned mebase = 0;
    int mrowb = 0, mcolb = 0;
    long mwidx = 0;

    auto mask_step = [&]() {
        if (mt >= NTRIPLES) return;
        if (mh == 0) {
            int bh = mt / 272;
            int r = mt - bh * 272;
            int qb = 0;
            while (r >= 2 * qb + 2) { r -= 2 * qb + 2; qb++; }
            int jb = r;
            mebase = (unsigned)bh * 4194304u;
            mrowb = qb * 128 + wid * 16 + (lane >> 2);
            mcolb = jb * 64 + (lane & 3) * 2;
            mwidx = ((((long)bh * 16 + qb) * 32 + jb) * 8 + wid) * 32 + lane;
        }
        int nf = mh >> 2, rs = (mh >> 1) & 1, cs = mh & 1;
        unsigned e = mebase + (unsigned)(mrowb + rs * 8) * 2048u
                            + (unsigned)(mcolb + nf * 8 + cs);
        mword |= dropout_bit(e) << mh;
        mh++;
        if (mh == 32) { mask[mwidx] = mword; mword = 0; mh = 0; mt += mstride; }
    };

    auto issue = [&](int st, int kc) {
        uint32_t base = sb + st * G_STG;
        #pragma unroll
        for (int cc2 = 0; cc2 < 2; cc2++) {
            int ch = ach2 + cc2;
            cpasync16(base + G_A + swadr(ar, ch), A + (m0 + ar) * 2048 + kc + ch * 8);
        }
        {
            long g = (long)(n0 + br) * 2048 + kc + bch * 8;
            cpasync16(base + G_B0 + swadr(br, bch), B0 + g);
            cpasync16(base + G_B1 + swadr(br, bch), B1 + g);
        }
        asm volatile("cp.async.commit_group;" ::: "memory");
    };

    const int KI = 2048 / 32;
    issue(0, 0);
    issue(1, 32);
    int stage = 0;
    for (int kci = 0; kci < KI; kci++) {
        if (kci + 1 < KI) {
            asm volatile("cp.async.wait_group 1;" ::: "memory");
        } else {
            asm volatile("cp.async.wait_group 0;" ::: "memory");
        }
        __syncthreads();
        if (kci + 2 < KI) issue((stage + 2) % 3, (kci + 2) * 32);

        uint32_t base = sb + stage * G_STG;
        #pragma unroll
        for (int ks = 0; ks < 2; ks++) {
            uint32_t ah[2][4];
            #pragma unroll
            for (int mf = 0; mf < 2; mf++) {
                uint32_t adr = base + G_A + swadr(a_row + mf * 16, ks * 2 + a_ch);
                ldsm4(ah[mf][0], ah[mf][1], ah[mf][2], ah[mf][3], adr);
            }
            uint32_t bh[4][2], bl[4][2];
            #pragma unroll
            for (int nf2 = 0; nf2 < 2; nf2++) {
                uint32_t adr = base + G_B0 + swadr(b_row + nf2 * 16, ks * 2 + b_ch);
                ldsm4(bh[nf2*2][0], bh[nf2*2][1], bh[nf2*2+1][0], bh[nf2*2+1][1], adr);
                adr = base + G_B1 + swadr(b_row + nf2 * 16, ks * 2 + b_ch);
                ldsm4(bl[nf2*2][0], bl[nf2*2][1], bl[nf2*2+1][0], bl[nf2*2+1][1], adr);
            }
            #pragma unroll
            for (int mf = 0; mf < 2; mf++)
                #pragma unroll
                for (int nf = 0; nf < 4; nf++) {
                    mma16816h(acc[mf][nf], ah[mf], bh[nf]);
                    mma16816h(acc[mf][nf], ah[mf], bl[nf]);
                }
        }
        mask_step();
        mask_step();
        mask_step();
        stage = (stage + 1) % 3;
    }
    while (mt < NTRIPLES) mask_step();

    int cr = lane >> 2, cc = (lane & 3) << 1;
    #pragma unroll
    for (int mf = 0; mf < 2; mf++)
        #pragma unroll
        for (int nf = 0; nf < 4; nf++) {
            long row = m0 + wm * 32 + mf * 16 + cr;
            int col = n0 + wn * 32 + nf * 8 + cc;
            *(float2*)(C + row * N + col)       = make_float2(acc[mf][nf][0], acc[mf][nf][1]);
            *(float2*)(C + (row + 8) * N + col) = make_float2(acc[mf][nf][2], acc[mf][nf][3]);
        }
}

// ============================ RoPE + pack + fp16 operands ======================
#define ROPE_RK (-0.20762050593478158f)   // -2*log2(10000)/128
__global__ void rope_pack(const float* __restrict__ q, const float* __restrict__ kraw,
                          const float* __restrict__ vraw, float* __restrict__ kv,
                          __half* __restrict__ qh,
                          __half* __restrict__ kh, __half* __restrict__ kl,
                          __half* __restrict__ vh, __half* __restrict__ vl) {
    int idx = blockIdx.x * 256 + threadIdx.x;
    {
        int row = idx >> 10;          // b*T + t
        int rem = idx & 1023;
        int h = rem >> 6, m = rem & 63;
        int b = row >> 11, t = row & 2047;
        float invf = exp2f(ROPE_RK * (float)m);
        float ang = (float)t * invf;
        float c, s;
        sincosf(ang, &s, &c);
        const float scale = 0.08838834764831845f;
        long base = (long)row * (HQ_ * HD_) + h * HD_ + m;
        float x1 = q[base], x2 = q[base + 64];
        float v1 = (x1 * c - x2 * s) * scale;
        float v2 = (x2 * c + x1 * s) * scale;
        long so = ((long)(b * HQ_ + h) * T_ + t) * 128 + m;
        qh[so] = __float2half_rn(v1);
        qh[so + 64] = __float2half_rn(v2);
    }
    if (idx < MROWS * HK_ * 64) {
        int krow = idx >> 8;
        int krem = idx & 255;
        int khd = krem >> 6, km = krem & 63;
        int b = krow >> 11, t = krow & 2047;
        float invf = exp2f(ROPE_RK * (float)km);
        float ang = (float)t * invf;
        float c, s;
        sincosf(ang, &s, &c);
        long src = (long)krow * (HK_ * HD_) + khd * HD_ + km;
        float x1 = kraw[src], x2 = kraw[src + 64];
        float v1 = x1 * c - x2 * s;
        float v2 = x2 * c + x1 * s;
        long dst = ((long)krow * HK_ + khd) * 256 + km;
        kv[dst]      = v1;
        kv[dst + 64] = v2;
        long so = ((long)(b * HK_ + khd) * T_ + t) * 128 + km;
        __half h1 = __float2half_rn(v1), h2 = __float2half_rn(v2);
        kh[so] = h1;      kh[so + 64] = h2;
        kl[so] = __float2half_rn(v1 - __half2float(h1));
        kl[so + 64] = __float2half_rn(v2 - __half2float(h2));
    }
    if (idx < KVELEMS / 4) {
        int f = idx;
        int vrow = f >> 7;
        int vc4 = f & 127;
        int vhd = vc4 >> 5, vd4 = (vc4 & 31) << 2;
        int b = vrow >> 11, t = vrow & 2047;
        float4 v = *(const float4*)(vraw + (long)f * 4);
        long dst = ((long)vrow * HK_ + vhd) * 256 + 128 + vd4;
        *(float4*)(kv + dst) = v;
        long so = ((long)(b * HK_ + vhd) * T_ + t) * 128 + vd4;
        float vv[4] = {v.x, v.y, v.z, v.w};
        #pragma unroll
        for (int j = 0; j < 4; j++) {
            __half hj = __float2half_rn(vv[j]);
            vh[so + j] = hj;
            vl[so + j] = __float2half_rn(vv[j] - __half2float(hj));
        }
    }
}

// ============================ tensor-core attention ============================
// smem: Q (32KB) + 2-stage KV (2x64KB) = 160 KB; double-buffered pipeline.
#define A_QH 0
#define A_KV0 (A_QH + 128*256)          // stage base; KH/KL/VH/VL at +0/16K/32K/48K
#define A_KVSTG 65536
#define A_TOT (A_KV0 + 2*A_KVSTG)       // 163840 bytes

__global__ void __launch_bounds__(256) attn_mma(
    const __half* __restrict__ Qh,
    const __half* __restrict__ Kh, const __half* __restrict__ Kl,
    const __half* __restrict__ Vh, const __half* __restrict__ Vl,
    const uint32_t* __restrict__ Mask, __half* __restrict__ Oh) {
    extern __shared__ char smem[];
    uint32_t sb = smem_u32(smem);
    int tid = threadIdx.x, lane = tid & 31, wid = tid >> 5;
    int qb = (gridDim.x - 1) - blockIdx.x;
    int bh = blockIdx.y;
    int b = bh >> 4, hq = bh & 15, hk = hq & 3;

    const __half* qhp = Qh + ((long)(b * HQ_ + hq) * T_ + qb * 128) * 128;
    const __half* khp = Kh + (long)(b * HK_ + hk) * T_ * 128;
    const __half* klp = Kl + (long)(b * HK_ + hk) * T_ * 128;
    const __half* vhp = Vh + (long)(b * HK_ + hk) * T_ * 128;
    const __half* vlp = Vl + (long)(b * HK_ + hk) * T_ * 128;

    // Q tile: 2048 chunks
    #pragma unroll
    for (int it = 0; it < 8; it++) {
        int lin = tid + it * 256;
        int row = lin >> 4, ch = lin & 15;
        cpasync16(sb + A_QH + asw(row, ch), qhp + row * 128 + ch * 8);
    }

    auto kv_issue = [&](int st, int jb) {
        uint32_t base = sb + A_KV0 + st * A_KVSTG;
        #pragma unroll
        for (int it = 0; it < 16; it++) {
            int lin = tid + it * 256;
            int arr = lin >> 10, cidx = lin & 1023;
            int row = cidx >> 4, ch = cidx & 15;
            long g = (long)(jb * 64 + row) * 128 + ch * 8;
            const __half* src;
            if (arr == 0)      src = khp + g;
            else if (arr == 1) src = klp + g;
            else if (arr == 2) src = vhp + g;
            else               src = vlp + g;
            cpasync16(base + arr * 16384 + asw(row, ch), src);
        }
        asm volatile("cp.async.commit_group;" ::: "memory");
    };

    int qrw = wid * 16;
    float m1 = -INFINITY, m2 = -INFINITY, l1 = 0.f, l2 = 0.f;
    float o[16][4];
    #pragma unroll
    for (int nf = 0; nf < 16; nf++)
        #pragma unroll
        for (int c = 0; c < 4; c++) o[nf][c] = 0.f;

    int ig1 = qb * 128 + qrw + (lane >> 2);
    long wbase0 = ((long)bh * 16 + qb) * 8192 + wid * 32 + lane;

    int a_row = qrw + ((lane >> 3) & 1) * 8 + (lane & 7);
    int a_chb = lane >> 4;
    int k_row8 = ((lane >> 4)) * 8 + (lane & 7);
    int k_chb = (lane >> 3) & 1;
    int v_row8 = ((lane >> 3) & 1) * 8 + (lane & 7);
    int v_chb = lane >> 4;

    int njb = 2 * qb + 2;
    kv_issue(0, 0);   // includes Q loads in this group
    for (int jb = 0; jb < njb; jb++) {
        if (jb + 1 < njb) {
            kv_issue((jb + 1) & 1, jb + 1);
            asm volatile("cp.async.wait_group 1;" ::: "memory");
        } else {
            asm volatile("cp.async.wait_group 0;" ::: "memory");
        }
        uint32_t mw = Mask[wbase0 + (long)jb * 256];
        __syncthreads();
        uint32_t kvb = sb + A_KV0 + (jb & 1) * A_KVSTG;

        // S = Q K^T (Q single fp16, K hi/lo fp16: 2 MMAs/fragment)
        float sc[8][4];
        #pragma unroll
        for (int nf = 0; nf < 8; nf++)
            #pragma unroll
            for (int c = 0; c < 4; c++) sc[nf][c] = 0.f;
        #pragma unroll
        for (int ks = 0; ks < 8; ks++) {
            uint32_t qh4[4];
            ldsm4(qh4[0], qh4[1], qh4[2], qh4[3], sb + A_QH + asw(a_row, 2 * ks + a_chb));
            #pragma unroll
            for (int nfp = 0; nfp < 4; nfp++) {
                uint32_t kh4[4], kl4[4];
                int br = nfp * 16 + k_row8;
                int bc = 2 * ks + k_chb;
                ldsm4(kh4[0], kh4[1], kh4[2], kh4[3], kvb + asw(br, bc));
                ldsm4(kl4[0], kl4[1], kl4[2], kl4[3], kvb + 16384 + asw(br, bc));
                mma16816h(sc[2 * nfp],     qh4, kh4);
                mma16816h(sc[2 * nfp],     qh4, kl4);
                mma16816h(sc[2 * nfp + 1], qh4, kh4 + 2);
                mma16816h(sc[2 * nfp + 1], qh4, kl4 + 2);
            }
        }

        if (jb * 64 + 63 > qb * 128 + qrw) {
            #pragma unroll
            for (int nf = 0; nf < 8; nf++) {
                int j0 = jb * 64 + nf * 8 + (lane & 3) * 2;
                if (j0 > ig1)     sc[nf][0] = -INFINITY;
                if (j0 + 1 > ig1) sc[nf][1] = -INFINITY;
                if (j0 > ig1 + 8)     sc[nf][2] = -INFINITY;
                if (j0 + 1 > ig1 + 8) sc[nf][3] = -INFINITY;
            }
        }

        float mx1 = -INFINITY, mx2 = -INFINITY;
        #pragma unroll
        for (int nf = 0; nf < 8; nf++) {
            mx1 = fmaxf(mx1, fmaxf(sc[nf][0], sc[nf][1]));
            mx2 = fmaxf(mx2, fmaxf(sc[nf][2], sc[nf][3]));
        }
        mx1 = fmaxf(mx1, __shfl_xor_sync(0xffffffffu, mx1, 1));
        mx1 = fmaxf(mx1, __shfl_xor_sync(0xffffffffu, mx1, 2));
        mx2 = fmaxf(mx2, __shfl_xor_sync(0xffffffffu, mx2, 1));
        mx2 = fmaxf(mx2, __shfl_xor_sync(0xffffffffu, mx2, 2));
        float mn1 = fmaxf(m1, mx1), mn2 = fmaxf(m2, mx2);
        float cr1 = __expf(m1 - mn1), cr2 = __expf(m2 - mn2);
        float rs1 = 0.f, rs2 = 0.f;
        #pragma unroll
        for (int nf = 0; nf < 8; nf++) {
            sc[nf][0] = __expf(sc[nf][0] - mn1); rs1 += sc[nf][0];
            sc[nf][1] = __expf(sc[nf][1] - mn1); rs1 += sc[nf][1];
            sc[nf][2] = __expf(sc[nf][2] - mn2); rs2 += sc[nf][2];
            sc[nf][3] = __expf(sc[nf][3] - mn2); rs2 += sc[nf][3];
        }
        rs1 += __shfl_xor_sync(0xffffffffu, rs1, 1);
        rs1 += __shfl_xor_sync(0xffffffffu, rs1, 2);
        rs2 += __shfl_xor_sync(0xffffffffu, rs2, 1);
        rs2 += __shfl_xor_sync(0xffffffffu, rs2, 2);
        l1 = l1 * cr1 + rs1;  l2 = l2 * cr2 + rs2;   // denom WITHOUT dropout (matches ref)
        m1 = mn1;  m2 = mn2;
        #pragma unroll
        for (int nf = 0; nf < 16; nf++) {
            o[nf][0] *= cr1; o[nf][1] *= cr1;
            o[nf][2] *= cr2; o[nf][3] *= cr2;
        }

        #pragma unroll
        for (int nf = 0; nf < 8; nf++) {
            sc[nf][0] *= ((mw >> (nf * 4 + 0)) & 1u) ? (1.0f / 0.9f) : 0.f;
            sc[nf][1] *= ((mw >> (nf * 4 + 1)) & 1u) ? (1.0f / 0.9f) : 0.f;
            sc[nf][2] *= ((mw >> (nf * 4 + 2)) & 1u) ? (1.0f / 0.9f) : 0.f;
            sc[nf][3] *= ((mw >> (nf * 4 + 3)) & 1u) ? (1.0f / 0.9f) : 0.f;
        }

        // O += P V  (P fp16, V fp16 hi/lo: 2 MMAs per fragment pair)
        #pragma unroll
        for (int ksj = 0; ksj < 4; ksj++) {
            uint32_t ahi[4];
            #pragma unroll
            for (int half = 0; half < 2; half++) {
                int nf = 2 * ksj + half;
                __half2 p01 = __floats2half2_rn(sc[nf][0], sc[nf][1]);
                __half2 p23 = __floats2half2_rn(sc[nf][2], sc[nf][3]);
                ahi[2 * half]     = *reinterpret_cast<uint32_t*>(&p01);
                ahi[2 * half + 1] = *reinterpret_cast<uint32_t*>(&p23);
            }
            #pragma unroll
            for (int nfp = 0; nfp < 8; nfp++) {
                uint32_t vh4[4], vl4[4];
                int vr = ksj * 16 + v_row8;
                int vc = 2 * nfp + v_chb;
                ldsm4t(vh4[0], vh4[1], vh4[2], vh4[3], kvb + 32768 + asw(vr, vc));
                ldsm4t(vl4[0], vl4[1], vl4[2], vl4[3], kvb + 49152 + asw(vr, vc));
                mma16816h(o[2 * nfp],     ahi, vh4);
                mma16816h(o[2 * nfp],     ahi, vl4);
                mma16816h(o[2 * nfp + 1], ahi, vh4 + 2);
                mma16816h(o[2 * nfp + 1], ahi, vl4 + 2);
            }
        }
        __syncthreads();
    }

    // fused epilogue: normalize, write fp16 output (wo GEMM's A operand)
    float inv1 = 1.f / l1, inv2 = 1.f / l2;
    long r1g = (long)(b * T_ + qb * 128 + qrw + (lane >> 2));
    #pragma unroll
    for (int nf = 0; nf < 16; nf++) {
        int col = hq * 128 + nf * 8 + (lane & 3) * 2;
        __half2 h1 = __floats2half2_rn(o[nf][0] * inv1, o[nf][1] * inv1);
        __half2 h2 = __floats2half2_rn(o[nf][2] * inv2, o[nf][3] * inv2);
        *(uint32_t*)(Oh + r1g * 2048 + col)       = *reinterpret_cast<uint32_t*>(&h1);
        *(uint32_t*)(Oh + (r1g + 8) * 2048 + col) = *reinterpret_cast<uint32_t*>(&h2);
    }
}

// ============================ launch ===========================================
extern "C" void kernel_launch(void* const* d_in, const int* in_sizes, int n_in,
                              void* d_out, int out_size) {
    const float* x  = (const float*)d_in[0];
    const float* wq = (const float*)d_in[1];
    const float* wk = (const float*)d_in[2];
    const float* wv = (const float*)d_in[3];
    const float* wo = (const float*)d_in[4];
    float* out = (float*)d_out;
    float* kv  = out + QELEMS;

    float *qp, *kp, *vp;
    cudaGetSymbolAddress((void**)&qp, g_q);
    cudaGetSymbolAddress((void**)&kp, g_kraw);
    cudaGetSymbolAddress((void**)&vp, g_vraw);
    uint32_t* maskp;
    cudaGetSymbolAddress((void**)&maskp, g_mask);
    __half *xh, *wqh0, *wqh1, *wkh0, *wkh1, *wvh0, *wvh1, *woh0, *woh1, *ao;
    __half *aqh, *akh, *akl, *avh, *avl;
    cudaGetSymbolAddress((void**)&xh, g_xh);
    cudaGetSymbolAddress((void**)&wqh0, g_wqh0);
    cudaGetSymbolAddress((void**)&wqh1, g_wqh1);
    cudaGetSymbolAddress((void**)&wkh0, g_wkh0);
    cudaGetSymbolAddress((void**)&wkh1, g_wkh1);
    cudaGetSymbolAddress((void**)&wvh0, g_wvh0);
    cudaGetSymbolAddress((void**)&wvh1, g_wvh1);
    cudaGetSymbolAddress((void**)&woh0, g_woh0);
    cudaGetSymbolAddress((void**)&woh1, g_woh1);
    cudaGetSymbolAddress((void**)&ao, g_ao);
    cudaGetSymbolAddress((void**)&aqh, g_aqh);
    cudaGetSymbolAddress((void**)&akh, g_akh);
    cudaGetSymbolAddress((void**)&akl, g_akl);
    cudaGetSymbolAddress((void**)&avh, g_avh);
    cudaGetSymbolAddress((void**)&avl, g_avl);

    cudaFuncSetAttribute(gemm_h, cudaFuncAttributeMaxDynamicSharedMemorySize, G_TOT);
    cudaFuncSetAttribute(attn_mma, cudaFuncAttributeMaxDynamicSharedMemorySize, A_TOT);

    // prep
    conv_h<<<(MROWS * D_ / 4) / 256, 256>>>(x, xh);
    wsplitT_h<<<dim3(D_ / 32, D_ / 32), dim3(32, 8)>>>(wq, wqh0, wqh1, D_);
    wsplitT_h<<<dim3(512 / 32, D_ / 32), dim3(32, 8)>>>(wk, wkh0, wkh1, 512);
    wsplitT_h<<<dim3(512 / 32, D_ / 32), dim3(32, 8)>>>(wv, wvh0, wvh1, 512);
    wsplitT_h<<<dim3(D_ / 32, D_ / 32), dim3(32, 8)>>>(wo, woh0, woh1, D_);

    // fused q/k/v projections + dropout-mask generation (fp16x2)
    gemm_h<<<dim3(48, MROWS / 128), 256, G_TOT>>>(
        xh, wqh0, wqh1, wkh0, wkh1, wvh0, wvh1, qp, kp, vp, maskp);

    rope_pack<<<(MROWS * HQ_ * 64) / 256, 256>>>(qp, kp, vp, kv, aqh, akh, akl, avh, avl);

    // tensor-core attention (fp16x2 both phases)
    attn_mma<<<dim3(T_ / 128, B_ * HQ_), 256, A_TOT>>>(
        aqh, akh, akl, avh, avl, maskp, ao);

    // out projection (fp16x2, same kernel, no mask)
    gemm_h<<<dim3(32, MROWS / 128), 256, G_TOT>>>(
        ao, woh0, woh1, woh0, woh1, woh0, woh1, out, out, out, (uint32_t*)nullptr);
}

// round 14
// speedup vs baseline: 1.8078x; 1.1728x over previous
#include <cuda_runtime.h>
#include <cuda_bf16.h>
#include <cuda_fp16.h>
#include <math.h>
#include <stdint.h>

#define B_   2
#define T_   2048
#define D_   2048
#define HQ_  16
#define HK_  4
#define HD_  128
#define MROWS (B_*T_)            // 4096
#define QELEMS (MROWS*HQ_*HD_)   // 8388608
#define KVELEMS (MROWS*HK_*HD_)  // 2097152
#define NTRIPLES 8704            // 32 bh * sum_{qb<16}(2qb+2)

// fp32 scratch (GEMM outputs)
__device__ float g_q[QELEMS];
__device__ float g_kraw[KVELEMS];
__device__ float g_vraw[KVELEMS];
// dropout mask bits
__device__ uint32_t g_mask[32*16*32*8*32];   // 16 MB
// fp16 operands
__device__ __half g_xh[MROWS*D_];            // x (single fp16)
__device__ __half g_wqh0[D_*D_], g_wqh1[D_*D_];
__device__ __half g_wkh0[512*D_], g_wkh1[512*D_];
__device__ __half g_wvh0[512*D_], g_wvh1[512*D_];
__device__ __half g_woh0[D_*D_], g_woh1[D_*D_];
__device__ __half g_ao[MROWS*D_];            // attention output (fp16)
// attention operands, head-major [b][h][t][128] (single fp16)
__device__ __half g_aqh[QELEMS];
__device__ __half g_akh[KVELEMS];
__device__ __half g_avh[KVELEMS];

// ============================ helpers =========================================
__device__ __forceinline__ uint32_t smem_u32(const void* p) {
    uint32_t a;
    asm("{ .reg .u64 t; cvta.to.shared.u64 t, %1; cvt.u32.u64 %0, t; }" : "=r"(a) : "l"(p));
    return a;
}
__device__ __forceinline__ void cpasync16(uint32_t s, const void* g) {
    asm volatile("cp.async.cg.shared.global [%0], [%1], 16;" :: "r"(s), "l"(g));
}
__device__ __forceinline__ void ldsm4(uint32_t& r0, uint32_t& r1, uint32_t& r2, uint32_t& r3,
                                      uint32_t addr) {
    asm volatile("ldmatrix.sync.aligned.m8n8.x4.shared.b16 {%0,%1,%2,%3}, [%4];"
                 : "=r"(r0), "=r"(r1), "=r"(r2), "=r"(r3) : "r"(addr));
}
__device__ __forceinline__ void ldsm4t(uint32_t& r0, uint32_t& r1, uint32_t& r2, uint32_t& r3,
                                       uint32_t addr) {
    asm volatile("ldmatrix.sync.aligned.m8n8.x4.trans.shared.b16 {%0,%1,%2,%3}, [%4];"
                 : "=r"(r0), "=r"(r1), "=r"(r2), "=r"(r3) : "r"(addr));
}
__device__ __forceinline__ void mma16816h(float* c, const uint32_t* a, const uint32_t* b) {
    asm volatile("mma.sync.aligned.m16n8k16.row.col.f32.f16.f16.f32 "
                 "{%0,%1,%2,%3}, {%4,%5,%6,%7}, {%8,%9}, {%0,%1,%2,%3};"
                 : "+f"(c[0]), "+f"(c[1]), "+f"(c[2]), "+f"(c[3])
                 : "r"(a[0]), "r"(a[1]), "r"(a[2]), "r"(a[3]), "r"(b[0]), "r"(b[1]));
}
// GEMM tile swizzle: [rows][32 elems of 2B] (64B rows, 16B chunks)
__device__ __forceinline__ uint32_t swadr(int row, int ch) {
    return (uint32_t)(row * 64 + ((ch ^ ((row >> 1) & 3)) << 4));
}
// attention tile swizzle: [rows][128 elems] (256B rows, 16 chunks of 16B)
__device__ __forceinline__ uint32_t asw(int row, int ch) {
    return (uint32_t)(row * 256 + ((ch ^ (row & 7)) << 4));
}

// ============================ threefry (partitionable) =========================
__device__ __forceinline__ unsigned tf_rotl(unsigned x, int r) {
    return (x << r) | (x >> (32 - r));
}
__device__ __forceinline__ unsigned dropout_bit(unsigned e) {
    unsigned x0 = 0u, x1 = e;
    const unsigned k0 = 0u, k1 = 1u, k2 = 0x1BD11BDAu ^ k0 ^ k1;
    x0 += k0; x1 += k1;
#define TFR(r) { x0 += x1; x1 = tf_rotl(x1, r); x1 ^= x0; }
    TFR(13) TFR(15) TFR(26) TFR(6)
    x0 += k1; x1 += k2 + 1u;
    TFR(17) TFR(29) TFR(16) TFR(24)
    x0 += k2; x1 += k0 + 2u;
    TFR(13) TFR(15) TFR(26) TFR(6)
    x0 += k0; x1 += k1 + 3u;
    TFR(17) TFR(29) TFR(16) TFR(24)
    x0 += k1; x1 += k2 + 4u;
    TFR(13) TFR(15) TFR(26) TFR(6)
    x0 += k2; x1 += k0 + 5u;
#undef TFR
    unsigned bits = x0 ^ x1;
    float u = __uint_as_float((bits >> 9) | 0x3F800000u) - 1.0f;
    return (u < 0.9f) ? 1u : 0u;
}

// ============================ prep kernels =====================================
__global__ void conv_h(const float* __restrict__ in, __half* __restrict__ o0) {
    int i = blockIdx.x * 256 + threadIdx.x;
    float4 v = ((const float4*)in)[i];
    __half2 a = __floats2half2_rn(v.x, v.y);
    __half2 b = __floats2half2_rn(v.z, v.w);
    ((uint2*)o0)[i] = make_uint2(*reinterpret_cast<uint32_t*>(&a),
                                 *reinterpret_cast<uint32_t*>(&b));
}

__global__ void wsplitT_h(const float* __restrict__ W, __half* __restrict__ t0,
                          __half* __restrict__ t1, int N) {
    __shared__ float tile[32][33];
    int n0 = blockIdx.x * 32, k0 = blockIdx.y * 32;
    int tx = threadIdx.x, ty = threadIdx.y;
    #pragma unroll
    for (int i = 0; i < 4; i++)
        tile[ty + i * 8][tx] = W[(long)(k0 + ty + i * 8) * N + n0 + tx];
    __syncthreads();
    #pragma unroll
    for (int i = 0; i < 4; i++) {
        float v = tile[tx][ty + i * 8];
        __half h = __float2half_rn(v);
        __half l = __float2half_rn(v - __half2float(h));
        long o = (long)(n0 + ty + i * 8) * 2048 + k0 + tx;
        t0[o] = h; t1[o] = l;
    }
}

// ============================ unified fp16 GEMM (+ optional mask gen) ==========
// two_b=1: C = A*(B0+B1) (2 MMAs); two_b=0: C = A*B0 (1 MMA).
#define G_STG 16384
#define G_A  0
#define G_B0 8192
#define G_B1 12288
#define G_TOT (3*G_STG)   // 49152

__global__ void __launch_bounds__(256) gemm_h(
    const __half* __restrict__ A,
    const __half* __restrict__ Bq0, const __half* __restrict__ Bq1,
    const __half* __restrict__ Bk0, const __half* __restrict__ Bk1,
    const __half* __restrict__ Bv0, const __half* __restrict__ Bv1,
    float* __restrict__ Cq, float* __restrict__ Ck, float* __restrict__ Cv,
    uint32_t* __restrict__ mask, int two_b) {
    extern __shared__ char smem[];
    uint32_t sb = smem_u32(smem);
    int tid = threadIdx.x, lane = tid & 31, wid = tid >> 5;
    int wm = wid & 3, wn = wid >> 2;
    long m0 = (long)blockIdx.y * 128;

    const __half *B0, *B1;
    float* C;
    int N, n0;
    int nb = blockIdx.x;
    if (nb < 32)      { B0 = Bq0; B1 = Bq1; C = Cq; N = 2048; n0 = nb * 64; }
    else if (nb < 40) { B0 = Bk0; B1 = Bk1; C = Ck; N = 512;  n0 = (nb - 32) * 64; }
    else              { B0 = Bv0; B1 = Bv1; C = Cv; N = 512;  n0 = (nb - 40) * 64; }

    int lrow = lane & 7, ltile = lane >> 3;
    int a_row = wm * 32 + ((ltile & 1) << 3) + lrow;
    int a_ch  = ltile >> 1;
    int b_row = wn * 32 + ((ltile >> 1) << 3) + lrow;
    int b_ch  = ltile & 1;

    float acc[2][4][4];
    #pragma unroll
    for (int mf = 0; mf < 2; mf++)
        #pragma unroll
        for (int nf = 0; nf < 4; nf++)
            #pragma unroll
            for (int j = 0; j < 4; j++) acc[mf][nf][j] = 0.f;

    int ar = tid >> 1, ach2 = (tid & 1) * 2;   // A: 2 chunks/thread
    int br = tid >> 2, bch = tid & 3;          // B: 1 chunk/thread/array

    int mstride = gridDim.x * gridDim.y;
    int mt = mask ? (blockIdx.y * gridDim.x + blockIdx.x) : NTRIPLES;
    int mh = 0;
    uint32_t mword = 0;
    unsigned mebase = 0;
    int mrowb = 0, mcolb = 0;
    long mwidx = 0;

    auto mask_step = [&]() {
        if (mt >= NTRIPLES) return;
        if (mh == 0) {
            int bh = mt / 272;
            int r = mt - bh * 272;
            int qb = 0;
            while (r >= 2 * qb + 2) { r -= 2 * qb + 2; qb++; }
            int jb = r;
            mebase = (unsigned)bh * 4194304u;
            mrowb = qb * 128 + wid * 16 + (lane >> 2);
            mcolb = jb * 64 + (lane & 3) * 2;
            mwidx = ((((long)bh * 16 + qb) * 32 + jb) * 8 + wid) * 32 + lane;
        }
        int nf = mh >> 2, rs = (mh >> 1) & 1, cs = mh & 1;
        unsigned e = mebase + (unsigned)(mrowb + rs * 8) * 2048u
                            + (unsigned)(mcolb + nf * 8 + cs);
        mword |= dropout_bit(e) << mh;
        mh++;
        if (mh == 32) { mask[mwidx] = mword; mword = 0; mh = 0; mt += mstride; }
    };

    auto issue = [&](int st, int kc) {
        uint32_t base = sb + st * G_STG;
        #pragma unroll
        for (int cc2 = 0; cc2 < 2; cc2++) {
            int ch = ach2 + cc2;
            cpasync16(base + G_A + swadr(ar, ch), A + (m0 + ar) * 2048 + kc + ch * 8);
        }
        {
            long g = (long)(n0 + br) * 2048 + kc + bch * 8;
            cpasync16(base + G_B0 + swadr(br, bch), B0 + g);
            if (two_b) cpasync16(base + G_B1 + swadr(br, bch), B1 + g);
        }
        asm volatile("cp.async.commit_group;" ::: "memory");
    };

    const int KI = 2048 / 32;
    issue(0, 0);
    issue(1, 32);
    int stage = 0;
    for (int kci = 0; kci < KI; kci++) {
        if (kci + 1 < KI) {
            asm volatile("cp.async.wait_group 1;" ::: "memory");
        } else {
            asm volatile("cp.async.wait_group 0;" ::: "memory");
        }
        __syncthreads();
        if (kci + 2 < KI) issue((stage + 2) % 3, (kci + 2) * 32);

        uint32_t base = sb + stage * G_STG;
        #pragma unroll
        for (int ks = 0; ks < 2; ks++) {
            uint32_t ah[2][4];
            #pragma unroll
            for (int mf = 0; mf < 2; mf++) {
                uint32_t adr = base + G_A + swadr(a_row + mf * 16, ks * 2 + a_ch);
                ldsm4(ah[mf][0], ah[mf][1], ah[mf][2], ah[mf][3], adr);
            }
            uint32_t bhf[4][2];
            #pragma unroll
            for (int nf2 = 0; nf2 < 2; nf2++) {
                uint32_t adr = base + G_B0 + swadr(b_row + nf2 * 16, ks * 2 + b_ch);
                ldsm4(bhf[nf2*2][0], bhf[nf2*2][1], bhf[nf2*2+1][0], bhf[nf2*2+1][1], adr);
            }
            #pragma unroll
            for (int mf = 0; mf < 2; mf++)
                #pragma unroll
                for (int nf = 0; nf < 4; nf++)
                    mma16816h(acc[mf][nf], ah[mf], bhf[nf]);
            if (two_b) {
                uint32_t blf[4][2];
                #pragma unroll
                for (int nf2 = 0; nf2 < 2; nf2++) {
                    uint32_t adr = base + G_B1 + swadr(b_row + nf2 * 16, ks * 2 + b_ch);
                    ldsm4(blf[nf2*2][0], blf[nf2*2][1], blf[nf2*2+1][0], blf[nf2*2+1][1], adr);
                }
                #pragma unroll
                for (int mf = 0; mf < 2; mf++)
                    #pragma unroll
                    for (int nf = 0; nf < 4; nf++)
                        mma16816h(acc[mf][nf], ah[mf], blf[nf]);
            }
        }
        mask_step();
        mask_step();
        mask_step();
        stage = (stage + 1) % 3;
    }
    while (mt < NTRIPLES) mask_step();

    int cr = lane >> 2, cc = (lane & 3) << 1;
    #pragma unroll
    for (int mf = 0; mf < 2; mf++)
        #pragma unroll
        for (int nf = 0; nf < 4; nf++) {
            long row = m0 + wm * 32 + mf * 16 + cr;
            int col = n0 + wn * 32 + nf * 8 + cc;
            *(float2*)(C + row * N + col)       = make_float2(acc[mf][nf][0], acc[mf][nf][1]);
            *(float2*)(C + (row + 8) * N + col) = make_float2(acc[mf][nf][2], acc[mf][nf][3]);
        }
}

// ============================ RoPE + pack + fp16 operands ======================
#define ROPE_RK (-0.20762050593478158f)   // -2*log2(10000)/128
__global__ void rope_pack(const float* __restrict__ q, const float* __restrict__ kraw,
                          const float* __restrict__ vraw, float* __restrict__ kv,
                          __half* __restrict__ qh,
                          __half* __restrict__ kh, __half* __restrict__ vh) {
    int idx = blockIdx.x * 256 + threadIdx.x;
    {
        int row = idx >> 10;          // b*T + t
        int rem = idx & 1023;
        int h = rem >> 6, m = rem & 63;
        int b = row >> 11, t = row & 2047;
        float invf = exp2f(ROPE_RK * (float)m);
        float ang = (float)t * invf;
        float c, s;
        sincosf(ang, &s, &c);
        const float scale = 0.08838834764831845f;
        long base = (long)row * (HQ_ * HD_) + h * HD_ + m;
        float x1 = q[base], x2 = q[base + 64];
        float v1 = (x1 * c - x2 * s) * scale;
        float v2 = (x2 * c + x1 * s) * scale;
        long so = ((long)(b * HQ_ + h) * T_ + t) * 128 + m;
        qh[so] = __float2half_rn(v1);
        qh[so + 64] = __float2half_rn(v2);
    }
    if (idx < MROWS * HK_ * 64) {
        int krow = idx >> 8;
        int krem = idx & 255;
        int khd = krem >> 6, km = krem & 63;
        int b = krow >> 11, t = krow & 2047;
        float invf = exp2f(ROPE_RK * (float)km);
        float ang = (float)t * invf;
        float c, s;
        sincosf(ang, &s, &c);
        long src = (long)krow * (HK_ * HD_) + khd * HD_ + km;
        float x1 = kraw[src], x2 = kraw[src + 64];
        float v1 = x1 * c - x2 * s;
        float v2 = x2 * c + x1 * s;
        long dst = ((long)krow * HK_ + khd) * 256 + km;
        kv[dst]      = v1;
        kv[dst + 64] = v2;
        long so = ((long)(b * HK_ + khd) * T_ + t) * 128 + km;
        kh[so] = __float2half_rn(v1);
        kh[so + 64] = __float2half_rn(v2);
    }
    if (idx < KVELEMS / 4) {
        int f = idx;
        int vrow = f >> 7;
        int vc4 = f & 127;
        int vhd = vc4 >> 5, vd4 = (vc4 & 31) << 2;
        int b = vrow >> 11, t = vrow & 2047;
        float4 v = *(const float4*)(vraw + (long)f * 4);
        long dst = ((long)vrow * HK_ + vhd) * 256 + 128 + vd4;
        *(float4*)(kv + dst) = v;
        long so = ((long)(b * HK_ + vhd) * T_ + t) * 128 + vd4;
        __half2 p1 = __floats2half2_rn(v.x, v.y);
        __half2 p2 = __floats2half2_rn(v.z, v.w);
        *(uint32_t*)(vh + so)     = *reinterpret_cast<uint32_t*>(&p1);
        *(uint32_t*)(vh + so + 2) = *reinterpret_cast<uint32_t*>(&p2);
    }
}

// ============================ tensor-core attention ============================
// smem: Q (32KB) + 2-stage KV (2x32KB) = 96 KB; double-buffered pipeline.
#define A_QH 0
#define A_KV0 (A_QH + 128*256)          // stage base; K at +0, V at +16384
#define A_KVSTG 32768
#define A_TOT (A_KV0 + 2*A_KVSTG)       // 98304 bytes

__global__ void __launch_bounds__(256) attn_mma(
    const __half* __restrict__ Qh,
    const __half* __restrict__ Kh, const __half* __restrict__ Vh,
    const uint32_t* __restrict__ Mask, __half* __restrict__ Oh) {
    extern __shared__ char smem[];
    uint32_t sb = smem_u32(smem);
    int tid = threadIdx.x, lane = tid & 31, wid = tid >> 5;
    int qb = (gridDim.x - 1) - blockIdx.x;
    int bh = blockIdx.y;
    int b = bh >> 4, hq = bh & 15, hk = hq & 3;

    const __half* qhp = Qh + ((long)(b * HQ_ + hq) * T_ + qb * 128) * 128;
    const __half* khp = Kh + (long)(b * HK_ + hk) * T_ * 128;
    const __half* vhp = Vh + (long)(b * HK_ + hk) * T_ * 128;

    // Q tile: 2048 chunks
    #pragma unroll
    for (int it = 0; it < 8; it++) {
        int lin = tid + it * 256;
        int row = lin >> 4, ch = lin & 15;
        cpasync16(sb + A_QH + asw(row, ch), qhp + row * 128 + ch * 8);
    }

    auto kv_issue = [&](int st, int jb) {
        uint32_t base = sb + A_KV0 + st * A_KVSTG;
        #pragma unroll
        for (int it = 0; it < 8; it++) {
            int lin = tid + it * 256;
            int arr = lin >> 10, cidx = lin & 1023;
            int row = cidx >> 4, ch = cidx & 15;
            long g = (long)(jb * 64 + row) * 128 + ch * 8;
            const __half* src = arr ? (vhp + g) : (khp + g);
            cpasync16(base + arr * 16384 + asw(row, ch), src);
        }
        asm volatile("cp.async.commit_group;" ::: "memory");
    };

    int qrw = wid * 16;
    float m1 = -INFINITY, m2 = -INFINITY, l1 = 0.f, l2 = 0.f;
    float o[16][4];
    #pragma unroll
    for (int nf = 0; nf < 16; nf++)
        #pragma unroll
        for (int c = 0; c < 4; c++) o[nf][c] = 0.f;

    int ig1 = qb * 128 + qrw + (lane >> 2);
    long wbase0 = ((long)bh * 16 + qb) * 8192 + wid * 32 + lane;

    int a_row = qrw + ((lane >> 3) & 1) * 8 + (lane & 7);
    int a_chb = lane >> 4;
    int k_row8 = ((lane >> 4)) * 8 + (lane & 7);
    int k_chb = (lane >> 3) & 1;
    int v_row8 = ((lane >> 3) & 1) * 8 + (lane & 7);
    int v_chb = lane >> 4;

    int njb = 2 * qb + 2;
    kv_issue(0, 0);   // includes Q loads in this group
    for (int jb = 0; jb < njb; jb++) {
        if (jb + 1 < njb) {
            kv_issue((jb + 1) & 1, jb + 1);
            asm volatile("cp.async.wait_group 1;" ::: "memory");
        } else {
            asm volatile("cp.async.wait_group 0;" ::: "memory");
        }
        uint32_t mw = Mask[wbase0 + (long)jb * 256];
        __syncthreads();
        uint32_t kvb = sb + A_KV0 + (jb & 1) * A_KVSTG;

        // S = Q K^T (both single fp16: 1 MMA/fragment)
        float sc[8][4];
        #pragma unroll
        for (int nf = 0; nf < 8; nf++)
            #pragma unroll
            for (int c = 0; c < 4; c++) sc[nf][c] = 0.f;
        #pragma unroll
        for (int ks = 0; ks < 8; ks++) {
            uint32_t qh4[4];
            ldsm4(qh4[0], qh4[1], qh4[2], qh4[3], sb + A_QH + asw(a_row, 2 * ks + a_chb));
            #pragma unroll
            for (int nfp = 0; nfp < 4; nfp++) {
                uint32_t kh4[4];
                int br = nfp * 16 + k_row8;
                int bc = 2 * ks + k_chb;
                ldsm4(kh4[0], kh4[1], kh4[2], kh4[3], kvb + asw(br, bc));
                mma16816h(sc[2 * nfp],     qh4, kh4);
                mma16816h(sc[2 * nfp + 1], qh4, kh4 + 2);
            }
        }

        if (jb * 64 + 63 > qb * 128 + qrw) {
            #pragma unroll
            for (int nf = 0; nf < 8; nf++) {
                int j0 = jb * 64 + nf * 8 + (lane & 3) * 2;
                if (j0 > ig1)     sc[nf][0] = -INFINITY;
                if (j0 + 1 > ig1) sc[nf][1] = -INFINITY;
                if (j0 > ig1 + 8)     sc[nf][2] = -INFINITY;
                if (j0 + 1 > ig1 + 8) sc[nf][3] = -INFINITY;
            }
        }

        float mx1 = -INFINITY, mx2 = -INFINITY;
        #pragma unroll
        for (int nf = 0; nf < 8; nf++) {
            mx1 = fmaxf(mx1, fmaxf(sc[nf][0], sc[nf][1]));
            mx2 = fmaxf(mx2, fmaxf(sc[nf][2], sc[nf][3]));
        }
        mx1 = fmaxf(mx1, __shfl_xor_sync(0xffffffffu, mx1, 1));
        mx1 = fmaxf(mx1, __shfl_xor_sync(0xffffffffu, mx1, 2));
        mx2 = fmaxf(mx2, __shfl_xor_sync(0xffffffffu, mx2, 1));
        mx2 = fmaxf(mx2, __shfl_xor_sync(0xffffffffu, mx2, 2));
        float mn1 = fmaxf(m1, mx1), mn2 = fmaxf(m2, mx2);
        float cr1 = __expf(m1 - mn1), cr2 = __expf(m2 - mn2);
        float rs1 = 0.f, rs2 = 0.f;
        #pragma unroll
        for (int nf = 0; nf < 8; nf++) {
            sc[nf][0] = __expf(sc[nf][0] - mn1); rs1 += sc[nf][0];
            sc[nf][1] = __expf(sc[nf][1] - mn1); rs1 += sc[nf][1];
            sc[nf][2] = __expf(sc[nf][2] - mn2); rs2 += sc[nf][2];
            sc[nf][3] = __expf(sc[nf][3] - mn2); rs2 += sc[nf][3];
        }
        rs1 += __shfl_xor_sync(0xffffffffu, rs1, 1);
        rs1 += __shfl_xor_sync(0xffffffffu, rs1, 2);
        rs2 += __shfl_xor_sync(0xffffffffu, rs2, 1);
        rs2 += __shfl_xor_sync(0xffffffffu, rs2, 2);
        l1 = l1 * cr1 + rs1;  l2 = l2 * cr2 + rs2;   // denom WITHOUT dropout (matches ref)
        m1 = mn1;  m2 = mn2;
        #pragma unroll
        for (int nf = 0; nf < 16; nf++) {
            o[nf][0] *= cr1; o[nf][1] *= cr1;
            o[nf][2] *= cr2; o[nf][3] *= cr2;
        }

        #pragma unroll
        for (int nf = 0; nf < 8; nf++) {
            sc[nf][0] *= ((mw >> (nf * 4 + 0)) & 1u) ? (1.0f / 0.9f) : 0.f;
            sc[nf][1] *= ((mw >> (nf * 4 + 1)) & 1u) ? (1.0f / 0.9f) : 0.f;
            sc[nf][2] *= ((mw >> (nf * 4 + 2)) & 1u) ? (1.0f / 0.9f) : 0.f;
            sc[nf][3] *= ((mw >> (nf * 4 + 3)) & 1u) ? (1.0f / 0.9f) : 0.f;
        }

        // O += P V (both single fp16: 1 MMA/fragment)
        #pragma unroll
        for (int ksj = 0; ksj < 4; ksj++) {
            uint32_t ahi[4];
            #pragma unroll
            for (int half = 0; half < 2; half++) {
                int nf = 2 * ksj + half;
                __half2 p01 = __floats2half2_rn(sc[nf][0], sc[nf][1]);
                __half2 p23 = __floats2half2_rn(sc[nf][2], sc[nf][3]);
                ahi[2 * half]     = *reinterpret_cast<uint32_t*>(&p01);
                ahi[2 * half + 1] = *reinterpret_cast<uint32_t*>(&p23);
            }
            #pragma unroll
            for (int nfp = 0; nfp < 8; nfp++) {
                uint32_t vh4[4];
                int vr = ksj * 16 + v_row8;
                int vc = 2 * nfp + v_chb;
                ldsm4t(vh4[0], vh4[1], vh4[2], vh4[3], kvb + 16384 + asw(vr, vc));
                mma16816h(o[2 * nfp],     ahi, vh4);
                mma16816h(o[2 * nfp + 1], ahi, vh4 + 2);
            }
        }
        __syncthreads();
    }

    // fused epilogue: normalize, write fp16 output (wo GEMM's A operand)
    float inv1 = 1.f / l1, inv2 = 1.f / l2;
    long r1g = (long)(b * T_ + qb * 128 + qrw + (lane >> 2));
    #pragma unroll
    for (int nf = 0; nf < 16; nf++) {
        int col = hq * 128 + nf * 8 + (lane & 3) * 2;
        __half2 h1 = __floats2half2_rn(o[nf][0] * inv1, o[nf][1] * inv1);
        __half2 h2 = __floats2half2_rn(o[nf][2] * inv2, o[nf][3] * inv2);
        *(uint32_t*)(Oh + r1g * 2048 + col)       = *reinterpret_cast<uint32_t*>(&h1);
        *(uint32_t*)(Oh + (r1g + 8) * 2048 + col) = *reinterpret_cast<uint32_t*>(&h2);
    }
}

// ============================ launch ===========================================
extern "C" void kernel_launch(void* const* d_in, const int* in_sizes, int n_in,
                              void* d_out, int out_size) {
    const float* x  = (const float*)d_in[0];
    const float* wq = (const float*)d_in[1];
    const float* wk = (const float*)d_in[2];
    const float* wv = (const float*)d_in[3];
    const float* wo = (const float*)d_in[4];
    float* out = (float*)d_out;
    float* kv  = out + QELEMS;

    float *qp, *kp, *vp;
    cudaGetSymbolAddress((void**)&qp, g_q);
    cudaGetSymbolAddress((void**)&kp, g_kraw);
    cudaGetSymbolAddress((void**)&vp, g_vraw);
    uint32_t* maskp;
    cudaGetSymbolAddress((void**)&maskp, g_mask);
    __half *xh, *wqh0, *wqh1, *wkh0, *wkh1, *wvh0, *wvh1, *woh0, *woh1, *ao;
    __half *aqh, *akh, *avh;
    cudaGetSymbolAddress((void**)&xh, g_xh);
    cudaGetSymbolAddress((void**)&wqh0, g_wqh0);
    cudaGetSymbolAddress((void**)&wqh1, g_wqh1);
    cudaGetSymbolAddress((void**)&wkh0, g_wkh0);
    cudaGetSymbolAddress((void**)&wkh1, g_wkh1);
    cudaGetSymbolAddress((void**)&wvh0, g_wvh0);
    cudaGetSymbolAddress((void**)&wvh1, g_wvh1);
    cudaGetSymbolAddress((void**)&woh0, g_woh0);
    cudaGetSymbolAddress((void**)&woh1, g_woh1);
    cudaGetSymbolAddress((void**)&ao, g_ao);
    cudaGetSymbolAddress((void**)&aqh, g_aqh);
    cudaGetSymbolAddress((void**)&akh, g_akh);
    cudaGetSymbolAddress((void**)&avh, g_avh);

    cudaFuncSetAttribute(gemm_h, cudaFuncAttributeMaxDynamicSharedMemorySize, G_TOT);
    cudaFuncSetAttribute(attn_mma, cudaFuncAttributeMaxDynamicSharedMemorySize, A_TOT);

    // prep
    conv_h<<<(MROWS * D_ / 4) / 256, 256>>>(x, xh);
    wsplitT_h<<<dim3(D_ / 32, D_ / 32), dim3(32, 8)>>>(wq, wqh0, wqh1, D_);
    wsplitT_h<<<dim3(512 / 32, D_ / 32), dim3(32, 8)>>>(wk, wkh0, wkh1, 512);
    wsplitT_h<<<dim3(512 / 32, D_ / 32), dim3(32, 8)>>>(wv, wvh0, wvh1, 512);
    wsplitT_h<<<dim3(D_ / 32, D_ / 32), dim3(32, 8)>>>(wo, woh0, woh1, D_);

    // fused q/k/v projections (weights hi/lo: 2 MMAs) + dropout-mask generation
    gemm_h<<<dim3(48, MROWS / 128), 256, G_TOT>>>(
        xh, wqh0, wqh1, wkh0, wkh1, wvh0, wvh1, qp, kp, vp, maskp, 1);

    rope_pack<<<(MROWS * HQ_ * 64) / 256, 256>>>(qp, kp, vp, kv, aqh, akh, avh);

    // tensor-core attention: all single fp16 (1 MMA/fragment both phases)
    attn_mma<<<dim3(T_ / 128, B_ * HQ_), 256, A_TOT>>>(aqh, akh, avh, maskp, ao);

    // out projection: single fp16 weights (1 MMA)
    gemm_h<<<dim3(32, MROWS / 128), 256, G_TOT>>>(
        ao, woh0, woh0, woh0, woh0, woh0, woh0, out, out, out, (uint32_t*)nullptr, 0);
}

// round 16
// speedup vs baseline: 2.0866x; 1.1542x over previous
#include <cuda_runtime.h>
#include <cuda_bf16.h>
#include <cuda_fp16.h>
#include <math.h>
#include <stdint.h>

#define B_   2
#define T_   2048
#define D_   2048
#define HQ_  16
#define HK_  4
#define HD_  128
#define MROWS (B_*T_)            // 4096
#define QELEMS (MROWS*HQ_*HD_)   // 8388608
#define KVELEMS (MROWS*HK_*HD_)  // 2097152
#define NTRIPLES 8704            // 32 bh * sum_{qb<16}(2qb+2)

// fp32 scratch (GEMM outputs)
__device__ float g_q[QELEMS];
__device__ float g_kraw[KVELEMS];
__device__ float g_vraw[KVELEMS];
// dropout mask bits
__device__ uint32_t g_mask[32*16*32*8*32];   // 16 MB
// fp16 operands
__device__ __half g_xh[MROWS*D_];            // x (single fp16)
__device__ __half g_wqh0[D_*D_];
__device__ __half g_wkh0[512*D_];
__device__ __half g_wvh0[512*D_];
__device__ __half g_woh0[D_*D_];
__device__ __half g_ao[MROWS*D_];            // attention output (fp16)
// attention operands, head-major [b][h][t][128] (single fp16)
__device__ __half g_aqh[QELEMS];
__device__ __half g_akh[KVELEMS];
__device__ __half g_avh[KVELEMS];

// ============================ helpers =========================================
__device__ __forceinline__ uint32_t smem_u32(const void* p) {
    uint32_t a;
    asm("{ .reg .u64 t; cvta.to.shared.u64 t, %1; cvt.u32.u64 %0, t; }" : "=r"(a) : "l"(p));
    return a;
}
__device__ __forceinline__ void cpasync16(uint32_t s, const void* g) {
    asm volatile("cp.async.cg.shared.global [%0], [%1], 16;" :: "r"(s), "l"(g));
}
__device__ __forceinline__ void ldsm4(uint32_t& r0, uint32_t& r1, uint32_t& r2, uint32_t& r3,
                                      uint32_t addr) {
    asm volatile("ldmatrix.sync.aligned.m8n8.x4.shared.b16 {%0,%1,%2,%3}, [%4];"
                 : "=r"(r0), "=r"(r1), "=r"(r2), "=r"(r3) : "r"(addr));
}
__device__ __forceinline__ void ldsm4t(uint32_t& r0, uint32_t& r1, uint32_t& r2, uint32_t& r3,
                                       uint32_t addr) {
    asm volatile("ldmatrix.sync.aligned.m8n8.x4.trans.shared.b16 {%0,%1,%2,%3}, [%4];"
                 : "=r"(r0), "=r"(r1), "=r"(r2), "=r"(r3) : "r"(addr));
}
__device__ __forceinline__ void mma16816h(float* c, const uint32_t* a, const uint32_t* b) {
    asm volatile("mma.sync.aligned.m16n8k16.row.col.f32.f16.f16.f32 "
                 "{%0,%1,%2,%3}, {%4,%5,%6,%7}, {%8,%9}, {%0,%1,%2,%3};"
                 : "+f"(c[0]), "+f"(c[1]), "+f"(c[2]), "+f"(c[3])
                 : "r"(a[0]), "r"(a[1]), "r"(a[2]), "r"(a[3]), "r"(b[0]), "r"(b[1]));
}
// GEMM tile swizzle: [rows][32 elems of 2B] (64B rows, 16B chunks)
__device__ __forceinline__ uint32_t swadr(int row, int ch) {
    return (uint32_t)(row * 64 + ((ch ^ ((row >> 1) & 3)) << 4));
}
// attention tile swizzle: [rows][128 elems] (256B rows, 16 chunks of 16B)
__device__ __forceinline__ uint32_t asw(int row, int ch) {
    return (uint32_t)(row * 256 + ((ch ^ (row & 7)) << 4));
}

// ============================ threefry (partitionable) =========================
__device__ __forceinline__ unsigned tf_rotl(unsigned x, int r) {
    return (x << r) | (x >> (32 - r));
}
__device__ __forceinline__ unsigned dropout_bit(unsigned e) {
    unsigned x0 = 0u, x1 = e;
    const unsigned k0 = 0u, k1 = 1u, k2 = 0x1BD11BDAu ^ k0 ^ k1;
    x0 += k0; x1 += k1;
#define TFR(r) { x0 += x1; x1 = tf_rotl(x1, r); x1 ^= x0; }
    TFR(13) TFR(15) TFR(26) TFR(6)
    x0 += k1; x1 += k2 + 1u;
    TFR(17) TFR(29) TFR(16) TFR(24)
    x0 += k2; x1 += k0 + 2u;
    TFR(13) TFR(15) TFR(26) TFR(6)
    x0 += k0; x1 += k1 + 3u;
    TFR(17) TFR(29) TFR(16) TFR(24)
    x0 += k1; x1 += k2 + 4u;
    TFR(13) TFR(15) TFR(26) TFR(6)
    x0 += k2; x1 += k0 + 5u;
#undef TFR
    unsigned bits = x0 ^ x1;
    float u = __uint_as_float((bits >> 9) | 0x3F800000u) - 1.0f;
    return (u < 0.9f) ? 1u : 0u;
}

// ============================ prep kernels =====================================
__global__ void conv_h(const float* __restrict__ in, __half* __restrict__ o0) {
    int i = blockIdx.x * 256 + threadIdx.x;
    float4 v = ((const float4*)in)[i];
    __half2 a = __floats2half2_rn(v.x, v.y);
    __half2 b = __floats2half2_rn(v.z, v.w);
    ((uint2*)o0)[i] = make_uint2(*reinterpret_cast<uint32_t*>(&a),
                                 *reinterpret_cast<uint32_t*>(&b));
}

// transpose + single fp16 convert: W [2048][N] -> Wt [N][2048]
__global__ void wconvT_h(const float* __restrict__ W, __half* __restrict__ t0, int N) {
    __shared__ float tile[32][33];
    int n0 = blockIdx.x * 32, k0 = blockIdx.y * 32;
    int tx = threadIdx.x, ty = threadIdx.y;
    #pragma unroll
    for (int i = 0; i < 4; i++)
        tile[ty + i * 8][tx] = W[(long)(k0 + ty + i * 8) * N + n0 + tx];
    __syncthreads();
    #pragma unroll
    for (int i = 0; i < 4; i++) {
        long o = (long)(n0 + ty + i * 8) * 2048 + k0 + tx;
        t0[o] = __float2half_rn(tile[tx][ty + i * 8]);
    }
}

// ============================ unified fp16 GEMM (+ optional mask gen) ==========
// C = A*B0, 1 MMA per fragment; B single fp16.
#define G_STG 16384
#define G_A  0
#define G_B0 8192
#define G_B1 12288
#define G_TOT (3*G_STG)   // 49152

__global__ void __launch_bounds__(256) gemm_h(
    const __half* __restrict__ A,
    const __half* __restrict__ Bq0, const __half* __restrict__ Bk0,
    const __half* __restrict__ Bv0,
    float* __restrict__ Cq, float* __restrict__ Ck, float* __restrict__ Cv,
    uint32_t* __restrict__ mask) {
    extern __shared__ char smem[];
    uint32_t sb = smem_u32(smem);
    int tid = threadIdx.x, lane = tid & 31, wid = tid >> 5;
    int wm = wid & 3, wn = wid >> 2;
    long m0 = (long)blockIdx.y * 128;

    const __half *B0;
    float* C;
    int N, n0;
    int nb = blockIdx.x;
    if (nb < 32)      { B0 = Bq0; C = Cq; N = 2048; n0 = nb * 64; }
    else if (nb < 40) { B0 = Bk0; C = Ck; N = 512;  n0 = (nb - 32) * 64; }
    else              { B0 = Bv0; C = Cv; N = 512;  n0 = (nb - 40) * 64; }

    int lrow = lane & 7, ltile = lane >> 3;
    int a_row = wm * 32 + ((ltile & 1) << 3) + lrow;
    int a_ch  = ltile >> 1;
    int b_row = wn * 32 + ((ltile >> 1) << 3) + lrow;
    int b_ch  = ltile & 1;

    float acc[2][4][4];
    #pragma unroll
    for (int mf = 0; mf < 2; mf++)
        #pragma unroll
        for (int nf = 0; nf < 4; nf++)
            #pragma unroll
            for (int j = 0; j < 4; j++) acc[mf][nf][j] = 0.f;

    int ar = tid >> 1, ach2 = (tid & 1) * 2;   // A: 2 chunks/thread
    int br = tid >> 2, bch = tid & 3;          // B: 1 chunk/thread

    int mstride = gridDim.x * gridDim.y;
    int mt = mask ? (blockIdx.y * gridDim.x + blockIdx.x) : NTRIPLES;
    int mh = 0;
    uint32_t mword = 0;
    unsigned mebase = 0;
    int mrowb = 0, mcolb = 0;
    long mwidx = 0;

    auto mask_step = [&]() {
        if (mt >= NTRIPLES) return;
        if (mh == 0) {
            int bh = mt / 272;
            int r = mt - bh * 272;
            int qb = 0;
            while (r >= 2 * qb + 2) { r -= 2 * qb + 2; qb++; }
            int jb = r;
            mebase = (unsigned)bh * 4194304u;
            mrowb = qb * 128 + wid * 16 + (lane >> 2);
            mcolb = jb * 64 + (lane & 3) * 2;
            mwidx = ((((long)bh * 16 + qb) * 32 + jb) * 8 + wid) * 32 + lane;
        }
        int nf = mh >> 2, rs = (mh >> 1) & 1, cs = mh & 1;
        unsigned e = mebase + (unsigned)(mrowb + rs * 8) * 2048u
                            + (unsigned)(mcolb + nf * 8 + cs);
        mword |= dropout_bit(e) << mh;
        mh++;
        if (mh == 32) { mask[mwidx] = mword; mword = 0; mh = 0; mt += mstride; }
    };

    auto issue = [&](int st, int kc) {
        uint32_t base = sb + st * G_STG;
        #pragma unroll
        for (int cc2 = 0; cc2 < 2; cc2++) {
            int ch = ach2 + cc2;
            cpasync16(base + G_A + swadr(ar, ch), A + (m0 + ar) * 2048 + kc + ch * 8);
        }
        {
            long g = (long)(n0 + br) * 2048 + kc + bch * 8;
            cpasync16(base + G_B0 + swadr(br, bch), B0 + g);
        }
        asm volatile("cp.async.commit_group;" ::: "memory");
    };

    const int KI = 2048 / 32;
    issue(0, 0);
    issue(1, 32);
    int stage = 0;
    for (int kci = 0; kci < KI; kci++) {
        if (kci + 1 < KI) {
            asm volatile("cp.async.wait_group 1;" ::: "memory");
        } else {
            asm volatile("cp.async.wait_group 0;" ::: "memory");
        }
        __syncthreads();
        if (kci + 2 < KI) issue((stage + 2) % 3, (kci + 2) * 32);

        uint32_t base = sb + stage * G_STG;
        #pragma unroll
        for (int ks = 0; ks < 2; ks++) {
            uint32_t ah[2][4];
            #pragma unroll
            for (int mf = 0; mf < 2; mf++) {
                uint32_t adr = base + G_A + swadr(a_row + mf * 16, ks * 2 + a_ch);
                ldsm4(ah[mf][0], ah[mf][1], ah[mf][2], ah[mf][3], adr);
            }
            uint32_t bhf[4][2];
            #pragma unroll
            for (int nf2 = 0; nf2 < 2; nf2++) {
                uint32_t adr = base + G_B0 + swadr(b_row + nf2 * 16, ks * 2 + b_ch);
                ldsm4(bhf[nf2*2][0], bhf[nf2*2][1], bhf[nf2*2+1][0], bhf[nf2*2+1][1], adr);
            }
            #pragma unroll
            for (int mf = 0; mf < 2; mf++)
                #pragma unroll
                for (int nf = 0; nf < 4; nf++)
                    mma16816h(acc[mf][nf], ah[mf], bhf[nf]);
        }
        mask_step();
        mask_step();
        mask_step();
        stage = (stage + 1) % 3;
    }
    while (mt < NTRIPLES) mask_step();

    int cr = lane >> 2, cc = (lane & 3) << 1;
    #pragma unroll
    for (int mf = 0; mf < 2; mf++)
        #pragma unroll
        for (int nf = 0; nf < 4; nf++) {
            long row = m0 + wm * 32 + mf * 16 + cr;
            int col = n0 + wn * 32 + nf * 8 + cc;
            *(float2*)(C + row * N + col)       = make_float2(acc[mf][nf][0], acc[mf][nf][1]);
            *(float2*)(C + (row + 8) * N + col) = make_float2(acc[mf][nf][2], acc[mf][nf][3]);
        }
}

// ============================ RoPE + pack + fp16 operands ======================
#define ROPE_RK (-0.20762050593478158f)   // -2*log2(10000)/128
__global__ void rope_pack(const float* __restrict__ q, const float* __restrict__ kraw,
                          const float* __restrict__ vraw, float* __restrict__ kv,
                          __half* __restrict__ qh,
                          __half* __restrict__ kh, __half* __restrict__ vh) {
    int idx = blockIdx.x * 256 + threadIdx.x;
    {
        int row = idx >> 10;          // b*T + t
        int rem = idx & 1023;
        int h = rem >> 6, m = rem & 63;
        int b = row >> 11, t = row & 2047;
        float invf = exp2f(ROPE_RK * (float)m);
        float ang = (float)t * invf;
        float c, s;
        sincosf(ang, &s, &c);
        const float scale = 0.08838834764831845f;
        long base = (long)row * (HQ_ * HD_) + h * HD_ + m;
        float x1 = q[base], x2 = q[base + 64];
        float v1 = (x1 * c - x2 * s) * scale;
        float v2 = (x2 * c + x1 * s) * scale;
        long so = ((long)(b * HQ_ + h) * T_ + t) * 128 + m;
        qh[so] = __float2half_rn(v1);
        qh[so + 64] = __float2half_rn(v2);
    }
    if (idx < MROWS * HK_ * 64) {
        int krow = idx >> 8;
        int krem = idx & 255;
        int khd = krem >> 6, km = krem & 63;
        int b = krow >> 11, t = krow & 2047;
        float invf = exp2f(ROPE_RK * (float)km);
        float ang = (float)t * invf;
        float c, s;
        sincosf(ang, &s, &c);
        long src = (long)krow * (HK_ * HD_) + khd * HD_ + km;
        float x1 = kraw[src], x2 = kraw[src + 64];
        float v1 = x1 * c - x2 * s;
        float v2 = x2 * c + x1 * s;
        long dst = ((long)krow * HK_ + khd) * 256 + km;
        kv[dst]      = v1;
        kv[dst + 64] = v2;
        long so = ((long)(b * HK_ + khd) * T_ + t) * 128 + km;
        kh[so] = __float2half_rn(v1);
        kh[so + 64] = __float2half_rn(v2);
    }
    if (idx < KVELEMS / 4) {
        int f = idx;
        int vrow = f >> 7;
        int vc4 = f & 127;
        int vhd = vc4 >> 5, vd4 = (vc4 & 31) << 2;
        int b = vrow >> 11, t = vrow & 2047;
        float4 v = *(const float4*)(vraw + (long)f * 4);
        long dst = ((long)vrow * HK_ + vhd) * 256 + 128 + vd4;
        *(float4*)(kv + dst) = v;
        long so = ((long)(b * HK_ + vhd) * T_ + t) * 128 + vd4;
        __half2 p1 = __floats2half2_rn(v.x, v.y);
        __half2 p2 = __floats2half2_rn(v.z, v.w);
        *(uint32_t*)(vh + so)     = *reinterpret_cast<uint32_t*>(&p1);
        *(uint32_t*)(vh + so + 2) = *reinterpret_cast<uint32_t*>(&p2);
    }
}

// ============================ tensor-core attention ============================
// smem: Q (32KB) + 2-stage KV (2x32KB) = 96 KB; double-buffered pipeline.
#define A_QH 0
#define A_KV0 (A_QH + 128*256)          // stage base; K at +0, V at +16384
#define A_KVSTG 32768
#define A_TOT (A_KV0 + 2*A_KVSTG)       // 98304 bytes

__global__ void __launch_bounds__(256) attn_mma(
    const __half* __restrict__ Qh,
    const __half* __restrict__ Kh, const __half* __restrict__ Vh,
    const uint32_t* __restrict__ Mask, __half* __restrict__ Oh) {
    extern __shared__ char smem[];
    uint32_t sb = smem_u32(smem);
    int tid = threadIdx.x, lane = tid & 31, wid = tid >> 5;
    int qb = (gridDim.x - 1) - blockIdx.x;
    int bh = blockIdx.y;
    int b = bh >> 4, hq = bh & 15, hk = hq & 3;

    const __half* qhp = Qh + ((long)(b * HQ_ + hq) * T_ + qb * 128) * 128;
    const __half* khp = Kh + (long)(b * HK_ + hk) * T_ * 128;
    const __half* vhp = Vh + (long)(b * HK_ + hk) * T_ * 128;

    #pragma unroll
    for (int it = 0; it < 8; it++) {
        int lin = tid + it * 256;
        int row = lin >> 4, ch = lin & 15;
        cpasync16(sb + A_QH + asw(row, ch), qhp + row * 128 + ch * 8);
    }

    auto kv_issue = [&](int st, int jb) {
        uint32_t base = sb + A_KV0 + st * A_KVSTG;
        #pragma unroll
        for (int it = 0; it < 8; it++) {
            int lin = tid + it * 256;
            int arr = lin >> 10, cidx = lin & 1023;
            int row = cidx >> 4, ch = cidx & 15;
            long g = (long)(jb * 64 + row) * 128 + ch * 8;
            const __half* src = arr ? (vhp + g) : (khp + g);
            cpasync16(base + arr * 16384 + asw(row, ch), src);
        }
        asm volatile("cp.async.commit_group;" ::: "memory");
    };

    int qrw = wid * 16;
    float m1 = -INFINITY, m2 = -INFINITY, l1 = 0.f, l2 = 0.f;
    float o[16][4];
    #pragma unroll
    for (int nf = 0; nf < 16; nf++)
        #pragma unroll
        for (int c = 0; c < 4; c++) o[nf][c] = 0.f;

    int ig1 = qb * 128 + qrw + (lane >> 2);
    long wbase0 = ((long)bh * 16 + qb) * 8192 + wid * 32 + lane;

    int a_row = qrw + ((lane >> 3) & 1) * 8 + (lane & 7);
    int a_chb = lane >> 4;
    int k_row8 = ((lane >> 4)) * 8 + (lane & 7);
    int k_chb = (lane >> 3) & 1;
    int v_row8 = ((lane >> 3) & 1) * 8 + (lane & 7);
    int v_chb = lane >> 4;

    int njb = 2 * qb + 2;
    kv_issue(0, 0);   // includes Q loads in this group
    for (int jb = 0; jb < njb; jb++) {
        if (jb + 1 < njb) {
            kv_issue((jb + 1) & 1, jb + 1);
            asm volatile("cp.async.wait_group 1;" ::: "memory");
        } else {
            asm volatile("cp.async.wait_group 0;" ::: "memory");
        }
        uint32_t mw = Mask[wbase0 + (long)jb * 256];
        __syncthreads();
        uint32_t kvb = sb + A_KV0 + (jb & 1) * A_KVSTG;

        float sc[8][4];
        #pragma unroll
        for (int nf = 0; nf < 8; nf++)
            #pragma unroll
            for (int c = 0; c < 4; c++) sc[nf][c] = 0.f;
        #pragma unroll
        for (int ks = 0; ks < 8; ks++) {
            uint32_t qh4[4];
            ldsm4(qh4[0], qh4[1], qh4[2], qh4[3], sb + A_QH + asw(a_row, 2 * ks + a_chb));
            #pragma unroll
            for (int nfp = 0; nfp < 4; nfp++) {
                uint32_t kh4[4];
                int br = nfp * 16 + k_row8;
                int bc = 2 * ks + k_chb;
                ldsm4(kh4[0], kh4[1], kh4[2], kh4[3], kvb + asw(br, bc));
                mma16816h(sc[2 * nfp],     qh4, kh4);
                mma16816h(sc[2 * nfp + 1], qh4, kh4 + 2);
            }
        }

        if (jb * 64 + 63 > qb * 128 + qrw) {
            #pragma unroll
            for (int nf = 0; nf < 8; nf++) {
                int j0 = jb * 64 + nf * 8 + (lane & 3) * 2;
                if (j0 > ig1)     sc[nf][0] = -INFINITY;
                if (j0 + 1 > ig1) sc[nf][1] = -INFINITY;
                if (j0 > ig1 + 8)     sc[nf][2] = -INFINITY;
                if (j0 + 1 > ig1 + 8) sc[nf][3] = -INFINITY;
            }
        }

        float mx1 = -INFINITY, mx2 = -INFINITY;
        #pragma unroll
        for (int nf = 0; nf < 8; nf++) {
            mx1 = fmaxf(mx1, fmaxf(sc[nf][0], sc[nf][1]));
            mx2 = fmaxf(mx2, fmaxf(sc[nf][2], sc[nf][3]));
        }
        mx1 = fmaxf(mx1, __shfl_xor_sync(0xffffffffu, mx1, 1));
        mx1 = fmaxf(mx1, __shfl_xor_sync(0xffffffffu, mx1, 2));
        mx2 = fmaxf(mx2, __shfl_xor_sync(0xffffffffu, mx2, 1));
        mx2 = fmaxf(mx2, __shfl_xor_sync(0xffffffffu, mx2, 2));
        float mn1 = fmaxf(m1, mx1), mn2 = fmaxf(m2, mx2);
        float cr1 = __expf(m1 - mn1), cr2 = __expf(m2 - mn2);
        float rs1 = 0.f, rs2 = 0.f;
        #pragma unroll
        for (int nf = 0; nf < 8; nf++) {
            sc[nf][0] = __expf(sc[nf][0] - mn1); rs1 += sc[nf][0];
            sc[nf][1] = __expf(sc[nf][1] - mn1); rs1 += sc[nf][1];
            sc[nf][2] = __expf(sc[nf][2] - mn2); rs2 += sc[nf][2];
            sc[nf][3] = __expf(sc[nf][3] - mn2); rs2 += sc[nf][3];
        }
        rs1 += __shfl_xor_sync(0xffffffffu, rs1, 1);
        rs1 += __shfl_xor_sync(0xffffffffu, rs1, 2);
        rs2 += __shfl_xor_sync(0xffffffffu, rs2, 1);
        rs2 += __shfl_xor_sync(0xffffffffu, rs2, 2);
        l1 = l1 * cr1 + rs1;  l2 = l2 * cr2 + rs2;   // denom WITHOUT dropout (matches ref)
        m1 = mn1;  m2 = mn2;
        #pragma unroll
        for (int nf = 0; nf < 16; nf++) {
            o[nf][0] *= cr1; o[nf][1] *= cr1;
            o[nf][2] *= cr2; o[nf][3] *= cr2;
        }

        #pragma unroll
        for (int nf = 0; nf < 8; nf++) {
            sc[nf][0] *= ((mw >> (nf * 4 + 0)) & 1u) ? (1.0f / 0.9f) : 0.f;
            sc[nf][1] *= ((mw >> (nf * 4 + 1)) & 1u) ? (1.0f / 0.9f) : 0.f;
            sc[nf][2] *= ((mw >> (nf * 4 + 2)) & 1u) ? (1.0f / 0.9f) : 0.f;
            sc[nf][3] *= ((mw >> (nf * 4 + 3)) & 1u) ? (1.0f / 0.9f) : 0.f;
        }

        #pragma unroll
        for (int ksj = 0; ksj < 4; ksj++) {
            uint32_t ahi[4];
            #pragma unroll
            for (int half = 0; half < 2; half++) {
                int nf = 2 * ksj + half;
                __half2 p01 = __floats2half2_rn(sc[nf][0], sc[nf][1]);
                __half2 p23 = __floats2half2_rn(sc[nf][2], sc[nf][3]);
                ahi[2 * half]     = *reinterpret_cast<uint32_t*>(&p01);
                ahi[2 * half + 1] = *reinterpret_cast<uint32_t*>(&p23);
            }
            #pragma unroll
            for (int nfp = 0; nfp < 8; nfp++) {
                uint32_t vh4[4];
                int vr = ksj * 16 + v_row8;
                int vc = 2 * nfp + v_chb;
                ldsm4t(vh4[0], vh4[1], vh4[2], vh4[3], kvb + 16384 + asw(vr, vc));
                mma16816h(o[2 * nfp],     ahi, vh4);
                mma16816h(o[2 * nfp + 1], ahi, vh4 + 2);
            }
        }
        __syncthreads();
    }

    float inv1 = 1.f / l1, inv2 = 1.f / l2;
    long r1g = (long)(b * T_ + qb * 128 + qrw + (lane >> 2));
    #pragma unroll
    for (int nf = 0; nf < 16; nf++) {
        int col = hq * 128 + nf * 8 + (lane & 3) * 2;
        __half2 h1 = __floats2half2_rn(o[nf][0] * inv1, o[nf][1] * inv1);
        __half2 h2 = __floats2half2_rn(o[nf][2] * inv2, o[nf][3] * inv2);
        *(uint32_t*)(Oh + r1g * 2048 + col)       = *reinterpret_cast<uint32_t*>(&h1);
        *(uint32_t*)(Oh + (r1g + 8) * 2048 + col) = *reinterpret_cast<uint32_t*>(&h2);
    }
}

// ============================ launch ===========================================
extern "C" void kernel_launch(void* const* d_in, const int* in_sizes, int n_in,
                              void* d_out, int out_size) {
    const float* x  = (const float*)d_in[0];
    const float* wq = (const float*)d_in[1];
    const float* wk = (const float*)d_in[2];
    const float* wv = (const float*)d_in[3];
    const float* wo = (const float*)d_in[4];
    float* out = (float*)d_out;
    float* kv  = out + QELEMS;

    float *qp, *kp, *vp;
    cudaGetSymbolAddress((void**)&qp, g_q);
    cudaGetSymbolAddress((void**)&kp, g_kraw);
    cudaGetSymbolAddress((void**)&vp, g_vraw);
    uint32_t* maskp;
    cudaGetSymbolAddress((void**)&maskp, g_mask);
    __half *xh, *wqh0, *wkh0, *wvh0, *woh0, *ao;
    __half *aqh, *akh, *avh;
    cudaGetSymbolAddress((void**)&xh, g_xh);
    cudaGetSymbolAddress((void**)&wqh0, g_wqh0);
    cudaGetSymbolAddress((void**)&wkh0, g_wkh0);
    cudaGetSymbolAddress((void**)&wvh0, g_wvh0);
    cudaGetSymbolAddress((void**)&woh0, g_woh0);
    cudaGetSymbolAddress((void**)&ao, g_ao);
    cudaGetSymbolAddress((void**)&aqh, g_aqh);
    cudaGetSymbolAddress((void**)&akh, g_akh);
    cudaGetSymbolAddress((void**)&avh, g_avh);

    cudaFuncSetAttribute(gemm_h, cudaFuncAttributeMaxDynamicSharedMemorySize, G_TOT);
    cudaFuncSetAttribute(attn_mma, cudaFuncAttributeMaxDynamicSharedMemorySize, A_TOT);

    // prep (all single fp16)
    conv_h<<<(MROWS * D_ / 4) / 256, 256>>>(x, xh);
    wconvT_h<<<dim3(D_ / 32, D_ / 32), dim3(32, 8)>>>(wq, wqh0, D_);
    wconvT_h<<<dim3(512 / 32, D_ / 32), dim3(32, 8)>>>(wk, wkh0, 512);
    wconvT_h<<<dim3(512 / 32, D_ / 32), dim3(32, 8)>>>(wv, wvh0, 512);
    wconvT_h<<<dim3(D_ / 32, D_ / 32), dim3(32, 8)>>>(wo, woh0, D_);

    // fused q/k/v projections (single fp16 weights: 1 MMA) + mask generation
    gemm_h<<<dim3(48, MROWS / 128), 256, G_TOT>>>(
        xh, wqh0, wkh0, wvh0, qp, kp, vp, maskp);

    rope_pack<<<(MROWS * HQ_ * 64) / 256, 256>>>(qp, kp, vp, kv, aqh, akh, avh);

    // tensor-core attention (single fp16 both phases)
    attn_mma<<<dim3(T_ / 128, B_ * HQ_), 256, A_TOT>>>(aqh, akh, avh, maskp, ao);

    // out projection (single fp16 weights)
    gemm_h<<<dim3(32, MROWS / 128), 256, G_TOT>>>(
        ao, woh0, woh0, woh0, out, out, out, (uint32_t*)nullptr);
}